// round 3
// baseline (speedup 1.0000x reference)
#include <cuda_runtime.h>
#include <math.h>
#include <stddef.h>

// Problem constants
#define B_SZ   4
#define S_SZ   1024
#define D_M    1024
#define H_N    16
#define D_INT  64
#define D_V    128      // 2*D_INT
#define HID    4096
#define NTOK   4096     // B*S
#define HB     64       // H*B
#define LAMBDA_INIT 0.3555090675909693f
#define HEADLN_SCALE 0.6444909324090307f   // 1 - LAMBDA_INIT
#define R2_ELEMS 4194304                    // B*S*D_M
#define FULL_ELEMS 71303168                 // R2 + H*B*S*S

// ---------------- scratch (static device memory; no allocation) -------------
__device__ float g_Q[(size_t)NTOK * (H_N * D_INT)];          // [tok][h*64+e]
__device__ float g_Kb[(size_t)NTOK * (H_N * D_INT)];
__device__ float g_V[(size_t)NTOK * (H_N * D_V)];            // [tok][h*128+v]
__device__ float g_S[(size_t)HB * S_SZ * S_SZ];              // scores / A scratch
__device__ float g_O[(size_t)HB * S_SZ * D_V];               // [hb][s][v]
__device__ float g_Ocat[(size_t)NTOK * (H_N * D_V)];         // [tok][h*128+v]
__device__ float g_h1pre[(size_t)NTOK * D_M];
__device__ float g_h1[(size_t)NTOK * D_M];
__device__ float g_ffh[(size_t)NTOK * HID];
__device__ float g_r2pre[(size_t)NTOK * D_M];
__device__ float g_lamscale;                                  // 1 - lambda

// ---------------- lambda ----------------------------------------------------
__global__ void lam_kernel(const float* __restrict__ lq1, const float* __restrict__ lk1,
                           const float* __restrict__ lq2, const float* __restrict__ lk2)
{
    __shared__ float s1[64], s2[64];
    int t = threadIdx.x;
    s1[t] = lq1[t] * lk1[t];
    s2[t] = lq2[t] * lk2[t];
    __syncthreads();
    if (t == 0) {
        float d1 = 0.f, d2 = 0.f;
        for (int i = 0; i < 64; i++) { d1 += s1[i]; d2 += s2[i]; }
        float lam = expf(d1) - expf(d2) + LAMBDA_INIT;
        g_lamscale = 1.0f - lam;
    }
}

// ---------------- generic GEMM: C = A[M,K] @ B + bias + res, optional relu --
// B element (k, n) lives at Bm[(n/dout)*K*dout + k*dout + (n%dout)]
// (dout==N -> plain row-major [K,N]; dout=64/128 -> per-head stacked weights)
__global__ void __launch_bounds__(256) gemm128(
    const float* __restrict__ A, const float* __restrict__ Bm,
    const float* __restrict__ bias, const float* __restrict__ res,
    float* __restrict__ C, int M, int N, int K, int dout, int relu)
{
    __shared__ float As[16][129];
    __shared__ float Bs[16][129];
    const int tid = threadIdx.x;
    const int tx = tid & 15, ty = tid >> 4;
    const int m0 = blockIdx.y * 128, n0 = blockIdx.x * 128;

    // B column precompute (column fixed per thread across k-tiles)
    const int nn = tid & 127;
    const int n  = n0 + nn;
    const int kb = tid >> 7;                    // 0 or 1
    const int hsel = n / dout;
    const size_t colbase = (size_t)hsel * (size_t)K * (size_t)dout + (size_t)(n - hsel * dout);

    // A load slots
    const int ka = tid & 15;
    const int mrow0 = tid >> 4;

    float acc[8][8];
#pragma unroll
    for (int i = 0; i < 8; i++)
#pragma unroll
        for (int j = 0; j < 8; j++) acc[i][j] = 0.f;

    for (int k0 = 0; k0 < K; k0 += 16) {
#pragma unroll
        for (int i = 0; i < 8; i++) {
            int mm = mrow0 + i * 16;
            As[ka][mm] = A[(size_t)(m0 + mm) * K + k0 + ka];
        }
#pragma unroll
        for (int i = 0; i < 8; i++) {
            int kk = kb + 2 * i;
            Bs[kk][nn] = Bm[colbase + (size_t)(k0 + kk) * dout];
        }
        __syncthreads();
#pragma unroll
        for (int kk = 0; kk < 16; kk++) {
            float a[8], bb[8];
#pragma unroll
            for (int i = 0; i < 4; i++) { a[i] = As[kk][ty * 4 + i]; a[i + 4] = As[kk][64 + ty * 4 + i]; }
#pragma unroll
            for (int j = 0; j < 4; j++) { bb[j] = Bs[kk][tx * 4 + j]; bb[j + 4] = Bs[kk][64 + tx * 4 + j]; }
#pragma unroll
            for (int i = 0; i < 8; i++)
#pragma unroll
                for (int j = 0; j < 8; j++)
                    acc[i][j] = fmaf(a[i], bb[j], acc[i][j]);
        }
        __syncthreads();
    }

#pragma unroll
    for (int i = 0; i < 8; i++) {
        int r = m0 + ((i < 4) ? ty * 4 + i : 64 + ty * 4 + (i - 4));
#pragma unroll
        for (int j = 0; j < 8; j++) {
            int c = n0 + ((j < 4) ? tx * 4 + j : 64 + tx * 4 + (j - 4));
            float v = acc[i][j];
            if (bias) v += bias[c];
            if (res)  v += res[(size_t)r * N + c];
            if (relu) v = fmaxf(v, 0.f);
            C[(size_t)r * N + c] = v;
        }
    }
}

// ---------------- batched scores: S[z,s,t] = Q . K / 32 ---------------------
// grid (8, 8, 64), z = h*4 + b
__global__ void __launch_bounds__(256) scores128(
    const float* __restrict__ Q, const float* __restrict__ Kp, float* __restrict__ Sc)
{
    __shared__ float Qs[32][129];   // [e][s]
    __shared__ float Ks[32][129];   // [e][t]
    const int tid = threadIdx.x;
    const int tx = tid & 15, ty = tid >> 4;
    const int z = blockIdx.z, h = z >> 2, b = z & 3;
    const int s0 = blockIdx.y * 128, t0 = blockIdx.x * 128;

    float acc[8][8];
#pragma unroll
    for (int i = 0; i < 8; i++)
#pragma unroll
        for (int j = 0; j < 8; j++) acc[i][j] = 0.f;

    const int el = tid & 31;
    const int r0 = tid >> 5;

    for (int e0 = 0; e0 < 64; e0 += 32) {
#pragma unroll
        for (int i = 0; i < 16; i++) {
            int r = r0 + i * 8;
            Qs[el][r] = Q [(size_t)(b * S_SZ + s0 + r) * 1024 + h * 64 + e0 + el];
            Ks[el][r] = Kp[(size_t)(b * S_SZ + t0 + r) * 1024 + h * 64 + e0 + el];
        }
        __syncthreads();
#pragma unroll
        for (int kk = 0; kk < 32; kk++) {
            float a[8], bb[8];
#pragma unroll
            for (int i = 0; i < 4; i++) { a[i] = Qs[kk][ty * 4 + i]; a[i + 4] = Qs[kk][64 + ty * 4 + i]; }
#pragma unroll
            for (int j = 0; j < 4; j++) { bb[j] = Ks[kk][tx * 4 + j]; bb[j + 4] = Ks[kk][64 + tx * 4 + j]; }
#pragma unroll
            for (int i = 0; i < 8; i++)
#pragma unroll
                for (int j = 0; j < 8; j++)
                    acc[i][j] = fmaf(a[i], bb[j], acc[i][j]);
        }
        __syncthreads();
    }

    const float scal = 0.03125f;   // 1/sqrt(1024)
#pragma unroll
    for (int i = 0; i < 8; i++) {
        int s = s0 + ((i < 4) ? ty * 4 + i : 64 + ty * 4 + (i - 4));
#pragma unroll
        for (int j = 0; j < 8; j++) {
            int t = t0 + ((j < 4) ? tx * 4 + j : 64 + tx * 4 + (j - 4));
            Sc[((size_t)z * S_SZ + s) * S_SZ + t] = acc[i][j] * scal;
        }
    }
}

// ---------------- softmax over t, scaled by (1-lambda) ----------------------
// one block per (hb, s) row
__global__ void __launch_bounds__(256) softmax_row(
    const float* __restrict__ Sc, const int* __restrict__ mask, float* __restrict__ Aout)
{
    __shared__ float red[8];
    __shared__ float bcast;
    size_t row = blockIdx.x;
    int b = (int)((row >> 10) & 3);
    const float* in = Sc + row * 1024;
    const int* mrow = mask + b * 1024;
    int t = threadIdx.x;
    int wid = t >> 5, lane = t & 31;

    float v[4];
    float mx = -INFINITY;
#pragma unroll
    for (int i = 0; i < 4; i++) {
        int c = t + i * 256;
        float val = in[c];
        if (mrow[c] == 0) val = -INFINITY;
        v[i] = val;
        mx = fmaxf(mx, val);
    }
#pragma unroll
    for (int o = 16; o; o >>= 1) mx = fmaxf(mx, __shfl_xor_sync(0xffffffffu, mx, o));
    if (lane == 0) red[wid] = mx;
    __syncthreads();
    if (t < 32) {
        float m2 = (t < 8) ? red[t] : -INFINITY;
#pragma unroll
        for (int o = 4; o; o >>= 1) m2 = fmaxf(m2, __shfl_xor_sync(0xffffffffu, m2, o));
        if (t == 0) bcast = m2;
    }
    __syncthreads();
    mx = bcast;

    float sum = 0.f;
#pragma unroll
    for (int i = 0; i < 4; i++) { v[i] = expf(v[i] - mx); sum += v[i]; }
#pragma unroll
    for (int o = 16; o; o >>= 1) sum += __shfl_xor_sync(0xffffffffu, sum, o);
    __syncthreads();
    if (lane == 0) red[wid] = sum;
    __syncthreads();
    if (t < 32) {
        float s2 = (t < 8) ? red[t] : 0.f;
#pragma unroll
        for (int o = 4; o; o >>= 1) s2 += __shfl_xor_sync(0xffffffffu, s2, o);
        if (t == 0) bcast = g_lamscale / s2;
    }
    __syncthreads();
    float sc = bcast;
#pragma unroll
    for (int i = 0; i < 4; i++)
        Aout[row * 1024 + t + i * 256] = v[i] * sc;
}

// ---------------- batched AV: O[z,s,v] = sum_t A[z,s,t] * V[b,t,h,v] --------
// grid (8, 64); N tile = 128 (full head value dim)
__global__ void __launch_bounds__(256) av128(
    const float* __restrict__ Am, const float* __restrict__ V, float* __restrict__ O)
{
    __shared__ float As_[16][129];
    __shared__ float Vs[16][129];
    const int tid = threadIdx.x;
    const int tx = tid & 15, ty = tid >> 4;
    const int z = blockIdx.y, h = z >> 2, b = z & 3;
    const int s0 = blockIdx.x * 128;

    float acc[8][8];
#pragma unroll
    for (int i = 0; i < 8; i++)
#pragma unroll
        for (int j = 0; j < 8; j++) acc[i][j] = 0.f;

    const int ka = tid & 15, mrow0 = tid >> 4;
    const int nn = tid & 127, kb = tid >> 7;

    for (int t0 = 0; t0 < 1024; t0 += 16) {
#pragma unroll
        for (int i = 0; i < 8; i++) {
            int mm = mrow0 + i * 16;
            As_[ka][mm] = Am[((size_t)z * S_SZ + s0 + mm) * 1024 + t0 + ka];
        }
#pragma unroll
        for (int i = 0; i < 8; i++) {
            int kk = kb + 2 * i;
            Vs[kk][nn] = V[(size_t)(b * S_SZ + t0 + kk) * 2048 + h * 128 + nn];
        }
        __syncthreads();
#pragma unroll
        for (int kk = 0; kk < 16; kk++) {
            float a[8], bb[8];
#pragma unroll
            for (int i = 0; i < 4; i++) { a[i] = As_[kk][ty * 4 + i]; a[i + 4] = As_[kk][64 + ty * 4 + i]; }
#pragma unroll
            for (int j = 0; j < 4; j++) { bb[j] = Vs[kk][tx * 4 + j]; bb[j + 4] = Vs[kk][64 + tx * 4 + j]; }
#pragma unroll
            for (int i = 0; i < 8; i++)
#pragma unroll
                for (int j = 0; j < 8; j++)
                    acc[i][j] = fmaf(a[i], bb[j], acc[i][j]);
        }
        __syncthreads();
    }

#pragma unroll
    for (int i = 0; i < 8; i++) {
        int s = s0 + ((i < 4) ? ty * 4 + i : 64 + ty * 4 + (i - 4));
#pragma unroll
        for (int j = 0; j < 8; j++) {
            int c = (j < 4) ? tx * 4 + j : 64 + tx * 4 + (j - 4);
            O[((size_t)z * S_SZ + s) * 128 + c] = acc[i][j];
        }
    }
}

// ---------------- per-head LayerNorm(128) + scale + concat ------------------
// one warp per (hb, s) row; 8 rows per block
__global__ void __launch_bounds__(256) headln_kernel(
    const float* __restrict__ O, const float* __restrict__ w,
    const float* __restrict__ bvec, float* __restrict__ Ocat)
{
    int gw = blockIdx.x * 8 + (threadIdx.x >> 5);
    int lane = threadIdx.x & 31;
    const float* xr = O + (size_t)gw * 128;
    float x0 = xr[lane], x1 = xr[lane + 32], x2 = xr[lane + 64], x3 = xr[lane + 96];
    float s = x0 + x1 + x2 + x3;
#pragma unroll
    for (int o = 16; o; o >>= 1) s += __shfl_xor_sync(0xffffffffu, s, o);
    float mean = s * (1.f / 128.f);
    float d0 = x0 - mean, d1 = x1 - mean, d2 = x2 - mean, d3 = x3 - mean;
    float q = d0 * d0 + d1 * d1 + d2 * d2 + d3 * d3;
#pragma unroll
    for (int o = 16; o; o >>= 1) q += __shfl_xor_sync(0xffffffffu, q, o);
    float rstd = rsqrtf(q * (1.f / 128.f) + 1e-5f);

    int z = gw >> 10, s_ = gw & 1023;
    int h = z >> 2, b = z & 3;
    size_t base = ((size_t)(b * S_SZ + s_)) * 2048 + h * 128;
    Ocat[base + lane]      = (d0 * rstd * w[lane]      + bvec[lane])      * HEADLN_SCALE;
    Ocat[base + lane + 32] = (d1 * rstd * w[lane + 32] + bvec[lane + 32]) * HEADLN_SCALE;
    Ocat[base + lane + 64] = (d2 * rstd * w[lane + 64] + bvec[lane + 64]) * HEADLN_SCALE;
    Ocat[base + lane + 96] = (d3 * rstd * w[lane + 96] + bvec[lane + 96]) * HEADLN_SCALE;
}

// ---------------- LayerNorm over 1024 ---------------------------------------
__global__ void __launch_bounds__(256) ln1024(
    const float* __restrict__ X, const float* __restrict__ w,
    const float* __restrict__ bvec, float* __restrict__ out)
{
    __shared__ float red[8];
    __shared__ float bc;
    size_t row = blockIdx.x;
    const float* xr = X + row * 1024;
    int t = threadIdx.x;
    int wid = t >> 5, lane = t & 31;

    float v[4];
    float s = 0.f;
#pragma unroll
    for (int i = 0; i < 4; i++) { v[i] = xr[t + i * 256]; s += v[i]; }
#pragma unroll
    for (int o = 16; o; o >>= 1) s += __shfl_xor_sync(0xffffffffu, s, o);
    if (lane == 0) red[wid] = s;
    __syncthreads();
    if (t < 32) {
        float s2 = (t < 8) ? red[t] : 0.f;
#pragma unroll
        for (int o = 4; o; o >>= 1) s2 += __shfl_xor_sync(0xffffffffu, s2, o);
        if (t == 0) bc = s2 * (1.f / 1024.f);
    }
    __syncthreads();
    float mean = bc;

    float q = 0.f;
#pragma unroll
    for (int i = 0; i < 4; i++) { float d = v[i] - mean; q += d * d; }
#pragma unroll
    for (int o = 16; o; o >>= 1) q += __shfl_xor_sync(0xffffffffu, q, o);
    __syncthreads();
    if (lane == 0) red[wid] = q;
    __syncthreads();
    if (t < 32) {
        float q2 = (t < 8) ? red[t] : 0.f;
#pragma unroll
        for (int o = 4; o; o >>= 1) q2 += __shfl_xor_sync(0xffffffffu, q2, o);
        if (t == 0) bc = rsqrtf(q2 * (1.f / 1024.f) + 1e-5f);
    }
    __syncthreads();
    float rstd = bc;
#pragma unroll
    for (int i = 0; i < 4; i++) {
        int c = t + i * 256;
        out[row * 1024 + c] = (v[i] - mean) * rstd * w[c] + bvec[c];
    }
}

// ---------------- host launcher ---------------------------------------------
extern "C" void kernel_launch(void* const* d_in, const int* in_sizes, int n_in,
                              void* d_out, int out_size)
{
    const float* x    = (const float*)d_in[0];
    const int*   mask = (const int*)  d_in[1];
    const float* WQ1  = (const float*)d_in[2];
    const float* bQ1  = (const float*)d_in[3];
    const float* WK1  = (const float*)d_in[4];
    const float* bK1  = (const float*)d_in[5];
    const float* WV   = (const float*)d_in[6];
    const float* bV   = (const float*)d_in[7];
    const float* lnhw = (const float*)d_in[8];
    const float* lnhb = (const float*)d_in[9];
    const float* WO   = (const float*)d_in[10];
    const float* bO   = (const float*)d_in[11];
    const float* ln1w = (const float*)d_in[12];
    const float* ln1b = (const float*)d_in[13];
    const float* ln2w = (const float*)d_in[14];
    const float* ln2b = (const float*)d_in[15];
    const float* W1   = (const float*)d_in[16];
    const float* b1   = (const float*)d_in[17];
    const float* W2   = (const float*)d_in[18];
    const float* b2   = (const float*)d_in[19];
    const float* lq1  = (const float*)d_in[20];
    const float* lk1  = (const float*)d_in[21];
    const float* lq2  = (const float*)d_in[22];
    const float* lk2  = (const float*)d_in[23];

    float* out = (float*)d_out;

    float *qp, *kp, *vp, *sp, *op, *ocat, *h1pre, *h1, *ffh, *r2pre;
    cudaGetSymbolAddress((void**)&qp,    g_Q);
    cudaGetSymbolAddress((void**)&kp,    g_Kb);
    cudaGetSymbolAddress((void**)&vp,    g_V);
    cudaGetSymbolAddress((void**)&sp,    g_S);
    cudaGetSymbolAddress((void**)&op,    g_O);
    cudaGetSymbolAddress((void**)&ocat,  g_Ocat);
    cudaGetSymbolAddress((void**)&h1pre, g_h1pre);
    cudaGetSymbolAddress((void**)&h1,    g_h1);
    cudaGetSymbolAddress((void**)&ffh,   g_ffh);
    cudaGetSymbolAddress((void**)&r2pre, g_r2pre);

    // A goes straight into d_out when the harness expects (r2, A); else scratch.
    float* A_ptr = (out_size >= FULL_ELEMS) ? (out + R2_ELEMS) : sp;

    lam_kernel<<<1, 64>>>(lq1, lk1, lq2, lk2);

    // QKV projections
    gemm128<<<dim3(8, 32),  256>>>(x, WQ1, bQ1, nullptr, qp, NTOK, 1024, 1024, 64, 0);
    gemm128<<<dim3(8, 32),  256>>>(x, WK1, bK1, nullptr, kp, NTOK, 1024, 1024, 64, 0);
    gemm128<<<dim3(16, 32), 256>>>(x, WV,  bV,  nullptr, vp, NTOK, 2048, 1024, 128, 0);

    // attention
    scores128<<<dim3(8, 8, 64), 256>>>(qp, kp, sp);
    softmax_row<<<65536, 256>>>(sp, mask, A_ptr);
    av128<<<dim3(8, 64), 256>>>(A_ptr, vp, op);
    headln_kernel<<<8192, 256>>>(op, lnhw, lnhb, ocat);

    // output projection + residual, LN1
    gemm128<<<dim3(8, 32), 256>>>(ocat, WO, bO, x, h1pre, NTOK, 1024, 2048, 1024, 0);
    ln1024<<<4096, 256>>>(h1pre, ln1w, ln1b, h1);

    // FFN + residual, LN2 -> r2 into d_out
    gemm128<<<dim3(32, 32), 256>>>(h1, W1, b1, nullptr, ffh, NTOK, 4096, 1024, 4096, 1);
    gemm128<<<dim3(8, 32),  256>>>(ffh, W2, b2, h1, r2pre, NTOK, 1024, 4096, 1024, 0);
    ln1024<<<4096, 256>>>(r2pre, ln2w, ln2b, out);
}

// round 4
// speedup vs baseline: 1.0002x; 1.0002x over previous
#include <cuda_runtime.h>
#include <math.h>
#include <stddef.h>

// Problem constants
#define B_SZ   4
#define S_SZ   1024
#define D_M    1024
#define H_N    16
#define D_INT  64
#define D_V    128      // 2*D_INT
#define HID    4096
#define NTOK   4096     // B*S
#define HB     64       // H*B
#define LAMBDA_INIT 0.3555090675909693f
#define HEADLN_SCALE 0.6444909324090307f   // 1 - LAMBDA_INIT
#define R2_ELEMS 4194304                    // B*S*D_M
#define FULL_ELEMS 71303168                 // R2 + H*B*S*S

// ---------------- scratch (static device memory; no allocation) -------------
__device__ float g_Q[(size_t)NTOK * (H_N * D_INT)];          // [tok][h*64+e]
__device__ float g_Kb[(size_t)NTOK * (H_N * D_INT)];
__device__ float g_V[(size_t)NTOK * (H_N * D_V)];            // [tok][h*128+v]
__device__ float g_S[(size_t)HB * S_SZ * S_SZ];              // scores / A scratch
__device__ float g_O[(size_t)HB * S_SZ * D_V];               // [hb][s][v]
__device__ float g_Ocat[(size_t)NTOK * (H_N * D_V)];         // [tok][h*128+v]
__device__ float g_h1pre[(size_t)NTOK * D_M];
__device__ float g_h1[(size_t)NTOK * D_M];
__device__ float g_ffh[(size_t)NTOK * HID];
__device__ float g_r2pre[(size_t)NTOK * D_M];
__device__ float g_lamscale;                                  // 1 - lambda

// ---------------- lambda ----------------------------------------------------
__global__ void lam_kernel(const float* __restrict__ lq1, const float* __restrict__ lk1,
                           const float* __restrict__ lq2, const float* __restrict__ lk2)
{
    __shared__ float s1[64], s2[64];
    int t = threadIdx.x;
    s1[t] = lq1[t] * lk1[t];
    s2[t] = lq2[t] * lk2[t];
    __syncthreads();
    if (t == 0) {
        float d1 = 0.f, d2 = 0.f;
        for (int i = 0; i < 64; i++) { d1 += s1[i]; d2 += s2[i]; }
        float lam = expf(d1) - expf(d2) + LAMBDA_INIT;
        g_lamscale = 1.0f - lam;
    }
}

// ---------------- generic GEMM: C = A[M,K] @ B + bias + res, optional relu --
// B element (k, n) lives at Bm[(n/dout)*K*dout + k*dout + (n%dout)]
// (dout==N -> plain row-major [K,N]; dout=64/128 -> per-head stacked weights)
__global__ void __launch_bounds__(256) gemm128(
    const float* __restrict__ A, const float* __restrict__ Bm,
    const float* __restrict__ bias, const float* __restrict__ res,
    float* __restrict__ C, int M, int N, int K, int dout, int relu)
{
    __shared__ float As[16][129];
    __shared__ float Bs[16][129];
    const int tid = threadIdx.x;
    const int tx = tid & 15, ty = tid >> 4;
    const int m0 = blockIdx.y * 128, n0 = blockIdx.x * 128;

    // B column precompute (column fixed per thread across k-tiles)
    const int nn = tid & 127;
    const int n  = n0 + nn;
    const int kb = tid >> 7;                    // 0 or 1
    const int hsel = n / dout;
    const size_t colbase = (size_t)hsel * (size_t)K * (size_t)dout + (size_t)(n - hsel * dout);

    // A load slots
    const int ka = tid & 15;
    const int mrow0 = tid >> 4;

    float acc[8][8];
#pragma unroll
    for (int i = 0; i < 8; i++)
#pragma unroll
        for (int j = 0; j < 8; j++) acc[i][j] = 0.f;

    for (int k0 = 0; k0 < K; k0 += 16) {
#pragma unroll
        for (int i = 0; i < 8; i++) {
            int mm = mrow0 + i * 16;
            As[ka][mm] = A[(size_t)(m0 + mm) * K + k0 + ka];
        }
#pragma unroll
        for (int i = 0; i < 8; i++) {
            int kk = kb + 2 * i;
            Bs[kk][nn] = Bm[colbase + (size_t)(k0 + kk) * dout];
        }
        __syncthreads();
#pragma unroll
        for (int kk = 0; kk < 16; kk++) {
            float a[8], bb[8];
#pragma unroll
            for (int i = 0; i < 4; i++) { a[i] = As[kk][ty * 4 + i]; a[i + 4] = As[kk][64 + ty * 4 + i]; }
#pragma unroll
            for (int j = 0; j < 4; j++) { bb[j] = Bs[kk][tx * 4 + j]; bb[j + 4] = Bs[kk][64 + tx * 4 + j]; }
#pragma unroll
            for (int i = 0; i < 8; i++)
#pragma unroll
                for (int j = 0; j < 8; j++)
                    acc[i][j] = fmaf(a[i], bb[j], acc[i][j]);
        }
        __syncthreads();
    }

#pragma unroll
    for (int i = 0; i < 8; i++) {
        int r = m0 + ((i < 4) ? ty * 4 + i : 64 + ty * 4 + (i - 4));
#pragma unroll
        for (int j = 0; j < 8; j++) {
            int c = n0 + ((j < 4) ? tx * 4 + j : 64 + tx * 4 + (j - 4));
            float v = acc[i][j];
            if (bias) v += bias[c];
            if (res)  v += res[(size_t)r * N + c];
            if (relu) v = fmaxf(v, 0.f);
            C[(size_t)r * N + c] = v;
        }
    }
}

// ---------------- batched scores: S[z,s,t] = Q . K / 32 ---------------------
// grid (8, 8, 64), z = h*4 + b
__global__ void __launch_bounds__(256) scores128(
    const float* __restrict__ Q, const float* __restrict__ Kp, float* __restrict__ Sc)
{
    __shared__ float Qs[32][129];   // [e][s]
    __shared__ float Ks[32][129];   // [e][t]
    const int tid = threadIdx.x;
    const int tx = tid & 15, ty = tid >> 4;
    const int z = blockIdx.z, h = z >> 2, b = z & 3;
    const int s0 = blockIdx.y * 128, t0 = blockIdx.x * 128;

    float acc[8][8];
#pragma unroll
    for (int i = 0; i < 8; i++)
#pragma unroll
        for (int j = 0; j < 8; j++) acc[i][j] = 0.f;

    const int el = tid & 31;
    const int r0 = tid >> 5;

    for (int e0 = 0; e0 < 64; e0 += 32) {
#pragma unroll
        for (int i = 0; i < 16; i++) {
            int r = r0 + i * 8;
            Qs[el][r] = Q [(size_t)(b * S_SZ + s0 + r) * 1024 + h * 64 + e0 + el];
            Ks[el][r] = Kp[(size_t)(b * S_SZ + t0 + r) * 1024 + h * 64 + e0 + el];
        }
        __syncthreads();
#pragma unroll
        for (int kk = 0; kk < 32; kk++) {
            float a[8], bb[8];
#pragma unroll
            for (int i = 0; i < 4; i++) { a[i] = Qs[kk][ty * 4 + i]; a[i + 4] = Qs[kk][64 + ty * 4 + i]; }
#pragma unroll
            for (int j = 0; j < 4; j++) { bb[j] = Ks[kk][tx * 4 + j]; bb[j + 4] = Ks[kk][64 + tx * 4 + j]; }
#pragma unroll
            for (int i = 0; i < 8; i++)
#pragma unroll
                for (int j = 0; j < 8; j++)
                    acc[i][j] = fmaf(a[i], bb[j], acc[i][j]);
        }
        __syncthreads();
    }

    const float scal = 0.03125f;   // 1/sqrt(1024)
#pragma unroll
    for (int i = 0; i < 8; i++) {
        int s = s0 + ((i < 4) ? ty * 4 + i : 64 + ty * 4 + (i - 4));
#pragma unroll
        for (int j = 0; j < 8; j++) {
            int t = t0 + ((j < 4) ? tx * 4 + j : 64 + tx * 4 + (j - 4));
            Sc[((size_t)z * S_SZ + s) * S_SZ + t] = acc[i][j] * scal;
        }
    }
}

// ---------------- softmax over t, scaled by (1-lambda) ----------------------
// one block per (hb, s) row
__global__ void __launch_bounds__(256) softmax_row(
    const float* __restrict__ Sc, const int* __restrict__ mask, float* __restrict__ Aout)
{
    __shared__ float red[8];
    __shared__ float bcast;
    size_t row = blockIdx.x;
    int b = (int)((row >> 10) & 3);
    const float* in = Sc + row * 1024;
    const int* mrow = mask + b * 1024;
    int t = threadIdx.x;
    int wid = t >> 5, lane = t & 31;

    float v[4];
    float mx = -INFINITY;
#pragma unroll
    for (int i = 0; i < 4; i++) {
        int c = t + i * 256;
        float val = in[c];
        if (mrow[c] == 0) val = -INFINITY;
        v[i] = val;
        mx = fmaxf(mx, val);
    }
#pragma unroll
    for (int o = 16; o; o >>= 1) mx = fmaxf(mx, __shfl_xor_sync(0xffffffffu, mx, o));
    if (lane == 0) red[wid] = mx;
    __syncthreads();
    if (t < 32) {
        float m2 = (t < 8) ? red[t] : -INFINITY;
#pragma unroll
        for (int o = 4; o; o >>= 1) m2 = fmaxf(m2, __shfl_xor_sync(0xffffffffu, m2, o));
        if (t == 0) bcast = m2;
    }
    __syncthreads();
    mx = bcast;

    float sum = 0.f;
#pragma unroll
    for (int i = 0; i < 4; i++) { v[i] = expf(v[i] - mx); sum += v[i]; }
#pragma unroll
    for (int o = 16; o; o >>= 1) sum += __shfl_xor_sync(0xffffffffu, sum, o);
    __syncthreads();
    if (lane == 0) red[wid] = sum;
    __syncthreads();
    if (t < 32) {
        float s2 = (t < 8) ? red[t] : 0.f;
#pragma unroll
        for (int o = 4; o; o >>= 1) s2 += __shfl_xor_sync(0xffffffffu, s2, o);
        if (t == 0) bcast = g_lamscale / s2;
    }
    __syncthreads();
    float sc = bcast;
#pragma unroll
    for (int i = 0; i < 4; i++)
        Aout[row * 1024 + t + i * 256] = v[i] * sc;
}

// ---------------- batched AV: O[z,s,v] = sum_t A[z,s,t] * V[b,t,h,v] --------
// grid (8, 64); N tile = 128 (full head value dim)
__global__ void __launch_bounds__(256) av128(
    const float* __restrict__ Am, const float* __restrict__ V, float* __restrict__ O)
{
    __shared__ float As_[16][129];
    __shared__ float Vs[16][129];
    const int tid = threadIdx.x;
    const int tx = tid & 15, ty = tid >> 4;
    const int z = blockIdx.y, h = z >> 2, b = z & 3;
    const int s0 = blockIdx.x * 128;

    float acc[8][8];
#pragma unroll
    for (int i = 0; i < 8; i++)
#pragma unroll
        for (int j = 0; j < 8; j++) acc[i][j] = 0.f;

    const int ka = tid & 15, mrow0 = tid >> 4;
    const int nn = tid & 127, kb = tid >> 7;

    for (int t0 = 0; t0 < 1024; t0 += 16) {
#pragma unroll
        for (int i = 0; i < 8; i++) {
            int mm = mrow0 + i * 16;
            As_[ka][mm] = Am[((size_t)z * S_SZ + s0 + mm) * 1024 + t0 + ka];
        }
#pragma unroll
        for (int i = 0; i < 8; i++) {
            int kk = kb + 2 * i;
            Vs[kk][nn] = V[(size_t)(b * S_SZ + t0 + kk) * 2048 + h * 128 + nn];
        }
        __syncthreads();
#pragma unroll
        for (int kk = 0; kk < 16; kk++) {
            float a[8], bb[8];
#pragma unroll
            for (int i = 0; i < 4; i++) { a[i] = As_[kk][ty * 4 + i]; a[i + 4] = As_[kk][64 + ty * 4 + i]; }
#pragma unroll
            for (int j = 0; j < 4; j++) { bb[j] = Vs[kk][tx * 4 + j]; bb[j + 4] = Vs[kk][64 + tx * 4 + j]; }
#pragma unroll
            for (int i = 0; i < 8; i++)
#pragma unroll
                for (int j = 0; j < 8; j++)
                    acc[i][j] = fmaf(a[i], bb[j], acc[i][j]);
        }
        __syncthreads();
    }

#pragma unroll
    for (int i = 0; i < 8; i++) {
        int s = s0 + ((i < 4) ? ty * 4 + i : 64 + ty * 4 + (i - 4));
#pragma unroll
        for (int j = 0; j < 8; j++) {
            int c = (j < 4) ? tx * 4 + j : 64 + tx * 4 + (j - 4);
            O[((size_t)z * S_SZ + s) * 128 + c] = acc[i][j];
        }
    }
}

// ---------------- per-head LayerNorm(128) + scale + concat ------------------
// one warp per (hb, s) row; 8 rows per block
__global__ void __launch_bounds__(256) headln_kernel(
    const float* __restrict__ O, const float* __restrict__ w,
    const float* __restrict__ bvec, float* __restrict__ Ocat)
{
    int gw = blockIdx.x * 8 + (threadIdx.x >> 5);
    int lane = threadIdx.x & 31;
    const float* xr = O + (size_t)gw * 128;
    float x0 = xr[lane], x1 = xr[lane + 32], x2 = xr[lane + 64], x3 = xr[lane + 96];
    float s = x0 + x1 + x2 + x3;
#pragma unroll
    for (int o = 16; o; o >>= 1) s += __shfl_xor_sync(0xffffffffu, s, o);
    float mean = s * (1.f / 128.f);
    float d0 = x0 - mean, d1 = x1 - mean, d2 = x2 - mean, d3 = x3 - mean;
    float q = d0 * d0 + d1 * d1 + d2 * d2 + d3 * d3;
#pragma unroll
    for (int o = 16; o; o >>= 1) q += __shfl_xor_sync(0xffffffffu, q, o);
    float rstd = rsqrtf(q * (1.f / 128.f) + 1e-5f);

    int z = gw >> 10, s_ = gw & 1023;
    int h = z >> 2, b = z & 3;
    size_t base = ((size_t)(b * S_SZ + s_)) * 2048 + h * 128;
    Ocat[base + lane]      = (d0 * rstd * w[lane]      + bvec[lane])      * HEADLN_SCALE;
    Ocat[base + lane + 32] = (d1 * rstd * w[lane + 32] + bvec[lane + 32]) * HEADLN_SCALE;
    Ocat[base + lane + 64] = (d2 * rstd * w[lane + 64] + bvec[lane + 64]) * HEADLN_SCALE;
    Ocat[base + lane + 96] = (d3 * rstd * w[lane + 96] + bvec[lane + 96]) * HEADLN_SCALE;
}

// ---------------- LayerNorm over 1024 ---------------------------------------
__global__ void __launch_bounds__(256) ln1024(
    const float* __restrict__ X, const float* __restrict__ w,
    const float* __restrict__ bvec, float* __restrict__ out)
{
    __shared__ float red[8];
    __shared__ float bc;
    size_t row = blockIdx.x;
    const float* xr = X + row * 1024;
    int t = threadIdx.x;
    int wid = t >> 5, lane = t & 31;

    float v[4];
    float s = 0.f;
#pragma unroll
    for (int i = 0; i < 4; i++) { v[i] = xr[t + i * 256]; s += v[i]; }
#pragma unroll
    for (int o = 16; o; o >>= 1) s += __shfl_xor_sync(0xffffffffu, s, o);
    if (lane == 0) red[wid] = s;
    __syncthreads();
    if (t < 32) {
        float s2 = (t < 8) ? red[t] : 0.f;
#pragma unroll
        for (int o = 4; o; o >>= 1) s2 += __shfl_xor_sync(0xffffffffu, s2, o);
        if (t == 0) bc = s2 * (1.f / 1024.f);
    }
    __syncthreads();
    float mean = bc;

    float q = 0.f;
#pragma unroll
    for (int i = 0; i < 4; i++) { float d = v[i] - mean; q += d * d; }
#pragma unroll
    for (int o = 16; o; o >>= 1) q += __shfl_xor_sync(0xffffffffu, q, o);
    __syncthreads();
    if (lane == 0) red[wid] = q;
    __syncthreads();
    if (t < 32) {
        float q2 = (t < 8) ? red[t] : 0.f;
#pragma unroll
        for (int o = 4; o; o >>= 1) q2 += __shfl_xor_sync(0xffffffffu, q2, o);
        if (t == 0) bc = rsqrtf(q2 * (1.f / 1024.f) + 1e-5f);
    }
    __syncthreads();
    float rstd = bc;
#pragma unroll
    for (int i = 0; i < 4; i++) {
        int c = t + i * 256;
        out[row * 1024 + c] = (v[i] - mean) * rstd * w[c] + bvec[c];
    }
}

// ---------------- host launcher ---------------------------------------------
extern "C" void kernel_launch(void* const* d_in, const int* in_sizes, int n_in,
                              void* d_out, int out_size)
{
    const float* x    = (const float*)d_in[0];
    const int*   mask = (const int*)  d_in[1];
    const float* WQ1  = (const float*)d_in[2];
    const float* bQ1  = (const float*)d_in[3];
    const float* WK1  = (const float*)d_in[4];
    const float* bK1  = (const float*)d_in[5];
    const float* WV   = (const float*)d_in[6];
    const float* bV   = (const float*)d_in[7];
    const float* lnhw = (const float*)d_in[8];
    const float* lnhb = (const float*)d_in[9];
    const float* WO   = (const float*)d_in[10];
    const float* bO   = (const float*)d_in[11];
    const float* ln1w = (const float*)d_in[12];
    const float* ln1b = (const float*)d_in[13];
    const float* ln2w = (const float*)d_in[14];
    const float* ln2b = (const float*)d_in[15];
    const float* W1   = (const float*)d_in[16];
    const float* b1   = (const float*)d_in[17];
    const float* W2   = (const float*)d_in[18];
    const float* b2   = (const float*)d_in[19];
    const float* lq1  = (const float*)d_in[20];
    const float* lk1  = (const float*)d_in[21];
    const float* lq2  = (const float*)d_in[22];
    const float* lk2  = (const float*)d_in[23];

    float* out = (float*)d_out;

    float *qp, *kp, *vp, *sp, *op, *ocat, *h1pre, *h1, *ffh, *r2pre;
    cudaGetSymbolAddress((void**)&qp,    g_Q);
    cudaGetSymbolAddress((void**)&kp,    g_Kb);
    cudaGetSymbolAddress((void**)&vp,    g_V);
    cudaGetSymbolAddress((void**)&sp,    g_S);
    cudaGetSymbolAddress((void**)&op,    g_O);
    cudaGetSymbolAddress((void**)&ocat,  g_Ocat);
    cudaGetSymbolAddress((void**)&h1pre, g_h1pre);
    cudaGetSymbolAddress((void**)&h1,    g_h1);
    cudaGetSymbolAddress((void**)&ffh,   g_ffh);
    cudaGetSymbolAddress((void**)&r2pre, g_r2pre);

    // A goes straight into d_out when the harness expects (r2, A); else scratch.
    float* A_ptr = (out_size >= FULL_ELEMS) ? (out + R2_ELEMS) : sp;

    lam_kernel<<<1, 64>>>(lq1, lk1, lq2, lk2);

    // QKV projections
    gemm128<<<dim3(8, 32),  256>>>(x, WQ1, bQ1, nullptr, qp, NTOK, 1024, 1024, 64, 0);
    gemm128<<<dim3(8, 32),  256>>>(x, WK1, bK1, nullptr, kp, NTOK, 1024, 1024, 64, 0);
    gemm128<<<dim3(16, 32), 256>>>(x, WV,  bV,  nullptr, vp, NTOK, 2048, 1024, 128, 0);

    // attention
    scores128<<<dim3(8, 8, 64), 256>>>(qp, kp, sp);
    softmax_row<<<65536, 256>>>(sp, mask, A_ptr);
    av128<<<dim3(8, 64), 256>>>(A_ptr, vp, op);
    headln_kernel<<<8192, 256>>>(op, lnhw, lnhb, ocat);

    // output projection + residual, LN1
    gemm128<<<dim3(8, 32), 256>>>(ocat, WO, bO, x, h1pre, NTOK, 1024, 2048, 1024, 0);
    ln1024<<<4096, 256>>>(h1pre, ln1w, ln1b, h1);

    // FFN + residual, LN2 -> r2 into d_out
    gemm128<<<dim3(32, 32), 256>>>(h1, W1, b1, nullptr, ffh, NTOK, 4096, 1024, 4096, 1);
    gemm128<<<dim3(8, 32),  256>>>(ffh, W2, b2, h1, r2pre, NTOK, 1024, 4096, 1024, 0);
    ln1024<<<4096, 256>>>(r2pre, ln2w, ln2b, out);
}

// round 5
// speedup vs baseline: 1.0049x; 1.0047x over previous
#include <cuda_runtime.h>
#include <math.h>
#include <stddef.h>

// Problem constants
#define B_SZ   4
#define S_SZ   1024
#define D_M    1024
#define H_N    16
#define D_INT  64
#define D_V    128      // 2*D_INT
#define HID    4096
#define NTOK   4096     // B*S
#define HB     64       // H*B
#define LAMBDA_INIT 0.3555090675909693f
#define HEADLN_SCALE 0.6444909324090307f   // 1 - LAMBDA_INIT
#define R2_ELEMS 4194304                    // B*S*D_M
#define FULL_ELEMS 71303168                 // R2 + H*B*S*S

// ---------------- scratch (static device memory; no allocation) -------------
__device__ float g_Q[(size_t)NTOK * (H_N * D_INT)];          // [tok][h*64+e]
__device__ float g_Kb[(size_t)NTOK * (H_N * D_INT)];
__device__ float g_V[(size_t)NTOK * (H_N * D_V)];            // [tok][h*128+v]
__device__ float g_S[(size_t)HB * S_SZ * S_SZ];              // scores / A scratch
__device__ float g_O[(size_t)HB * S_SZ * D_V];               // [hb][s][v]
__device__ float g_Ocat[(size_t)NTOK * (H_N * D_V)];         // [tok][h*128+v]
__device__ float g_h1pre[(size_t)NTOK * D_M];
__device__ float g_h1[(size_t)NTOK * D_M];
__device__ float g_ffh[(size_t)NTOK * HID];
__device__ float g_r2pre[(size_t)NTOK * D_M];
__device__ float g_lamscale;                                  // 1 - lambda

// ---------------- lambda ----------------------------------------------------
__global__ void lam_kernel(const float* __restrict__ lq1, const float* __restrict__ lk1,
                           const float* __restrict__ lq2, const float* __restrict__ lk2)
{
    __shared__ float s1[64], s2[64];
    int t = threadIdx.x;
    s1[t] = lq1[t] * lk1[t];
    s2[t] = lq2[t] * lk2[t];
    __syncthreads();
    if (t == 0) {
        float d1 = 0.f, d2 = 0.f;
        for (int i = 0; i < 64; i++) { d1 += s1[i]; d2 += s2[i]; }
        float lam = expf(d1) - expf(d2) + LAMBDA_INIT;
        g_lamscale = 1.0f - lam;
    }
}

// ---------------- generic GEMM: C = A[M,K] @ B + bias + res, optional relu --
// B element (k, n) lives at Bm[(n/dout)*K*dout + k*dout + (n%dout)]
// (dout==N -> plain row-major [K,N]; dout=64/128 -> per-head stacked weights)
__global__ void __launch_bounds__(256) gemm128(
    const float* __restrict__ A, const float* __restrict__ Bm,
    const float* __restrict__ bias, const float* __restrict__ res,
    float* __restrict__ C, int M, int N, int K, int dout, int relu)
{
    __shared__ float As[16][129];
    __shared__ float Bs[16][129];
    const int tid = threadIdx.x;
    const int tx = tid & 15, ty = tid >> 4;
    const int m0 = blockIdx.y * 128, n0 = blockIdx.x * 128;

    // B column precompute (column fixed per thread across k-tiles)
    const int nn = tid & 127;
    const int n  = n0 + nn;
    const int kb = tid >> 7;                    // 0 or 1
    const int hsel = n / dout;
    const size_t colbase = (size_t)hsel * (size_t)K * (size_t)dout + (size_t)(n - hsel * dout);

    // A load slots
    const int ka = tid & 15;
    const int mrow0 = tid >> 4;

    float acc[8][8];
#pragma unroll
    for (int i = 0; i < 8; i++)
#pragma unroll
        for (int j = 0; j < 8; j++) acc[i][j] = 0.f;

    for (int k0 = 0; k0 < K; k0 += 16) {
#pragma unroll
        for (int i = 0; i < 8; i++) {
            int mm = mrow0 + i * 16;
            As[ka][mm] = A[(size_t)(m0 + mm) * K + k0 + ka];
        }
#pragma unroll
        for (int i = 0; i < 8; i++) {
            int kk = kb + 2 * i;
            Bs[kk][nn] = Bm[colbase + (size_t)(k0 + kk) * dout];
        }
        __syncthreads();
#pragma unroll
        for (int kk = 0; kk < 16; kk++) {
            float a[8], bb[8];
#pragma unroll
            for (int i = 0; i < 4; i++) { a[i] = As[kk][ty * 4 + i]; a[i + 4] = As[kk][64 + ty * 4 + i]; }
#pragma unroll
            for (int j = 0; j < 4; j++) { bb[j] = Bs[kk][tx * 4 + j]; bb[j + 4] = Bs[kk][64 + tx * 4 + j]; }
#pragma unroll
            for (int i = 0; i < 8; i++)
#pragma unroll
                for (int j = 0; j < 8; j++)
                    acc[i][j] = fmaf(a[i], bb[j], acc[i][j]);
        }
        __syncthreads();
    }

#pragma unroll
    for (int i = 0; i < 8; i++) {
        int r = m0 + ((i < 4) ? ty * 4 + i : 64 + ty * 4 + (i - 4));
#pragma unroll
        for (int j = 0; j < 8; j++) {
            int c = n0 + ((j < 4) ? tx * 4 + j : 64 + tx * 4 + (j - 4));
            float v = acc[i][j];
            if (bias) v += bias[c];
            if (res)  v += res[(size_t)r * N + c];
            if (relu) v = fmaxf(v, 0.f);
            C[(size_t)r * N + c] = v;
        }
    }
}

// ---------------- batched scores: S[z,s,t] = Q . K / 32 ---------------------
// grid (8, 8, 64), z = h*4 + b
__global__ void __launch_bounds__(256) scores128(
    const float* __restrict__ Q, const float* __restrict__ Kp, float* __restrict__ Sc)
{
    __shared__ float Qs[32][129];   // [e][s]
    __shared__ float Ks[32][129];   // [e][t]
    const int tid = threadIdx.x;
    const int tx = tid & 15, ty = tid >> 4;
    const int z = blockIdx.z, h = z >> 2, b = z & 3;
    const int s0 = blockIdx.y * 128, t0 = blockIdx.x * 128;

    float acc[8][8];
#pragma unroll
    for (int i = 0; i < 8; i++)
#pragma unroll
        for (int j = 0; j < 8; j++) acc[i][j] = 0.f;

    const int el = tid & 31;
    const int r0 = tid >> 5;

    for (int e0 = 0; e0 < 64; e0 += 32) {
#pragma unroll
        for (int i = 0; i < 16; i++) {
            int r = r0 + i * 8;
            Qs[el][r] = Q [(size_t)(b * S_SZ + s0 + r) * 1024 + h * 64 + e0 + el];
            Ks[el][r] = Kp[(size_t)(b * S_SZ + t0 + r) * 1024 + h * 64 + e0 + el];
        }
        __syncthreads();
#pragma unroll
        for (int kk = 0; kk < 32; kk++) {
            float a[8], bb[8];
#pragma unroll
            for (int i = 0; i < 4; i++) { a[i] = Qs[kk][ty * 4 + i]; a[i + 4] = Qs[kk][64 + ty * 4 + i]; }
#pragma unroll
            for (int j = 0; j < 4; j++) { bb[j] = Ks[kk][tx * 4 + j]; bb[j + 4] = Ks[kk][64 + tx * 4 + j]; }
#pragma unroll
            for (int i = 0; i < 8; i++)
#pragma unroll
                for (int j = 0; j < 8; j++)
                    acc[i][j] = fmaf(a[i], bb[j], acc[i][j]);
        }
        __syncthreads();
    }

    const float scal = 0.03125f;   // 1/sqrt(1024)
#pragma unroll
    for (int i = 0; i < 8; i++) {
        int s = s0 + ((i < 4) ? ty * 4 + i : 64 + ty * 4 + (i - 4));
#pragma unroll
        for (int j = 0; j < 8; j++) {
            int t = t0 + ((j < 4) ? tx * 4 + j : 64 + tx * 4 + (j - 4));
            Sc[((size_t)z * S_SZ + s) * S_SZ + t] = acc[i][j] * scal;
        }
    }
}

// ---------------- softmax over t, scaled by (1-lambda) ----------------------
// one block per (hb, s) row
__global__ void __launch_bounds__(256) softmax_row(
    const float* __restrict__ Sc, const int* __restrict__ mask, float* __restrict__ Aout)
{
    __shared__ float red[8];
    __shared__ float bcast;
    size_t row = blockIdx.x;
    int b = (int)((row >> 10) & 3);
    const float* in = Sc + row * 1024;
    const int* mrow = mask + b * 1024;
    int t = threadIdx.x;
    int wid = t >> 5, lane = t & 31;

    float v[4];
    float mx = -INFINITY;
#pragma unroll
    for (int i = 0; i < 4; i++) {
        int c = t + i * 256;
        float val = in[c];
        if (mrow[c] == 0) val = -INFINITY;
        v[i] = val;
        mx = fmaxf(mx, val);
    }
#pragma unroll
    for (int o = 16; o; o >>= 1) mx = fmaxf(mx, __shfl_xor_sync(0xffffffffu, mx, o));
    if (lane == 0) red[wid] = mx;
    __syncthreads();
    if (t < 32) {
        float m2 = (t < 8) ? red[t] : -INFINITY;
#pragma unroll
        for (int o = 4; o; o >>= 1) m2 = fmaxf(m2, __shfl_xor_sync(0xffffffffu, m2, o));
        if (t == 0) bcast = m2;
    }
    __syncthreads();
    mx = bcast;

    float sum = 0.f;
#pragma unroll
    for (int i = 0; i < 4; i++) { v[i] = expf(v[i] - mx); sum += v[i]; }
#pragma unroll
    for (int o = 16; o; o >>= 1) sum += __shfl_xor_sync(0xffffffffu, sum, o);
    __syncthreads();
    if (lane == 0) red[wid] = sum;
    __syncthreads();
    if (t < 32) {
        float s2 = (t < 8) ? red[t] : 0.f;
#pragma unroll
        for (int o = 4; o; o >>= 1) s2 += __shfl_xor_sync(0xffffffffu, s2, o);
        if (t == 0) bcast = g_lamscale / s2;
    }
    __syncthreads();
    float sc = bcast;
#pragma unroll
    for (int i = 0; i < 4; i++)
        Aout[row * 1024 + t + i * 256] = v[i] * sc;
}

// ---------------- batched AV: O[z,s,v] = sum_t A[z,s,t] * V[b,t,h,v] --------
// grid (8, 64); N tile = 128 (full head value dim)
__global__ void __launch_bounds__(256) av128(
    const float* __restrict__ Am, const float* __restrict__ V, float* __restrict__ O)
{
    __shared__ float As_[16][129];
    __shared__ float Vs[16][129];
    const int tid = threadIdx.x;
    const int tx = tid & 15, ty = tid >> 4;
    const int z = blockIdx.y, h = z >> 2, b = z & 3;
    const int s0 = blockIdx.x * 128;

    float acc[8][8];
#pragma unroll
    for (int i = 0; i < 8; i++)
#pragma unroll
        for (int j = 0; j < 8; j++) acc[i][j] = 0.f;

    const int ka = tid & 15, mrow0 = tid >> 4;
    const int nn = tid & 127, kb = tid >> 7;

    for (int t0 = 0; t0 < 1024; t0 += 16) {
#pragma unroll
        for (int i = 0; i < 8; i++) {
            int mm = mrow0 + i * 16;
            As_[ka][mm] = Am[((size_t)z * S_SZ + s0 + mm) * 1024 + t0 + ka];
        }
#pragma unroll
        for (int i = 0; i < 8; i++) {
            int kk = kb + 2 * i;
            Vs[kk][nn] = V[(size_t)(b * S_SZ + t0 + kk) * 2048 + h * 128 + nn];
        }
        __syncthreads();
#pragma unroll
        for (int kk = 0; kk < 16; kk++) {
            float a[8], bb[8];
#pragma unroll
            for (int i = 0; i < 4; i++) { a[i] = As_[kk][ty * 4 + i]; a[i + 4] = As_[kk][64 + ty * 4 + i]; }
#pragma unroll
            for (int j = 0; j < 4; j++) { bb[j] = Vs[kk][tx * 4 + j]; bb[j + 4] = Vs[kk][64 + tx * 4 + j]; }
#pragma unroll
            for (int i = 0; i < 8; i++)
#pragma unroll
                for (int j = 0; j < 8; j++)
                    acc[i][j] = fmaf(a[i], bb[j], acc[i][j]);
        }
        __syncthreads();
    }

#pragma unroll
    for (int i = 0; i < 8; i++) {
        int s = s0 + ((i < 4) ? ty * 4 + i : 64 + ty * 4 + (i - 4));
#pragma unroll
        for (int j = 0; j < 8; j++) {
            int c = (j < 4) ? tx * 4 + j : 64 + tx * 4 + (j - 4);
            O[((size_t)z * S_SZ + s) * 128 + c] = acc[i][j];
        }
    }
}

// ---------------- per-head LayerNorm(128) + scale + concat ------------------
// one warp per (hb, s) row; 8 rows per block
__global__ void __launch_bounds__(256) headln_kernel(
    const float* __restrict__ O, const float* __restrict__ w,
    const float* __restrict__ bvec, float* __restrict__ Ocat)
{
    int gw = blockIdx.x * 8 + (threadIdx.x >> 5);
    int lane = threadIdx.x & 31;
    const float* xr = O + (size_t)gw * 128;
    float x0 = xr[lane], x1 = xr[lane + 32], x2 = xr[lane + 64], x3 = xr[lane + 96];
    float s = x0 + x1 + x2 + x3;
#pragma unroll
    for (int o = 16; o; o >>= 1) s += __shfl_xor_sync(0xffffffffu, s, o);
    float mean = s * (1.f / 128.f);
    float d0 = x0 - mean, d1 = x1 - mean, d2 = x2 - mean, d3 = x3 - mean;
    float q = d0 * d0 + d1 * d1 + d2 * d2 + d3 * d3;
#pragma unroll
    for (int o = 16; o; o >>= 1) q += __shfl_xor_sync(0xffffffffu, q, o);
    float rstd = rsqrtf(q * (1.f / 128.f) + 1e-5f);

    int z = gw >> 10, s_ = gw & 1023;
    int h = z >> 2, b = z & 3;
    size_t base = ((size_t)(b * S_SZ + s_)) * 2048 + h * 128;
    Ocat[base + lane]      = (d0 * rstd * w[lane]      + bvec[lane])      * HEADLN_SCALE;
    Ocat[base + lane + 32] = (d1 * rstd * w[lane + 32] + bvec[lane + 32]) * HEADLN_SCALE;
    Ocat[base + lane + 64] = (d2 * rstd * w[lane + 64] + bvec[lane + 64]) * HEADLN_SCALE;
    Ocat[base + lane + 96] = (d3 * rstd * w[lane + 96] + bvec[lane + 96]) * HEADLN_SCALE;
}

// ---------------- LayerNorm over 1024 ---------------------------------------
__global__ void __launch_bounds__(256) ln1024(
    const float* __restrict__ X, const float* __restrict__ w,
    const float* __restrict__ bvec, float* __restrict__ out)
{
    __shared__ float red[8];
    __shared__ float bc;
    size_t row = blockIdx.x;
    const float* xr = X + row * 1024;
    int t = threadIdx.x;
    int wid = t >> 5, lane = t & 31;

    float v[4];
    float s = 0.f;
#pragma unroll
    for (int i = 0; i < 4; i++) { v[i] = xr[t + i * 256]; s += v[i]; }
#pragma unroll
    for (int o = 16; o; o >>= 1) s += __shfl_xor_sync(0xffffffffu, s, o);
    if (lane == 0) red[wid] = s;
    __syncthreads();
    if (t < 32) {
        float s2 = (t < 8) ? red[t] : 0.f;
#pragma unroll
        for (int o = 4; o; o >>= 1) s2 += __shfl_xor_sync(0xffffffffu, s2, o);
        if (t == 0) bc = s2 * (1.f / 1024.f);
    }
    __syncthreads();
    float mean = bc;

    float q = 0.f;
#pragma unroll
    for (int i = 0; i < 4; i++) { float d = v[i] - mean; q += d * d; }
#pragma unroll
    for (int o = 16; o; o >>= 1) q += __shfl_xor_sync(0xffffffffu, q, o);
    __syncthreads();
    if (lane == 0) red[wid] = q;
    __syncthreads();
    if (t < 32) {
        float q2 = (t < 8) ? red[t] : 0.f;
#pragma unroll
        for (int o = 4; o; o >>= 1) q2 += __shfl_xor_sync(0xffffffffu, q2, o);
        if (t == 0) bc = rsqrtf(q2 * (1.f / 1024.f) + 1e-5f);
    }
    __syncthreads();
    float rstd = bc;
#pragma unroll
    for (int i = 0; i < 4; i++) {
        int c = t + i * 256;
        out[row * 1024 + c] = (v[i] - mean) * rstd * w[c] + bvec[c];
    }
}

// ---------------- host launcher ---------------------------------------------
extern "C" void kernel_launch(void* const* d_in, const int* in_sizes, int n_in,
                              void* d_out, int out_size)
{
    const float* x    = (const float*)d_in[0];
    const int*   mask = (const int*)  d_in[1];
    const float* WQ1  = (const float*)d_in[2];
    const float* bQ1  = (const float*)d_in[3];
    const float* WK1  = (const float*)d_in[4];
    const float* bK1  = (const float*)d_in[5];
    const float* WV   = (const float*)d_in[6];
    const float* bV   = (const float*)d_in[7];
    const float* lnhw = (const float*)d_in[8];
    const float* lnhb = (const float*)d_in[9];
    const float* WO   = (const float*)d_in[10];
    const float* bO   = (const float*)d_in[11];
    const float* ln1w = (const float*)d_in[12];
    const float* ln1b = (const float*)d_in[13];
    const float* ln2w = (const float*)d_in[14];
    const float* ln2b = (const float*)d_in[15];
    const float* W1   = (const float*)d_in[16];
    const float* b1   = (const float*)d_in[17];
    const float* W2   = (const float*)d_in[18];
    const float* b2   = (const float*)d_in[19];
    const float* lq1  = (const float*)d_in[20];
    const float* lk1  = (const float*)d_in[21];
    const float* lq2  = (const float*)d_in[22];
    const float* lk2  = (const float*)d_in[23];

    float* out = (float*)d_out;

    float *qp, *kp, *vp, *sp, *op, *ocat, *h1pre, *h1, *ffh, *r2pre;
    cudaGetSymbolAddress((void**)&qp,    g_Q);
    cudaGetSymbolAddress((void**)&kp,    g_Kb);
    cudaGetSymbolAddress((void**)&vp,    g_V);
    cudaGetSymbolAddress((void**)&sp,    g_S);
    cudaGetSymbolAddress((void**)&op,    g_O);
    cudaGetSymbolAddress((void**)&ocat,  g_Ocat);
    cudaGetSymbolAddress((void**)&h1pre, g_h1pre);
    cudaGetSymbolAddress((void**)&h1,    g_h1);
    cudaGetSymbolAddress((void**)&ffh,   g_ffh);
    cudaGetSymbolAddress((void**)&r2pre, g_r2pre);

    // A goes straight into d_out when the harness expects (r2, A); else scratch.
    float* A_ptr = (out_size >= FULL_ELEMS) ? (out + R2_ELEMS) : sp;

    lam_kernel<<<1, 64>>>(lq1, lk1, lq2, lk2);

    // QKV projections
    gemm128<<<dim3(8, 32),  256>>>(x, WQ1, bQ1, nullptr, qp, NTOK, 1024, 1024, 64, 0);
    gemm128<<<dim3(8, 32),  256>>>(x, WK1, bK1, nullptr, kp, NTOK, 1024, 1024, 64, 0);
    gemm128<<<dim3(16, 32), 256>>>(x, WV,  bV,  nullptr, vp, NTOK, 2048, 1024, 128, 0);

    // attention
    scores128<<<dim3(8, 8, 64), 256>>>(qp, kp, sp);
    softmax_row<<<65536, 256>>>(sp, mask, A_ptr);
    av128<<<dim3(8, 64), 256>>>(A_ptr, vp, op);
    headln_kernel<<<8192, 256>>>(op, lnhw, lnhb, ocat);

    // output projection + residual, LN1
    gemm128<<<dim3(8, 32), 256>>>(ocat, WO, bO, x, h1pre, NTOK, 1024, 2048, 1024, 0);
    ln1024<<<4096, 256>>>(h1pre, ln1w, ln1b, h1);

    // FFN + residual, LN2 -> r2 into d_out
    gemm128<<<dim3(32, 32), 256>>>(h1, W1, b1, nullptr, ffh, NTOK, 4096, 1024, 4096, 1);
    gemm128<<<dim3(8, 32),  256>>>(ffh, W2, b2, h1, r2pre, NTOK, 1024, 4096, 1024, 0);
    ln1024<<<4096, 256>>>(r2pre, ln2w, ln2b, out);
}

// round 7
// speedup vs baseline: 3.4420x; 3.4251x over previous
#include <cuda_runtime.h>
#include <cuda_bf16.h>
#include <math.h>
#include <stddef.h>
#include <stdint.h>

#define B_SZ   4
#define S_SZ   1024
#define D_M    1024
#define H_N    16
#define D_INT  64
#define D_V    128
#define HID    4096
#define NTOK   4096
#define HB     64
#define LAMBDA_INIT 0.3555090675909693f
#define HEADLN_SCALE 0.6444909324090307f
#define R2_ELEMS 4194304
#define FULL_ELEMS 71303168

// ======================= helpers =======================
__device__ __forceinline__ uint32_t smem_u32(const void* p) {
    uint32_t a;
    asm("{ .reg .u64 t; cvta.to.shared.u64 t, %1; cvt.u32.u64 %0, t; }" : "=r"(a) : "l"(p));
    return a;
}
#define CP_ASYNC16(sdst, gsrc) \
    asm volatile("cp.async.cg.shared.global [%0], [%1], 16;" :: "r"(sdst), "l"(gsrc) : "memory")
#define CP_COMMIT() asm volatile("cp.async.commit_group;" ::: "memory")
#define CP_WAIT0()  asm volatile("cp.async.wait_group 0;" ::: "memory")
#define CP_WAIT1()  asm volatile("cp.async.wait_group 1;" ::: "memory")

__device__ __forceinline__ void mma16816(float* d, uint32_t a0, uint32_t a1, uint32_t a2,
                                         uint32_t a3, uint32_t b0, uint32_t b1) {
    asm volatile(
        "mma.sync.aligned.m16n8k16.row.col.f32.bf16.bf16.f32 "
        "{%0,%1,%2,%3}, {%4,%5,%6,%7}, {%8,%9}, {%0,%1,%2,%3};"
        : "+f"(d[0]), "+f"(d[1]), "+f"(d[2]), "+f"(d[3])
        : "r"(a0), "r"(a1), "r"(a2), "r"(a3), "r"(b0), "r"(b1));
}

// ======================= static scratch =======================
__device__ __align__(16) float          g_QKV  [(size_t)NTOK * 4096];
__device__ __align__(16) __nv_bfloat16  g_QKVh [(size_t)NTOK * 4096];
__device__ __align__(16) __nv_bfloat16  g_QKVl [(size_t)NTOK * 4096];
__device__ __align__(16) __nv_bfloat16  g_Bqh  [(size_t)4096 * 1024];
__device__ __align__(16) __nv_bfloat16  g_Bql  [(size_t)4096 * 1024];
__device__ __align__(16) __nv_bfloat16  g_WOth [(size_t)1024 * 2048];
__device__ __align__(16) __nv_bfloat16  g_WOtl [(size_t)1024 * 2048];
__device__ __align__(16) __nv_bfloat16  g_W1th [(size_t)4096 * 1024];
__device__ __align__(16) __nv_bfloat16  g_W1tl [(size_t)4096 * 1024];
__device__ __align__(16) __nv_bfloat16  g_W2th [(size_t)1024 * 4096];
__device__ __align__(16) __nv_bfloat16  g_W2tl [(size_t)1024 * 4096];
__device__ __align__(16) float          g_biasqkv[4096];
__device__ __align__(16) __nv_bfloat16  g_xh   [(size_t)NTOK * 1024];
__device__ __align__(16) __nv_bfloat16  g_xl   [(size_t)NTOK * 1024];
__device__ __align__(16) float          g_S    [(size_t)HB * S_SZ * S_SZ];
__device__ __align__(16) __nv_bfloat16  g_Ah   [(size_t)HB * S_SZ * S_SZ];
__device__ __align__(16) __nv_bfloat16  g_Al   [(size_t)HB * S_SZ * S_SZ];
__device__ __align__(16) __nv_bfloat16  g_Vth  [(size_t)HB * 128 * 1024];
__device__ __align__(16) __nv_bfloat16  g_Vtl  [(size_t)HB * 128 * 1024];
__device__ __align__(16) float          g_O    [(size_t)HB * S_SZ * D_V];
__device__ __align__(16) float          g_Ocat [(size_t)NTOK * 2048];
__device__ __align__(16) __nv_bfloat16  g_Och  [(size_t)NTOK * 2048];
__device__ __align__(16) __nv_bfloat16  g_Ocl  [(size_t)NTOK * 2048];
__device__ __align__(16) float          g_h1pre[(size_t)NTOK * D_M];
__device__ __align__(16) float          g_h1   [(size_t)NTOK * D_M];
__device__ __align__(16) __nv_bfloat16  g_h1h  [(size_t)NTOK * D_M];
__device__ __align__(16) __nv_bfloat16  g_h1l  [(size_t)NTOK * D_M];
__device__ __align__(16) __nv_bfloat16  g_ffhh [(size_t)NTOK * HID];
__device__ __align__(16) __nv_bfloat16  g_ffhl [(size_t)NTOK * HID];
__device__ __align__(16) float          g_r2pre[(size_t)NTOK * D_M];
__device__ float g_lamscale;

// ======================= lambda =======================
__global__ void lam_kernel(const float* __restrict__ lq1, const float* __restrict__ lk1,
                           const float* __restrict__ lq2, const float* __restrict__ lk2)
{
    __shared__ float s1[64], s2[64];
    int t = threadIdx.x;
    s1[t] = lq1[t] * lk1[t];
    s2[t] = lq2[t] * lk2[t];
    __syncthreads();
    if (t == 0) {
        float d1 = 0.f, d2 = 0.f;
        for (int i = 0; i < 64; i++) { d1 += s1[i]; d2 += s2[i]; }
        g_lamscale = 1.0f - (expf(d1) - expf(d2) + LAMBDA_INIT);
    }
}

// ======================= conversions =======================
__global__ void __launch_bounds__(256) conv_hilo(
    const float* __restrict__ in, __nv_bfloat16* __restrict__ oh,
    __nv_bfloat16* __restrict__ ol, int n4)
{
    int i = blockIdx.x * 256 + threadIdx.x;
    if (i >= n4) return;
    float4 v = reinterpret_cast<const float4*>(in)[i];
    __nv_bfloat16 h0 = __float2bfloat16(v.x), h1 = __float2bfloat16(v.y);
    __nv_bfloat16 h2 = __float2bfloat16(v.z), h3 = __float2bfloat16(v.w);
    __nv_bfloat162 p0, p1, q0, q1;
    p0.x = h0; p0.y = h1; p1.x = h2; p1.y = h3;
    q0.x = __float2bfloat16(v.x - __bfloat162float(h0));
    q0.y = __float2bfloat16(v.y - __bfloat162float(h1));
    q1.x = __float2bfloat16(v.z - __bfloat162float(h2));
    q1.y = __float2bfloat16(v.w - __bfloat162float(h3));
    reinterpret_cast<__nv_bfloat162*>(oh)[i * 2]     = p0;
    reinterpret_cast<__nv_bfloat162*>(oh)[i * 2 + 1] = p1;
    reinterpret_cast<__nv_bfloat162*>(ol)[i * 2]     = q0;
    reinterpret_cast<__nv_bfloat162*>(ol)[i * 2 + 1] = q1;
}

// weight transpose-convert: out[n][k] (K-major) from in[(n/dout)*K*dout + k*dout + n%dout]
__global__ void convW(const float* __restrict__ in, __nv_bfloat16* __restrict__ oh,
                      __nv_bfloat16* __restrict__ ol, int K, int dout)
{
    __shared__ float t[32][33];
    int k0 = blockIdx.x * 32, n0 = blockIdx.y * 32;
    int h = n0 / dout, d0 = n0 - h * dout;
    const float* src = in + (size_t)h * K * dout + d0;
    for (int r = threadIdx.y; r < 32; r += 8)
        t[r][threadIdx.x] = src[(size_t)(k0 + r) * dout + threadIdx.x];
    __syncthreads();
    for (int r = threadIdx.y; r < 32; r += 8) {
        float v = t[threadIdx.x][r];
        __nv_bfloat16 hi = __float2bfloat16(v);
        size_t idx = (size_t)(n0 + r) * K + k0 + threadIdx.x;
        oh[idx] = hi;
        ol[idx] = __float2bfloat16(v - __bfloat162float(hi));
    }
}

// V transpose: Vt[z][v][t] from g_QKV[(b*1024+t)*4096 + 2048 + h*128 + v]
__global__ void convVt(const float* __restrict__ qkv, __nv_bfloat16* __restrict__ oh,
                       __nv_bfloat16* __restrict__ ol)
{
    __shared__ float t[32][33];
    int z = blockIdx.z, h = z >> 2, b = z & 3;
    int t0 = blockIdx.x * 32, v0 = blockIdx.y * 32;
    for (int r = threadIdx.y; r < 32; r += 8)
        t[r][threadIdx.x] = qkv[(size_t)(b * 1024 + t0 + r) * 4096 + 2048 + h * 128 + v0 + threadIdx.x];
    __syncthreads();
    size_t base = (size_t)z * 131072;
    for (int r = threadIdx.y; r < 32; r += 8) {
        float v = t[threadIdx.x][r];
        __nv_bfloat16 hi = __float2bfloat16(v);
        size_t idx = base + (size_t)(v0 + r) * 1024 + t0 + threadIdx.x;
        oh[idx] = hi;
        ol[idx] = __float2bfloat16(v - __bfloat162float(hi));
    }
}

__global__ void concat_bias(const float* __restrict__ bq, const float* __restrict__ bk,
                            const float* __restrict__ bv, float* __restrict__ o)
{
    int t = blockIdx.x * 256 + threadIdx.x;
    if (t < 1024) o[t] = bq[t];
    else if (t < 2048) o[t] = bk[t - 1024];
    else if (t < 4096) o[t] = bv[t - 2048];
}

// ======================= tensor-core GEMM (mma.sync bf16, 3-term split) ======
// C[128x128 tile] = sum_k A[m][k]*B[n][k], both K-major bf16 hi/lo.
// modes: 0 plain; 1 scores batched (z=h*4+b); 2 AV batched.
// smem per stage: Ah/Al/Bh/Bl, each 128 rows x 80 bytes (64B data + 16B pad).
#define STG_BYTES 40960
#define GEMM_SMEM_BYTES (2 * STG_BYTES)

__global__ void __launch_bounds__(256) gemm_mma(
    const __nv_bfloat16* __restrict__ Ah, const __nv_bfloat16* __restrict__ Al,
    const __nv_bfloat16* __restrict__ Bh, const __nv_bfloat16* __restrict__ Bl,
    const float* __restrict__ bias, const float* __restrict__ res,
    float* __restrict__ cout, __nv_bfloat16* __restrict__ outh, __nv_bfloat16* __restrict__ outl,
    int K, int lda, int ldb, int ldc, float alpha, int relu, int mode)
{
    extern __shared__ char dsm[];
    const int tid = threadIdx.x;
    const int lane = tid & 31, wid = tid >> 5;
    const int wy = wid >> 2, wx = wid & 3;       // warp tile: 64(M) x 32(N)
    const int m0 = blockIdx.y * 128, n0 = blockIdx.x * 128;
    const uint32_t smbase = smem_u32(dsm);

    size_t aoff = 0, boff = 0, coff = 0;
    if (mode == 1) {
        int z = blockIdx.z, h = z >> 2, b = z & 3;
        aoff = (size_t)(b << 10) * lda + (h << 6);
        boff = (size_t)(b << 10) * ldb + (h << 6);
        coff = (size_t)z << 20;
    } else if (mode == 2) {
        int z = blockIdx.z;
        aoff = (size_t)z << 20;
        boff = (size_t)z << 17;
        coff = (size_t)z << 17;
    }

    float acc[4][4][4];
#pragma unroll
    for (int i = 0; i < 4; i++)
#pragma unroll
        for (int j = 0; j < 4; j++)
#pragma unroll
            for (int q = 0; q < 4; q++) acc[i][j][q] = 0.f;

    const int niter = K >> 5;

    auto issue_tile = [&](int it, int stage) {
        int k0 = it << 5;
        uint32_t sb = smbase + stage * STG_BYTES;
#pragma unroll
        for (int i = 0; i < 2; i++) {
            int l = tid + (i << 8);
            int row = l >> 2, c16 = l & 3;
            size_t aidx = aoff + (size_t)(m0 + row) * lda + k0 + (c16 << 3);
            size_t bidx = boff + (size_t)(n0 + row) * ldb + k0 + (c16 << 3);
            uint32_t so = (uint32_t)(row * 80 + (c16 << 4));
            CP_ASYNC16(sb + so,         Ah + aidx);
            CP_ASYNC16(sb + 10240 + so, Al + aidx);
            CP_ASYNC16(sb + 20480 + so, Bh + bidx);
            CP_ASYNC16(sb + 30720 + so, Bl + bidx);
        }
        CP_COMMIT();
    };

    issue_tile(0, 0);

    const int g = lane >> 2;
    const int c2b = (lane & 3) << 2;   // byte offset of k pair within row

    for (int it = 0; it < niter; it++) {
        int st = it & 1;
        if (it + 1 < niter) { issue_tile(it + 1, st ^ 1); CP_WAIT1(); }
        else { CP_WAIT0(); }
        __syncthreads();

        const char* base = dsm + st * STG_BYTES;
        const char* pAh = base;
        const char* pAl = base + 10240;
        const char* pBh = base + 20480;
        const char* pBl = base + 30720;

#pragma unroll
        for (int ks = 0; ks < 2; ks++) {
            const int ksb = ks << 5;   // 16 bf16 = 32 bytes
            uint32_t bhf[4][2], blf[4][2];
#pragma unroll
            for (int nt = 0; nt < 4; nt++) {
                int ro = ((wx << 5) + (nt << 3) + g) * 80 + ksb + c2b;
                bhf[nt][0] = *(const uint32_t*)(pBh + ro);
                bhf[nt][1] = *(const uint32_t*)(pBh + ro + 16);
                blf[nt][0] = *(const uint32_t*)(pBl + ro);
                blf[nt][1] = *(const uint32_t*)(pBl + ro + 16);
            }
#pragma unroll
            for (int mt = 0; mt < 4; mt++) {
                int r0 = ((wy << 6) + (mt << 4) + g) * 80 + ksb + c2b;
                int r1 = r0 + 8 * 80;
                uint32_t ah0 = *(const uint32_t*)(pAh + r0);
                uint32_t ah1 = *(const uint32_t*)(pAh + r1);
                uint32_t ah2 = *(const uint32_t*)(pAh + r0 + 16);
                uint32_t ah3 = *(const uint32_t*)(pAh + r1 + 16);
                uint32_t al0 = *(const uint32_t*)(pAl + r0);
                uint32_t al1 = *(const uint32_t*)(pAl + r1);
                uint32_t al2 = *(const uint32_t*)(pAl + r0 + 16);
                uint32_t al3 = *(const uint32_t*)(pAl + r1 + 16);
#pragma unroll
                for (int nt = 0; nt < 4; nt++) {
                    mma16816(acc[mt][nt], ah0, ah1, ah2, ah3, bhf[nt][0], bhf[nt][1]);
                    mma16816(acc[mt][nt], ah0, ah1, ah2, ah3, blf[nt][0], blf[nt][1]);
                    mma16816(acc[mt][nt], al0, al1, al2, al3, bhf[nt][0], bhf[nt][1]);
                }
            }
        }
        __syncthreads();
    }

    // epilogue: alpha, bias, residual, relu; fp32 and/or bf16 hi/lo outputs
#pragma unroll
    for (int mt = 0; mt < 4; mt++) {
#pragma unroll
        for (int nt = 0; nt < 4; nt++) {
#pragma unroll
            for (int hf = 0; hf < 2; hf++) {
                int row = m0 + (wy << 6) + (mt << 4) + g + (hf << 3);
                int col = n0 + (wx << 5) + (nt << 3) + ((lane & 3) << 1);
                float v0 = acc[mt][nt][hf * 2]     * alpha;
                float v1 = acc[mt][nt][hf * 2 + 1] * alpha;
                if (bias) { v0 += bias[col]; v1 += bias[col + 1]; }
                if (res) {
                    float2 rv = *reinterpret_cast<const float2*>(res + (size_t)row * ldc + col);
                    v0 += rv.x; v1 += rv.y;
                }
                if (relu) { v0 = fmaxf(v0, 0.f); v1 = fmaxf(v1, 0.f); }
                size_t oidx = coff + (size_t)row * ldc + col;
                if (cout) *reinterpret_cast<float2*>(cout + oidx) = make_float2(v0, v1);
                if (outh) {
                    __nv_bfloat16 h0 = __float2bfloat16(v0), h1 = __float2bfloat16(v1);
                    __nv_bfloat162 ph, pl;
                    ph.x = h0; ph.y = h1;
                    pl.x = __float2bfloat16(v0 - __bfloat162float(h0));
                    pl.y = __float2bfloat16(v1 - __bfloat162float(h1));
                    *reinterpret_cast<__nv_bfloat162*>(outh + oidx) = ph;
                    *reinterpret_cast<__nv_bfloat162*>(outl + oidx) = pl;
                }
            }
        }
    }
}

// ======================= softmax (emits fp32 + bf16 hi/lo) ==================
__global__ void __launch_bounds__(256) softmax_row(
    const float* __restrict__ Sc, const int* __restrict__ mask, float* __restrict__ Aout,
    __nv_bfloat16* __restrict__ Ahi, __nv_bfloat16* __restrict__ Alo)
{
    __shared__ float red[8];
    __shared__ float bcast;
    size_t row = blockIdx.x;
    int b = (int)((row >> 10) & 3);
    const float* in = Sc + row * 1024;
    const int* mrow = mask + b * 1024;
    int t = threadIdx.x;
    int wid = t >> 5, lane = t & 31;

    float v[4];
    float mx = -INFINITY;
#pragma unroll
    for (int i = 0; i < 4; i++) {
        int c = t + i * 256;
        float val = in[c];
        if (mrow[c] == 0) val = -INFINITY;
        v[i] = val;
        mx = fmaxf(mx, val);
    }
#pragma unroll
    for (int o = 16; o; o >>= 1) mx = fmaxf(mx, __shfl_xor_sync(0xffffffffu, mx, o));
    if (lane == 0) red[wid] = mx;
    __syncthreads();
    if (t < 32) {
        float m2 = (t < 8) ? red[t] : -INFINITY;
#pragma unroll
        for (int o = 4; o; o >>= 1) m2 = fmaxf(m2, __shfl_xor_sync(0xffffffffu, m2, o));
        if (t == 0) bcast = m2;
    }
    __syncthreads();
    mx = bcast;

    float sum = 0.f;
#pragma unroll
    for (int i = 0; i < 4; i++) { v[i] = expf(v[i] - mx); sum += v[i]; }
#pragma unroll
    for (int o = 16; o; o >>= 1) sum += __shfl_xor_sync(0xffffffffu, sum, o);
    __syncthreads();
    if (lane == 0) red[wid] = sum;
    __syncthreads();
    if (t < 32) {
        float s2 = (t < 8) ? red[t] : 0.f;
#pragma unroll
        for (int o = 4; o; o >>= 1) s2 += __shfl_xor_sync(0xffffffffu, s2, o);
        if (t == 0) bcast = g_lamscale / s2;
    }
    __syncthreads();
    float sc = bcast;
#pragma unroll
    for (int i = 0; i < 4; i++) {
        size_t idx = row * 1024 + t + i * 256;
        float vv = v[i] * sc;
        Aout[idx] = vv;
        __nv_bfloat16 hi = __float2bfloat16(vv);
        Ahi[idx] = hi;
        Alo[idx] = __float2bfloat16(vv - __bfloat162float(hi));
    }
}

// ======================= per-head LN(128) + concat ==========================
__global__ void __launch_bounds__(256) headln_kernel(
    const float* __restrict__ O, const float* __restrict__ w,
    const float* __restrict__ bvec, float* __restrict__ Ocat)
{
    int gw = blockIdx.x * 8 + (threadIdx.x >> 5);
    int lane = threadIdx.x & 31;
    const float* xr = O + (size_t)gw * 128;
    float x0 = xr[lane], x1 = xr[lane + 32], x2 = xr[lane + 64], x3 = xr[lane + 96];
    float s = x0 + x1 + x2 + x3;
#pragma unroll
    for (int o = 16; o; o >>= 1) s += __shfl_xor_sync(0xffffffffu, s, o);
    float mean = s * (1.f / 128.f);
    float d0 = x0 - mean, d1 = x1 - mean, d2 = x2 - mean, d3 = x3 - mean;
    float q = d0 * d0 + d1 * d1 + d2 * d2 + d3 * d3;
#pragma unroll
    for (int o = 16; o; o >>= 1) q += __shfl_xor_sync(0xffffffffu, q, o);
    float rstd = rsqrtf(q * (1.f / 128.f) + 1e-5f);

    int z = gw >> 10, s_ = gw & 1023;
    int h = z >> 2, b = z & 3;
    size_t base = ((size_t)(b * S_SZ + s_)) * 2048 + h * 128;
    Ocat[base + lane]      = (d0 * rstd * w[lane]      + bvec[lane])      * HEADLN_SCALE;
    Ocat[base + lane + 32] = (d1 * rstd * w[lane + 32] + bvec[lane + 32]) * HEADLN_SCALE;
    Ocat[base + lane + 64] = (d2 * rstd * w[lane + 64] + bvec[lane + 64]) * HEADLN_SCALE;
    Ocat[base + lane + 96] = (d3 * rstd * w[lane + 96] + bvec[lane + 96]) * HEADLN_SCALE;
}

// ======================= LayerNorm 1024 =====================================
__global__ void __launch_bounds__(256) ln1024(
    const float* __restrict__ X, const float* __restrict__ w,
    const float* __restrict__ bvec, float* __restrict__ out)
{
    __shared__ float red[8];
    __shared__ float bc;
    size_t row = blockIdx.x;
    const float* xr = X + row * 1024;
    int t = threadIdx.x;
    int wid = t >> 5, lane = t & 31;

    float v[4];
    float s = 0.f;
#pragma unroll
    for (int i = 0; i < 4; i++) { v[i] = xr[t + i * 256]; s += v[i]; }
#pragma unroll
    for (int o = 16; o; o >>= 1) s += __shfl_xor_sync(0xffffffffu, s, o);
    if (lane == 0) red[wid] = s;
    __syncthreads();
    if (t < 32) {
        float s2 = (t < 8) ? red[t] : 0.f;
#pragma unroll
        for (int o = 4; o; o >>= 1) s2 += __shfl_xor_sync(0xffffffffu, s2, o);
        if (t == 0) bc = s2 * (1.f / 1024.f);
    }
    __syncthreads();
    float mean = bc;

    float q = 0.f;
#pragma unroll
    for (int i = 0; i < 4; i++) { float d = v[i] - mean; q += d * d; }
#pragma unroll
    for (int o = 16; o; o >>= 1) q += __shfl_xor_sync(0xffffffffu, q, o);
    __syncthreads();
    if (lane == 0) red[wid] = q;
    __syncthreads();
    if (t < 32) {
        float q2 = (t < 8) ? red[t] : 0.f;
#pragma unroll
        for (int o = 4; o; o >>= 1) q2 += __shfl_xor_sync(0xffffffffu, q2, o);
        if (t == 0) bc = rsqrtf(q2 * (1.f / 1024.f) + 1e-5f);
    }
    __syncthreads();
    float rstd = bc;
#pragma unroll
    for (int i = 0; i < 4; i++) {
        int c = t + i * 256;
        out[row * 1024 + c] = (v[i] - mean) * rstd * w[c] + bvec[c];
    }
}

// ======================= host launcher ======================================
extern "C" void kernel_launch(void* const* d_in, const int* in_sizes, int n_in,
                              void* d_out, int out_size)
{
    const float* x    = (const float*)d_in[0];
    const int*   mask = (const int*)  d_in[1];
    const float* WQ1  = (const float*)d_in[2];
    const float* bQ1  = (const float*)d_in[3];
    const float* WK1  = (const float*)d_in[4];
    const float* bK1  = (const float*)d_in[5];
    const float* WV   = (const float*)d_in[6];
    const float* bV   = (const float*)d_in[7];
    const float* lnhw = (const float*)d_in[8];
    const float* lnhb = (const float*)d_in[9];
    const float* WO   = (const float*)d_in[10];
    const float* bO   = (const float*)d_in[11];
    const float* ln1w = (const float*)d_in[12];
    const float* ln1b = (const float*)d_in[13];
    const float* ln2w = (const float*)d_in[14];
    const float* ln2b = (const float*)d_in[15];
    const float* W1   = (const float*)d_in[16];
    const float* b1   = (const float*)d_in[17];
    const float* W2   = (const float*)d_in[18];
    const float* b2   = (const float*)d_in[19];
    const float* lq1  = (const float*)d_in[20];
    const float* lk1  = (const float*)d_in[21];
    const float* lq2  = (const float*)d_in[22];
    const float* lk2  = (const float*)d_in[23];

    float* out = (float*)d_out;

    cudaFuncSetAttribute(gemm_mma, cudaFuncAttributeMaxDynamicSharedMemorySize, GEMM_SMEM_BYTES);

    float *qkv, *sp, *op, *ocat, *h1pre, *h1, *r2pre, *biasqkv;
    __nv_bfloat16 *qkvh, *qkvl, *bqh, *bql, *woth, *wotl, *w1th, *w1tl, *w2th, *w2tl;
    __nv_bfloat16 *xh, *xl, *ah, *al, *vth, *vtl, *och, *ocl, *h1h, *h1l, *ffhh, *ffhl;
    cudaGetSymbolAddress((void**)&qkv,   g_QKV);
    cudaGetSymbolAddress((void**)&qkvh,  g_QKVh);
    cudaGetSymbolAddress((void**)&qkvl,  g_QKVl);
    cudaGetSymbolAddress((void**)&bqh,   g_Bqh);
    cudaGetSymbolAddress((void**)&bql,   g_Bql);
    cudaGetSymbolAddress((void**)&woth,  g_WOth);
    cudaGetSymbolAddress((void**)&wotl,  g_WOtl);
    cudaGetSymbolAddress((void**)&w1th,  g_W1th);
    cudaGetSymbolAddress((void**)&w1tl,  g_W1tl);
    cudaGetSymbolAddress((void**)&w2th,  g_W2th);
    cudaGetSymbolAddress((void**)&w2tl,  g_W2tl);
    cudaGetSymbolAddress((void**)&biasqkv, g_biasqkv);
    cudaGetSymbolAddress((void**)&xh,    g_xh);
    cudaGetSymbolAddress((void**)&xl,    g_xl);
    cudaGetSymbolAddress((void**)&sp,    g_S);
    cudaGetSymbolAddress((void**)&ah,    g_Ah);
    cudaGetSymbolAddress((void**)&al,    g_Al);
    cudaGetSymbolAddress((void**)&vth,   g_Vth);
    cudaGetSymbolAddress((void**)&vtl,   g_Vtl);
    cudaGetSymbolAddress((void**)&op,    g_O);
    cudaGetSymbolAddress((void**)&ocat,  g_Ocat);
    cudaGetSymbolAddress((void**)&och,   g_Och);
    cudaGetSymbolAddress((void**)&ocl,   g_Ocl);
    cudaGetSymbolAddress((void**)&h1pre, g_h1pre);
    cudaGetSymbolAddress((void**)&h1,    g_h1);
    cudaGetSymbolAddress((void**)&h1h,   g_h1h);
    cudaGetSymbolAddress((void**)&h1l,   g_h1l);
    cudaGetSymbolAddress((void**)&ffhh,  g_ffhh);
    cudaGetSymbolAddress((void**)&ffhl,  g_ffhl);
    cudaGetSymbolAddress((void**)&r2pre, g_r2pre);

    float* A_ptr = (out_size >= FULL_ELEMS) ? (out + R2_ELEMS) : sp;

    lam_kernel<<<1, 64>>>(lq1, lk1, lq2, lk2);
    concat_bias<<<16, 256>>>(bQ1, bK1, bV, biasqkv);

    // weight transpose-converts (K-major bf16 hi/lo)
    convW<<<dim3(32, 32),  dim3(32, 8)>>>(WQ1, bqh,               bql,               1024, 64);
    convW<<<dim3(32, 32),  dim3(32, 8)>>>(WK1, bqh + 1024 * 1024, bql + 1024 * 1024, 1024, 64);
    convW<<<dim3(32, 64),  dim3(32, 8)>>>(WV,  bqh + 2048 * 1024, bql + 2048 * 1024, 1024, 128);
    convW<<<dim3(64, 32),  dim3(32, 8)>>>(WO,  woth, wotl, 2048, 1024);
    convW<<<dim3(32, 128), dim3(32, 8)>>>(W1,  w1th, w1tl, 1024, 4096);
    convW<<<dim3(128, 32), dim3(32, 8)>>>(W2,  w2th, w2tl, 4096, 1024);
    conv_hilo<<<4096, 256>>>(x, xh, xl, 1048576);

    // fused QKV projection: [4096, 4096] = x @ Wqkv^T, K=1024
    gemm_mma<<<dim3(32, 32, 1), 256, GEMM_SMEM_BYTES>>>(
        xh, xl, bqh, bql, biasqkv, nullptr, qkv, qkvh, qkvl,
        1024, 1024, 1024, 4096, 1.0f, 0, 0);

    // scores, batched z=h*4+b, alpha = 1/sqrt(1024)
    gemm_mma<<<dim3(8, 8, 64), 256, GEMM_SMEM_BYTES>>>(
        qkvh, qkvl, qkvh + 1024, qkvl + 1024, nullptr, nullptr, sp, nullptr, nullptr,
        64, 4096, 4096, 1024, 0.03125f, 0, 1);

    softmax_row<<<65536, 256>>>(sp, mask, A_ptr, ah, al);
    convVt<<<dim3(32, 4, 64), dim3(32, 8)>>>(qkv, vth, vtl);

    // AV, batched
    gemm_mma<<<dim3(1, 8, 64), 256, GEMM_SMEM_BYTES>>>(
        ah, al, vth, vtl, nullptr, nullptr, op, nullptr, nullptr,
        1024, 1024, 1024, 128, 1.0f, 0, 2);

    headln_kernel<<<8192, 256>>>(op, lnhw, lnhb, ocat);
    conv_hilo<<<8192, 256>>>(ocat, och, ocl, 2097152);

    // output projection + residual(x), LN1
    gemm_mma<<<dim3(8, 32, 1), 256, GEMM_SMEM_BYTES>>>(
        och, ocl, woth, wotl, bO, x, h1pre, nullptr, nullptr,
        2048, 2048, 2048, 1024, 1.0f, 0, 0);
    ln1024<<<4096, 256>>>(h1pre, ln1w, ln1b, h1);
    conv_hilo<<<4096, 256>>>(h1, h1h, h1l, 1048576);

    // FFN: relu(h1 @ W1 + b1) @ W2 + b2 + h1, LN2 -> out
    gemm_mma<<<dim3(32, 32, 1), 256, GEMM_SMEM_BYTES>>>(
        h1h, h1l, w1th, w1tl, b1, nullptr, nullptr, ffhh, ffhl,
        1024, 1024, 1024, 4096, 1.0f, 1, 0);
    gemm_mma<<<dim3(8, 32, 1), 256, GEMM_SMEM_BYTES>>>(
        ffhh, ffhl, w2th, w2tl, b2, h1, r2pre, nullptr, nullptr,
        4096, 4096, 4096, 1024, 1.0f, 0, 0);
    ln1024<<<4096, 256>>>(r2pre, ln2w, ln2b, out);
}

// round 8
// speedup vs baseline: 3.6378x; 1.0569x over previous
#include <cuda_runtime.h>
#include <cuda_bf16.h>
#include <math.h>
#include <stddef.h>
#include <stdint.h>

#define B_SZ   4
#define S_SZ   1024
#define D_M    1024
#define H_N    16
#define D_INT  64
#define D_V    128
#define HID    4096
#define NTOK   4096
#define HB     64
#define LAMBDA_INIT 0.3555090675909693f
#define HEADLN_SCALE 0.6444909324090307f
#define R2_ELEMS 4194304
#define FULL_ELEMS 71303168

// ======================= helpers =======================
__device__ __forceinline__ uint32_t smem_u32(const void* p) {
    uint32_t a;
    asm("{ .reg .u64 t; cvta.to.shared.u64 t, %1; cvt.u32.u64 %0, t; }" : "=r"(a) : "l"(p));
    return a;
}
#define CP_ASYNC16(sdst, gsrc) \
    asm volatile("cp.async.cg.shared.global [%0], [%1], 16;" :: "r"(sdst), "l"(gsrc) : "memory")
#define CP_COMMIT() asm volatile("cp.async.commit_group;" ::: "memory")
#define CP_WAIT0()  asm volatile("cp.async.wait_group 0;" ::: "memory")
#define CP_WAIT1()  asm volatile("cp.async.wait_group 1;" ::: "memory")

__device__ __forceinline__ void mma16816(float* d, uint32_t a0, uint32_t a1, uint32_t a2,
                                         uint32_t a3, uint32_t b0, uint32_t b1) {
    asm volatile(
        "mma.sync.aligned.m16n8k16.row.col.f32.bf16.bf16.f32 "
        "{%0,%1,%2,%3}, {%4,%5,%6,%7}, {%8,%9}, {%0,%1,%2,%3};"
        : "+f"(d[0]), "+f"(d[1]), "+f"(d[2]), "+f"(d[3])
        : "r"(a0), "r"(a1), "r"(a2), "r"(a3), "r"(b0), "r"(b1));
}
__device__ __forceinline__ void ldmx4(uint32_t* r, uint32_t addr) {
    asm volatile("ldmatrix.sync.aligned.m8n8.x4.shared.b16 {%0,%1,%2,%3}, [%4];"
        : "=r"(r[0]), "=r"(r[1]), "=r"(r[2]), "=r"(r[3]) : "r"(addr));
}
__device__ __forceinline__ void ldmx2(uint32_t* r, uint32_t addr) {
    asm volatile("ldmatrix.sync.aligned.m8n8.x2.shared.b16 {%0,%1}, [%2];"
        : "=r"(r[0]), "=r"(r[1]) : "r"(addr));
}

// ======================= static scratch =======================
__device__ __align__(16) __nv_bfloat16  g_QKVh [(size_t)NTOK * 4096];
__device__ __align__(16) __nv_bfloat16  g_QKVl [(size_t)NTOK * 4096];
__device__ __align__(16) __nv_bfloat16  g_Bqh  [(size_t)4096 * 1024];
__device__ __align__(16) __nv_bfloat16  g_Bql  [(size_t)4096 * 1024];
__device__ __align__(16) __nv_bfloat16  g_WOth [(size_t)1024 * 2048];
__device__ __align__(16) __nv_bfloat16  g_WOtl [(size_t)1024 * 2048];
__device__ __align__(16) __nv_bfloat16  g_W1th [(size_t)4096 * 1024];
__device__ __align__(16) __nv_bfloat16  g_W1tl [(size_t)4096 * 1024];
__device__ __align__(16) __nv_bfloat16  g_W2th [(size_t)1024 * 4096];
__device__ __align__(16) __nv_bfloat16  g_W2tl [(size_t)1024 * 4096];
__device__ __align__(16) float          g_biasqkv[4096];
__device__ __align__(16) __nv_bfloat16  g_xh   [(size_t)NTOK * 1024];
__device__ __align__(16) __nv_bfloat16  g_xl   [(size_t)NTOK * 1024];
__device__ __align__(16) float          g_S    [(size_t)HB * S_SZ * S_SZ];
__device__ __align__(16) __nv_bfloat16  g_Ah   [(size_t)HB * S_SZ * S_SZ];
__device__ __align__(16) __nv_bfloat16  g_Al   [(size_t)HB * S_SZ * S_SZ];
__device__ __align__(16) __nv_bfloat16  g_Vth  [(size_t)HB * 128 * 1024];
__device__ __align__(16) __nv_bfloat16  g_Vtl  [(size_t)HB * 128 * 1024];
__device__ __align__(16) float          g_O    [(size_t)HB * S_SZ * D_V];
__device__ __align__(16) __nv_bfloat16  g_Och  [(size_t)NTOK * 2048];
__device__ __align__(16) __nv_bfloat16  g_Ocl  [(size_t)NTOK * 2048];
__device__ __align__(16) float          g_h1pre[(size_t)NTOK * D_M];
__device__ __align__(16) float          g_h1   [(size_t)NTOK * D_M];
__device__ __align__(16) __nv_bfloat16  g_h1h  [(size_t)NTOK * D_M];
__device__ __align__(16) __nv_bfloat16  g_h1l  [(size_t)NTOK * D_M];
__device__ __align__(16) __nv_bfloat16  g_ffhh [(size_t)NTOK * HID];
__device__ __align__(16) __nv_bfloat16  g_ffhl [(size_t)NTOK * HID];
__device__ __align__(16) float          g_r2pre[(size_t)NTOK * D_M];
__device__ float g_lamscale;

// ======================= lambda =======================
__global__ void lam_kernel(const float* __restrict__ lq1, const float* __restrict__ lk1,
                           const float* __restrict__ lq2, const float* __restrict__ lk2)
{
    __shared__ float s1[64], s2[64];
    int t = threadIdx.x;
    s1[t] = lq1[t] * lk1[t];
    s2[t] = lq2[t] * lk2[t];
    __syncthreads();
    if (t == 0) {
        float d1 = 0.f, d2 = 0.f;
        for (int i = 0; i < 64; i++) { d1 += s1[i]; d2 += s2[i]; }
        g_lamscale = 1.0f - (expf(d1) - expf(d2) + LAMBDA_INIT);
    }
}

// ======================= conversions =======================
__global__ void __launch_bounds__(256) conv_hilo(
    const float* __restrict__ in, __nv_bfloat16* __restrict__ oh,
    __nv_bfloat16* __restrict__ ol, int n4)
{
    int i = blockIdx.x * 256 + threadIdx.x;
    if (i >= n4) return;
    float4 v = reinterpret_cast<const float4*>(in)[i];
    __nv_bfloat16 h0 = __float2bfloat16(v.x), h1 = __float2bfloat16(v.y);
    __nv_bfloat16 h2 = __float2bfloat16(v.z), h3 = __float2bfloat16(v.w);
    __nv_bfloat162 p0, p1, q0, q1;
    p0.x = h0; p0.y = h1; p1.x = h2; p1.y = h3;
    q0.x = __float2bfloat16(v.x - __bfloat162float(h0));
    q0.y = __float2bfloat16(v.y - __bfloat162float(h1));
    q1.x = __float2bfloat16(v.z - __bfloat162float(h2));
    q1.y = __float2bfloat16(v.w - __bfloat162float(h3));
    reinterpret_cast<__nv_bfloat162*>(oh)[i * 2]     = p0;
    reinterpret_cast<__nv_bfloat162*>(oh)[i * 2 + 1] = p1;
    reinterpret_cast<__nv_bfloat162*>(ol)[i * 2]     = q0;
    reinterpret_cast<__nv_bfloat162*>(ol)[i * 2 + 1] = q1;
}

// weight transpose-convert: out[n][k] (K-major) from in[(n/dout)*K*dout + k*dout + n%dout]
__global__ void convW(const float* __restrict__ in, __nv_bfloat16* __restrict__ oh,
                      __nv_bfloat16* __restrict__ ol, int K, int dout)
{
    __shared__ float t[32][33];
    int k0 = blockIdx.x * 32, n0 = blockIdx.y * 32;
    int h = n0 / dout, d0 = n0 - h * dout;
    const float* src = in + (size_t)h * K * dout + d0;
    for (int r = threadIdx.y; r < 32; r += 8)
        t[r][threadIdx.x] = src[(size_t)(k0 + r) * dout + threadIdx.x];
    __syncthreads();
    for (int r = threadIdx.y; r < 32; r += 8) {
        float v = t[threadIdx.x][r];
        __nv_bfloat16 hi = __float2bfloat16(v);
        size_t idx = (size_t)(n0 + r) * K + k0 + threadIdx.x;
        oh[idx] = hi;
        ol[idx] = __float2bfloat16(v - __bfloat162float(hi));
    }
}

// V transpose (bf16, hi and lo): Vt[z][v][t] from QKVx[(b*1024+t)*4096 + 2048 + h*128 + v]
__global__ void convVt_bf16(const __nv_bfloat16* __restrict__ sh, const __nv_bfloat16* __restrict__ sl,
                            __nv_bfloat16* __restrict__ oh, __nv_bfloat16* __restrict__ ol)
{
    __shared__ __nv_bfloat16 th[32][33];
    __shared__ __nv_bfloat16 tl[32][33];
    int z = blockIdx.z, h = z >> 2, b = z & 3;
    int t0 = blockIdx.x * 32, v0 = blockIdx.y * 32;
    for (int r = threadIdx.y; r < 32; r += 8) {
        size_t si = (size_t)(b * 1024 + t0 + r) * 4096 + 2048 + h * 128 + v0 + threadIdx.x;
        th[r][threadIdx.x] = sh[si];
        tl[r][threadIdx.x] = sl[si];
    }
    __syncthreads();
    size_t base = (size_t)z * 131072;
    for (int r = threadIdx.y; r < 32; r += 8) {
        size_t di = base + (size_t)(v0 + r) * 1024 + t0 + threadIdx.x;
        oh[di] = th[threadIdx.x][r];
        ol[di] = tl[threadIdx.x][r];
    }
}

__global__ void concat_bias(const float* __restrict__ bq, const float* __restrict__ bk,
                            const float* __restrict__ bv, float* __restrict__ o)
{
    int t = blockIdx.x * 256 + threadIdx.x;
    if (t < 1024) o[t] = bq[t];
    else if (t < 2048) o[t] = bk[t - 1024];
    else if (t < 4096) o[t] = bv[t - 2048];
}

// ======================= tensor-core GEMM (mma.sync bf16, 3-term split) ======
// C[128x128 tile] = sum_k A[m][k]*B[n][k], both K-major bf16 hi/lo.
// modes: 0 plain; 1 scores batched (z=h*4+b); 2 AV batched.
// smem per stage: Ah/Al/Bh/Bl, each 128 rows x 80 bytes (64B data + 16B pad).
#define STG_BYTES 40960
#define GEMM_SMEM_BYTES (2 * STG_BYTES)

__global__ void __launch_bounds__(256, 2) gemm_mma(
    const __nv_bfloat16* __restrict__ Ah, const __nv_bfloat16* __restrict__ Al,
    const __nv_bfloat16* __restrict__ Bh, const __nv_bfloat16* __restrict__ Bl,
    const float* __restrict__ bias, const float* __restrict__ res,
    float* __restrict__ cout, __nv_bfloat16* __restrict__ outh, __nv_bfloat16* __restrict__ outl,
    int K, int lda, int ldb, int ldc, float alpha, int relu, int mode)
{
    extern __shared__ char dsm[];
    const int tid = threadIdx.x;
    const int lane = tid & 31, wid = tid >> 5;
    const int wy = wid >> 2, wx = wid & 3;       // warp tile: 64(M) x 32(N)
    const int m0 = blockIdx.y * 128, n0 = blockIdx.x * 128;
    const uint32_t smbase = smem_u32(dsm);

    size_t aoff = 0, boff = 0, coff = 0;
    if (mode == 1) {
        int z = blockIdx.z, h = z >> 2, b = z & 3;
        aoff = (size_t)(b << 10) * lda + (h << 6);
        boff = (size_t)(b << 10) * ldb + (h << 6);
        coff = (size_t)z << 20;
    } else if (mode == 2) {
        int z = blockIdx.z;
        aoff = (size_t)z << 20;
        boff = (size_t)z << 17;
        coff = (size_t)z << 17;
    }

    float acc[4][4][4];
#pragma unroll
    for (int i = 0; i < 4; i++)
#pragma unroll
        for (int j = 0; j < 4; j++)
#pragma unroll
            for (int q = 0; q < 4; q++) acc[i][j][q] = 0.f;

    const int niter = K >> 5;

    auto issue_tile = [&](int it, int stage) {
        int k0 = it << 5;
        uint32_t sb = smbase + stage * STG_BYTES;
#pragma unroll
        for (int i = 0; i < 2; i++) {
            int l = tid + (i << 8);
            int row = l >> 2, c16 = l & 3;
            size_t aidx = aoff + (size_t)(m0 + row) * lda + k0 + (c16 << 3);
            size_t bidx = boff + (size_t)(n0 + row) * ldb + k0 + (c16 << 3);
            uint32_t so = (uint32_t)(row * 80 + (c16 << 4));
            CP_ASYNC16(sb + so,         Ah + aidx);
            CP_ASYNC16(sb + 10240 + so, Al + aidx);
            CP_ASYNC16(sb + 20480 + so, Bh + bidx);
            CP_ASYNC16(sb + 30720 + so, Bl + bidx);
        }
        CP_COMMIT();
    };

    issue_tile(0, 0);

    // ldmatrix per-lane addressing
    // A (x4): mats (m0-7,k0-7),(m8-15,k0-7),(m0-7,k8-15),(m8-15,k8-15)
    const int a_row = (wy << 6) + (lane & 7) + ((lane >> 3) & 1) * 8;  // + mt*16
    const int a_kb  = (lane >> 4) << 4;                                // + ks*32
    // B (x2): mats (n0-7,k0-7),(n0-7,k8-15); lanes 0-15 supply addresses
    const int l15 = lane & 15;
    const int b_row = (wx << 5) + (l15 & 7);                           // + nt*8
    const int b_kb  = (l15 >> 3) << 4;                                 // + ks*32

    for (int it = 0; it < niter; it++) {
        int st = it & 1;
        if (it + 1 < niter) { issue_tile(it + 1, st ^ 1); CP_WAIT1(); }
        else { CP_WAIT0(); }
        __syncthreads();

        uint32_t base = smbase + st * STG_BYTES;
        uint32_t pAh = base;
        uint32_t pAl = base + 10240;
        uint32_t pBh = base + 20480;
        uint32_t pBl = base + 30720;

#pragma unroll
        for (int ks = 0; ks < 2; ks++) {
            const int ksb = ks << 5;
            uint32_t bhf[4][2], blf[4][2];
#pragma unroll
            for (int nt = 0; nt < 4; nt++) {
                uint32_t bo = (uint32_t)((b_row + (nt << 3)) * 80 + ksb + b_kb);
                ldmx2(bhf[nt], pBh + bo);
                ldmx2(blf[nt], pBl + bo);
            }
#pragma unroll
            for (int mt = 0; mt < 4; mt++) {
                uint32_t ao = (uint32_t)((a_row + (mt << 4)) * 80 + ksb + a_kb);
                uint32_t ahf[4], alf[4];
                ldmx4(ahf, pAh + ao);
                ldmx4(alf, pAl + ao);
#pragma unroll
                for (int nt = 0; nt < 4; nt++) {
                    mma16816(acc[mt][nt], ahf[0], ahf[1], ahf[2], ahf[3], bhf[nt][0], bhf[nt][1]);
                    mma16816(acc[mt][nt], ahf[0], ahf[1], ahf[2], ahf[3], blf[nt][0], blf[nt][1]);
                    mma16816(acc[mt][nt], alf[0], alf[1], alf[2], alf[3], bhf[nt][0], bhf[nt][1]);
                }
            }
        }
        __syncthreads();
    }

    // epilogue: alpha, bias, residual, relu; fp32 and/or bf16 hi/lo outputs
#pragma unroll
    for (int mt = 0; mt < 4; mt++) {
#pragma unroll
        for (int nt = 0; nt < 4; nt++) {
#pragma unroll
            for (int hf = 0; hf < 2; hf++) {
                int row = m0 + (wy << 6) + (mt << 4) + (lane >> 2) + (hf << 3);
                int col = n0 + (wx << 5) + (nt << 3) + ((lane & 3) << 1);
                float v0 = acc[mt][nt][hf * 2]     * alpha;
                float v1 = acc[mt][nt][hf * 2 + 1] * alpha;
                if (bias) { v0 += bias[col]; v1 += bias[col + 1]; }
                if (res) {
                    float2 rv = *reinterpret_cast<const float2*>(res + (size_t)row * ldc + col);
                    v0 += rv.x; v1 += rv.y;
                }
                if (relu) { v0 = fmaxf(v0, 0.f); v1 = fmaxf(v1, 0.f); }
                size_t oidx = coff + (size_t)row * ldc + col;
                if (cout) *reinterpret_cast<float2*>(cout + oidx) = make_float2(v0, v1);
                if (outh) {
                    __nv_bfloat16 h0 = __float2bfloat16(v0), h1 = __float2bfloat16(v1);
                    __nv_bfloat162 ph, pl;
                    ph.x = h0; ph.y = h1;
                    pl.x = __float2bfloat16(v0 - __bfloat162float(h0));
                    pl.y = __float2bfloat16(v1 - __bfloat162float(h1));
                    *reinterpret_cast<__nv_bfloat162*>(outh + oidx) = ph;
                    *reinterpret_cast<__nv_bfloat162*>(outl + oidx) = pl;
                }
            }
        }
    }
}

// ======================= softmax (emits fp32 + bf16 hi/lo) ==================
__global__ void __launch_bounds__(256) softmax_row(
    const float* __restrict__ Sc, const int* __restrict__ mask, float* __restrict__ Aout,
    __nv_bfloat16* __restrict__ Ahi, __nv_bfloat16* __restrict__ Alo)
{
    __shared__ float red[8];
    __shared__ float bcast;
    size_t row = blockIdx.x;
    int b = (int)((row >> 10) & 3);
    const float* in = Sc + row * 1024;
    const int* mrow = mask + b * 1024;
    int t = threadIdx.x;
    int wid = t >> 5, lane = t & 31;

    float v[4];
    float mx = -INFINITY;
#pragma unroll
    for (int i = 0; i < 4; i++) {
        int c = t + i * 256;
        float val = in[c];
        if (mrow[c] == 0) val = -INFINITY;
        v[i] = val;
        mx = fmaxf(mx, val);
    }
#pragma unroll
    for (int o = 16; o; o >>= 1) mx = fmaxf(mx, __shfl_xor_sync(0xffffffffu, mx, o));
    if (lane == 0) red[wid] = mx;
    __syncthreads();
    if (t < 32) {
        float m2 = (t < 8) ? red[t] : -INFINITY;
#pragma unroll
        for (int o = 4; o; o >>= 1) m2 = fmaxf(m2, __shfl_xor_sync(0xffffffffu, m2, o));
        if (t == 0) bcast = m2;
    }
    __syncthreads();
    mx = bcast;

    float sum = 0.f;
#pragma unroll
    for (int i = 0; i < 4; i++) { v[i] = expf(v[i] - mx); sum += v[i]; }
#pragma unroll
    for (int o = 16; o; o >>= 1) sum += __shfl_xor_sync(0xffffffffu, sum, o);
    __syncthreads();
    if (lane == 0) red[wid] = sum;
    __syncthreads();
    if (t < 32) {
        float s2 = (t < 8) ? red[t] : 0.f;
#pragma unroll
        for (int o = 4; o; o >>= 1) s2 += __shfl_xor_sync(0xffffffffu, s2, o);
        if (t == 0) bcast = g_lamscale / s2;
    }
    __syncthreads();
    float sc = bcast;
#pragma unroll
    for (int i = 0; i < 4; i++) {
        size_t idx = row * 1024 + t + i * 256;
        float vv = v[i] * sc;
        Aout[idx] = vv;
        __nv_bfloat16 hi = __float2bfloat16(vv);
        Ahi[idx] = hi;
        Alo[idx] = __float2bfloat16(vv - __bfloat162float(hi));
    }
}

// ======================= per-head LN(128) + concat, emits bf16 hi/lo ========
__global__ void __launch_bounds__(256) headln_kernel(
    const float* __restrict__ O, const float* __restrict__ w,
    const float* __restrict__ bvec, __nv_bfloat16* __restrict__ och,
    __nv_bfloat16* __restrict__ ocl)
{
    int gw = blockIdx.x * 8 + (threadIdx.x >> 5);
    int lane = threadIdx.x & 31;
    const float* xr = O + (size_t)gw * 128;
    float x0 = xr[lane], x1 = xr[lane + 32], x2 = xr[lane + 64], x3 = xr[lane + 96];
    float s = x0 + x1 + x2 + x3;
#pragma unroll
    for (int o = 16; o; o >>= 1) s += __shfl_xor_sync(0xffffffffu, s, o);
    float mean = s * (1.f / 128.f);
    float d0 = x0 - mean, d1 = x1 - mean, d2 = x2 - mean, d3 = x3 - mean;
    float q = d0 * d0 + d1 * d1 + d2 * d2 + d3 * d3;
#pragma unroll
    for (int o = 16; o; o >>= 1) q += __shfl_xor_sync(0xffffffffu, q, o);
    float rstd = rsqrtf(q * (1.f / 128.f) + 1e-5f);

    int z = gw >> 10, s_ = gw & 1023;
    int h = z >> 2, b = z & 3;
    size_t base = ((size_t)(b * S_SZ + s_)) * 2048 + h * 128;
    float vals[4] = {
        (d0 * rstd * w[lane]      + bvec[lane])      * HEADLN_SCALE,
        (d1 * rstd * w[lane + 32] + bvec[lane + 32]) * HEADLN_SCALE,
        (d2 * rstd * w[lane + 64] + bvec[lane + 64]) * HEADLN_SCALE,
        (d3 * rstd * w[lane + 96] + bvec[lane + 96]) * HEADLN_SCALE };
#pragma unroll
    for (int i = 0; i < 4; i++) {
        __nv_bfloat16 hi = __float2bfloat16(vals[i]);
        och[base + lane + i * 32] = hi;
        ocl[base + lane + i * 32] = __float2bfloat16(vals[i] - __bfloat162float(hi));
    }
}

// ======================= LayerNorm 1024 (optional bf16 hi/lo out) ===========
__global__ void __launch_bounds__(256) ln1024(
    const float* __restrict__ X, const float* __restrict__ w,
    const float* __restrict__ bvec, float* __restrict__ out,
    __nv_bfloat16* __restrict__ outh, __nv_bfloat16* __restrict__ outl)
{
    __shared__ float red[8];
    __shared__ float bc;
    size_t row = blockIdx.x;
    const float* xr = X + row * 1024;
    int t = threadIdx.x;
    int wid = t >> 5, lane = t & 31;

    float v[4];
    float s = 0.f;
#pragma unroll
    for (int i = 0; i < 4; i++) { v[i] = xr[t + i * 256]; s += v[i]; }
#pragma unroll
    for (int o = 16; o; o >>= 1) s += __shfl_xor_sync(0xffffffffu, s, o);
    if (lane == 0) red[wid] = s;
    __syncthreads();
    if (t < 32) {
        float s2 = (t < 8) ? red[t] : 0.f;
#pragma unroll
        for (int o = 4; o; o >>= 1) s2 += __shfl_xor_sync(0xffffffffu, s2, o);
        if (t == 0) bc = s2 * (1.f / 1024.f);
    }
    __syncthreads();
    float mean = bc;

    float q = 0.f;
#pragma unroll
    for (int i = 0; i < 4; i++) { float d = v[i] - mean; q += d * d; }
#pragma unroll
    for (int o = 16; o; o >>= 1) q += __shfl_xor_sync(0xffffffffu, q, o);
    __syncthreads();
    if (lane == 0) red[wid] = q;
    __syncthreads();
    if (t < 32) {
        float q2 = (t < 8) ? red[t] : 0.f;
#pragma unroll
        for (int o = 4; o; o >>= 1) q2 += __shfl_xor_sync(0xffffffffu, q2, o);
        if (t == 0) bc = rsqrtf(q2 * (1.f / 1024.f) + 1e-5f);
    }
    __syncthreads();
    float rstd = bc;
#pragma unroll
    for (int i = 0; i < 4; i++) {
        int c = t + i * 256;
        float vv = (v[i] - mean) * rstd * w[c] + bvec[c];
        out[row * 1024 + c] = vv;
        if (outh) {
            __nv_bfloat16 hi = __float2bfloat16(vv);
            outh[row * 1024 + c] = hi;
            outl[row * 1024 + c] = __float2bfloat16(vv - __bfloat162float(hi));
        }
    }
}

// ======================= host launcher ======================================
extern "C" void kernel_launch(void* const* d_in, const int* in_sizes, int n_in,
                              void* d_out, int out_size)
{
    const float* x    = (const float*)d_in[0];
    const int*   mask = (const int*)  d_in[1];
    const float* WQ1  = (const float*)d_in[2];
    const float* bQ1  = (const float*)d_in[3];
    const float* WK1  = (const float*)d_in[4];
    const float* bK1  = (const float*)d_in[5];
    const float* WV   = (const float*)d_in[6];
    const float* bV   = (const float*)d_in[7];
    const float* lnhw = (const float*)d_in[8];
    const float* lnhb = (const float*)d_in[9];
    const float* WO   = (const float*)d_in[10];
    const float* bO   = (const float*)d_in[11];
    const float* ln1w = (const float*)d_in[12];
    const float* ln1b = (const float*)d_in[13];
    const float* ln2w = (const float*)d_in[14];
    const float* ln2b = (const float*)d_in[15];
    const float* W1   = (const float*)d_in[16];
    const float* b1   = (const float*)d_in[17];
    const float* W2   = (const float*)d_in[18];
    const float* b2   = (const float*)d_in[19];
    const float* lq1  = (const float*)d_in[20];
    const float* lk1  = (const float*)d_in[21];
    const float* lq2  = (const float*)d_in[22];
    const float* lk2  = (const float*)d_in[23];

    float* out = (float*)d_out;

    cudaFuncSetAttribute(gemm_mma, cudaFuncAttributeMaxDynamicSharedMemorySize, GEMM_SMEM_BYTES);

    float *sp, *op, *h1pre, *h1, *r2pre, *biasqkv;
    __nv_bfloat16 *qkvh, *qkvl, *bqh, *bql, *woth, *wotl, *w1th, *w1tl, *w2th, *w2tl;
    __nv_bfloat16 *xh, *xl, *ah, *al, *vth, *vtl, *och, *ocl, *h1h, *h1l, *ffhh, *ffhl;
    cudaGetSymbolAddress((void**)&qkvh,  g_QKVh);
    cudaGetSymbolAddress((void**)&qkvl,  g_QKVl);
    cudaGetSymbolAddress((void**)&bqh,   g_Bqh);
    cudaGetSymbolAddress((void**)&bql,   g_Bql);
    cudaGetSymbolAddress((void**)&woth,  g_WOth);
    cudaGetSymbolAddress((void**)&wotl,  g_WOtl);
    cudaGetSymbolAddress((void**)&w1th,  g_W1th);
    cudaGetSymbolAddress((void**)&w1tl,  g_W1tl);
    cudaGetSymbolAddress((void**)&w2th,  g_W2th);
    cudaGetSymbolAddress((void**)&w2tl,  g_W2tl);
    cudaGetSymbolAddress((void**)&biasqkv, g_biasqkv);
    cudaGetSymbolAddress((void**)&xh,    g_xh);
    cudaGetSymbolAddress((void**)&xl,    g_xl);
    cudaGetSymbolAddress((void**)&sp,    g_S);
    cudaGetSymbolAddress((void**)&ah,    g_Ah);
    cudaGetSymbolAddress((void**)&al,    g_Al);
    cudaGetSymbolAddress((void**)&vth,   g_Vth);
    cudaGetSymbolAddress((void**)&vtl,   g_Vtl);
    cudaGetSymbolAddress((void**)&op,    g_O);
    cudaGetSymbolAddress((void**)&och,   g_Och);
    cudaGetSymbolAddress((void**)&ocl,   g_Ocl);
    cudaGetSymbolAddress((void**)&h1pre, g_h1pre);
    cudaGetSymbolAddress((void**)&h1,    g_h1);
    cudaGetSymbolAddress((void**)&h1h,   g_h1h);
    cudaGetSymbolAddress((void**)&h1l,   g_h1l);
    cudaGetSymbolAddress((void**)&ffhh,  g_ffhh);
    cudaGetSymbolAddress((void**)&ffhl,  g_ffhl);
    cudaGetSymbolAddress((void**)&r2pre, g_r2pre);

    float* A_ptr = (out_size >= FULL_ELEMS) ? (out + R2_ELEMS) : sp;

    lam_kernel<<<1, 64>>>(lq1, lk1, lq2, lk2);
    concat_bias<<<16, 256>>>(bQ1, bK1, bV, biasqkv);

    // weight transpose-converts (K-major bf16 hi/lo)
    convW<<<dim3(32, 32),  dim3(32, 8)>>>(WQ1, bqh,               bql,               1024, 64);
    convW<<<dim3(32, 32),  dim3(32, 8)>>>(WK1, bqh + 1024 * 1024, bql + 1024 * 1024, 1024, 64);
    convW<<<dim3(32, 64),  dim3(32, 8)>>>(WV,  bqh + 2048 * 1024, bql + 2048 * 1024, 1024, 128);
    convW<<<dim3(64, 32),  dim3(32, 8)>>>(WO,  woth, wotl, 2048, 1024);
    convW<<<dim3(32, 128), dim3(32, 8)>>>(W1,  w1th, w1tl, 1024, 4096);
    convW<<<dim3(128, 32), dim3(32, 8)>>>(W2,  w2th, w2tl, 4096, 1024);
    conv_hilo<<<4096, 256>>>(x, xh, xl, 1048576);

    // fused QKV projection: [4096, 4096] = x @ Wqkv^T, K=1024 (bf16 hi/lo out only)
    gemm_mma<<<dim3(32, 32, 1), 256, GEMM_SMEM_BYTES>>>(
        xh, xl, bqh, bql, biasqkv, nullptr, nullptr, qkvh, qkvl,
        1024, 1024, 1024, 4096, 1.0f, 0, 0);

    // scores, batched z=h*4+b, alpha = 1/sqrt(1024)
    gemm_mma<<<dim3(8, 8, 64), 256, GEMM_SMEM_BYTES>>>(
        qkvh, qkvl, qkvh + 1024, qkvl + 1024, nullptr, nullptr, sp, nullptr, nullptr,
        64, 4096, 4096, 1024, 0.03125f, 0, 1);

    softmax_row<<<65536, 256>>>(sp, mask, A_ptr, ah, al);
    convVt_bf16<<<dim3(32, 4, 64), dim3(32, 8)>>>(qkvh, qkvl, vth, vtl);

    // AV, batched
    gemm_mma<<<dim3(1, 8, 64), 256, GEMM_SMEM_BYTES>>>(
        ah, al, vth, vtl, nullptr, nullptr, op, nullptr, nullptr,
        1024, 1024, 1024, 128, 1.0f, 0, 2);

    headln_kernel<<<8192, 256>>>(op, lnhw, lnhb, och, ocl);

    // output projection + residual(x), LN1 (LN emits h1 fp32 + bf16 hi/lo)
    gemm_mma<<<dim3(8, 32, 1), 256, GEMM_SMEM_BYTES>>>(
        och, ocl, woth, wotl, bO, x, h1pre, nullptr, nullptr,
        2048, 2048, 2048, 1024, 1.0f, 0, 0);
    ln1024<<<4096, 256>>>(h1pre, ln1w, ln1b, h1, h1h, h1l);

    // FFN: relu(h1 @ W1 + b1) @ W2 + b2 + h1, LN2 -> out
    gemm_mma<<<dim3(32, 32, 1), 256, GEMM_SMEM_BYTES>>>(
        h1h, h1l, w1th, w1tl, b1, nullptr, nullptr, ffhh, ffhl,
        1024, 1024, 1024, 4096, 1.0f, 1, 0);
    gemm_mma<<<dim3(8, 32, 1), 256, GEMM_SMEM_BYTES>>>(
        ffhh, ffhl, w2th, w2tl, b2, h1, r2pre, nullptr, nullptr,
        4096, 4096, 4096, 1024, 1.0f, 0, 0);
    ln1024<<<4096, 256>>>(r2pre, ln2w, ln2b, out, nullptr, nullptr);
}

// round 9
// speedup vs baseline: 4.1323x; 1.1359x over previous
#include <cuda_runtime.h>
#include <cuda_bf16.h>
#include <cuda_fp16.h>
#include <math.h>
#include <stddef.h>
#include <stdint.h>

#define B_SZ   4
#define S_SZ   1024
#define D_M    1024
#define H_N    16
#define D_INT  64
#define D_V    128
#define HID    4096
#define NTOK   4096
#define HB     64
#define LAMBDA_INIT 0.3555090675909693f
#define HEADLN_SCALE 0.6444909324090307f
#define R2_ELEMS 4194304
#define FULL_ELEMS 71303168

// ======================= helpers =======================
__device__ __forceinline__ uint32_t smem_u32(const void* p) {
    uint32_t a;
    asm("{ .reg .u64 t; cvta.to.shared.u64 t, %1; cvt.u32.u64 %0, t; }" : "=r"(a) : "l"(p));
    return a;
}
#define CP_ASYNC16(sdst, gsrc) \
    asm volatile("cp.async.cg.shared.global [%0], [%1], 16;" :: "r"(sdst), "l"(gsrc) : "memory")
#define CP_COMMIT() asm volatile("cp.async.commit_group;" ::: "memory")
#define CP_WAIT0()  asm volatile("cp.async.wait_group 0;" ::: "memory")
#define CP_WAIT1()  asm volatile("cp.async.wait_group 1;" ::: "memory")

__device__ __forceinline__ void mma_bf16(float* d, uint32_t a0, uint32_t a1, uint32_t a2,
                                         uint32_t a3, uint32_t b0, uint32_t b1) {
    asm volatile(
        "mma.sync.aligned.m16n8k16.row.col.f32.bf16.bf16.f32 "
        "{%0,%1,%2,%3}, {%4,%5,%6,%7}, {%8,%9}, {%0,%1,%2,%3};"
        : "+f"(d[0]), "+f"(d[1]), "+f"(d[2]), "+f"(d[3])
        : "r"(a0), "r"(a1), "r"(a2), "r"(a3), "r"(b0), "r"(b1));
}
__device__ __forceinline__ void mma_f16(float* d, uint32_t a0, uint32_t a1, uint32_t a2,
                                        uint32_t a3, uint32_t b0, uint32_t b1) {
    asm volatile(
        "mma.sync.aligned.m16n8k16.row.col.f32.f16.f16.f32 "
        "{%0,%1,%2,%3}, {%4,%5,%6,%7}, {%8,%9}, {%0,%1,%2,%3};"
        : "+f"(d[0]), "+f"(d[1]), "+f"(d[2]), "+f"(d[3])
        : "r"(a0), "r"(a1), "r"(a2), "r"(a3), "r"(b0), "r"(b1));
}
__device__ __forceinline__ void ldmx4(uint32_t* r, uint32_t addr) {
    asm volatile("ldmatrix.sync.aligned.m8n8.x4.shared.b16 {%0,%1,%2,%3}, [%4];"
        : "=r"(r[0]), "=r"(r[1]), "=r"(r[2]), "=r"(r[3]) : "r"(addr));
}
__device__ __forceinline__ void ldmx2(uint32_t* r, uint32_t addr) {
    asm volatile("ldmatrix.sync.aligned.m8n8.x2.shared.b16 {%0,%1}, [%2];"
        : "=r"(r[0]), "=r"(r[1]) : "r"(addr));
}

template<int TYPE> __device__ __forceinline__ float hival(float v) {
    if (TYPE == 0) return __bfloat162float(__float2bfloat16(v));
    else           return __half2float(__float2half(v));
}
template<int TYPE> __device__ __forceinline__ uint32_t packT(float a, float b) {
    if (TYPE == 0) {
        __nv_bfloat162 p; p.x = __float2bfloat16(a); p.y = __float2bfloat16(b);
        return *reinterpret_cast<uint32_t*>(&p);
    } else {
        __half2 p; p.x = __float2half(a); p.y = __float2half(b);
        return *reinterpret_cast<uint32_t*>(&p);
    }
}

// ======================= static scratch =======================
__device__ __align__(16) __nv_bfloat16  g_QKVh [(size_t)NTOK * 4096];
__device__ __align__(16) __nv_bfloat16  g_QKVl [(size_t)NTOK * 4096];
__device__ __align__(16) __nv_bfloat16  g_Bqh  [(size_t)4096 * 1024];
__device__ __align__(16) __nv_bfloat16  g_Bql  [(size_t)4096 * 1024];
__device__ __align__(16) __half         g_WOth [(size_t)1024 * 2048];
__device__ __align__(16) __half         g_W1th [(size_t)4096 * 1024];
__device__ __align__(16) __half         g_W2th [(size_t)1024 * 4096];
__device__ __align__(16) float          g_biasqkv[4096];
__device__ __align__(16) __nv_bfloat16  g_xh   [(size_t)NTOK * 1024];
__device__ __align__(16) __nv_bfloat16  g_xl   [(size_t)NTOK * 1024];
__device__ __align__(16) float          g_S    [(size_t)HB * S_SZ * S_SZ];
__device__ __align__(16) __nv_bfloat16  g_Ah   [(size_t)HB * S_SZ * S_SZ];
__device__ __align__(16) __nv_bfloat16  g_Al   [(size_t)HB * S_SZ * S_SZ];
__device__ __align__(16) __nv_bfloat16  g_Vth  [(size_t)HB * 128 * 1024];
__device__ __align__(16) __nv_bfloat16  g_Vtl  [(size_t)HB * 128 * 1024];
__device__ __align__(16) float          g_O    [(size_t)HB * S_SZ * D_V];
__device__ __align__(16) __half         g_Och  [(size_t)NTOK * 2048];
__device__ __align__(16) __half         g_Ocl  [(size_t)NTOK * 2048];
__device__ __align__(16) float          g_h1pre[(size_t)NTOK * D_M];
__device__ __align__(16) float          g_h1   [(size_t)NTOK * D_M];
__device__ __align__(16) __half         g_h1h  [(size_t)NTOK * D_M];
__device__ __align__(16) __half         g_h1l  [(size_t)NTOK * D_M];
__device__ __align__(16) __half         g_ffhh [(size_t)NTOK * HID];
__device__ __align__(16) __half         g_ffhl [(size_t)NTOK * HID];
__device__ __align__(16) float          g_r2pre[(size_t)NTOK * D_M];
__device__ float g_lamscale;

// ======================= lambda =======================
__global__ void lam_kernel(const float* __restrict__ lq1, const float* __restrict__ lk1,
                           const float* __restrict__ lq2, const float* __restrict__ lk2)
{
    __shared__ float s1[64], s2[64];
    int t = threadIdx.x;
    s1[t] = lq1[t] * lk1[t];
    s2[t] = lq2[t] * lk2[t];
    __syncthreads();
    if (t == 0) {
        float d1 = 0.f, d2 = 0.f;
        for (int i = 0; i < 64; i++) { d1 += s1[i]; d2 += s2[i]; }
        g_lamscale = 1.0f - (expf(d1) - expf(d2) + LAMBDA_INIT);
    }
}

// ======================= conversions =======================
__global__ void __launch_bounds__(256) conv_hilo(
    const float* __restrict__ in, __nv_bfloat16* __restrict__ oh,
    __nv_bfloat16* __restrict__ ol, int n4)
{
    int i = blockIdx.x * 256 + threadIdx.x;
    if (i >= n4) return;
    float4 v = reinterpret_cast<const float4*>(in)[i];
    __nv_bfloat16 h0 = __float2bfloat16(v.x), h1 = __float2bfloat16(v.y);
    __nv_bfloat16 h2 = __float2bfloat16(v.z), h3 = __float2bfloat16(v.w);
    __nv_bfloat162 p0, p1, q0, q1;
    p0.x = h0; p0.y = h1; p1.x = h2; p1.y = h3;
    q0.x = __float2bfloat16(v.x - __bfloat162float(h0));
    q0.y = __float2bfloat16(v.y - __bfloat162float(h1));
    q1.x = __float2bfloat16(v.z - __bfloat162float(h2));
    q1.y = __float2bfloat16(v.w - __bfloat162float(h3));
    reinterpret_cast<__nv_bfloat162*>(oh)[i * 2]     = p0;
    reinterpret_cast<__nv_bfloat162*>(oh)[i * 2 + 1] = p1;
    reinterpret_cast<__nv_bfloat162*>(ol)[i * 2]     = q0;
    reinterpret_cast<__nv_bfloat162*>(ol)[i * 2 + 1] = q1;
}

// weight transpose-convert: out[n][k] (K-major) from in[(n/dout)*K*dout + k*dout + n%dout]
template<typename T, int LO>
__global__ void convW(const float* __restrict__ in, T* __restrict__ oh,
                      T* __restrict__ ol, int K, int dout)
{
    __shared__ float t[32][33];
    int k0 = blockIdx.x * 32, n0 = blockIdx.y * 32;
    int h = n0 / dout, d0 = n0 - h * dout;
    const float* src = in + (size_t)h * K * dout + d0;
    for (int r = threadIdx.y; r < 32; r += 8)
        t[r][threadIdx.x] = src[(size_t)(k0 + r) * dout + threadIdx.x];
    __syncthreads();
    for (int r = threadIdx.y; r < 32; r += 8) {
        float v = t[threadIdx.x][r];
        T hi = (T)v;
        size_t idx = (size_t)(n0 + r) * K + k0 + threadIdx.x;
        oh[idx] = hi;
        if (LO) ol[idx] = (T)(v - (float)hi);
    }
}

// V transpose (bf16, hi and lo): Vt[z][v][t] from QKVx[(b*1024+t)*4096 + 2048 + h*128 + v]
__global__ void convVt_bf16(const __nv_bfloat16* __restrict__ sh, const __nv_bfloat16* __restrict__ sl,
                            __nv_bfloat16* __restrict__ oh, __nv_bfloat16* __restrict__ ol)
{
    __shared__ __nv_bfloat16 th[32][33];
    __shared__ __nv_bfloat16 tl[32][33];
    int z = blockIdx.z, h = z >> 2, b = z & 3;
    int t0 = blockIdx.x * 32, v0 = blockIdx.y * 32;
    for (int r = threadIdx.y; r < 32; r += 8) {
        size_t si = (size_t)(b * 1024 + t0 + r) * 4096 + 2048 + h * 128 + v0 + threadIdx.x;
        th[r][threadIdx.x] = sh[si];
        tl[r][threadIdx.x] = sl[si];
    }
    __syncthreads();
    size_t base = (size_t)z * 131072;
    for (int r = threadIdx.y; r < 32; r += 8) {
        size_t di = base + (size_t)(v0 + r) * 1024 + t0 + threadIdx.x;
        oh[di] = th[threadIdx.x][r];
        ol[di] = tl[threadIdx.x][r];
    }
}

__global__ void concat_bias(const float* __restrict__ bq, const float* __restrict__ bk,
                            const float* __restrict__ bv, float* __restrict__ o)
{
    int t = blockIdx.x * 256 + threadIdx.x;
    if (t < 1024) o[t] = bq[t];
    else if (t < 2048) o[t] = bk[t - 1024];
    else if (t < 4096) o[t] = bv[t - 2048];
}

// ======================= tensor-core GEMM ====================================
// C[128x128 tile] = sum_k A[m][k]*B[n][k], K-major 16-bit hi/lo.
// TYPE: 0=bf16, 1=fp16. TERMS: 3 = Ah*Bh+Ah*Bl+Al*Bh ; 2 = Ah*Bh+Al*Bh (no Bl).
// modes: 0 plain; 1 scores batched (z=h*4+b); 2 AV batched.
template<int TYPE, int TERMS>
__global__ void __launch_bounds__(256, 2) gemm_mma(
    const uint16_t* __restrict__ Ah, const uint16_t* __restrict__ Al,
    const uint16_t* __restrict__ Bh, const uint16_t* __restrict__ Bl,
    const float* __restrict__ bias, const float* __restrict__ res,
    float* __restrict__ cout, uint16_t* __restrict__ outh, uint16_t* __restrict__ outl,
    int K, int lda, int ldb, int ldc, float alpha, int relu, int mode)
{
    constexpr int NTILE = (TERMS == 3) ? 4 : 3;
    constexpr int STG = NTILE * 10240;
    extern __shared__ char dsm[];
    const int tid = threadIdx.x;
    const int lane = tid & 31, wid = tid >> 5;
    const int wy = wid >> 2, wx = wid & 3;       // warp tile: 64(M) x 32(N)
    const int m0 = blockIdx.y * 128, n0 = blockIdx.x * 128;
    const uint32_t smbase = smem_u32(dsm);

    size_t aoff = 0, boff = 0, coff = 0;
    if (mode == 1) {
        int z = blockIdx.z, h = z >> 2, b = z & 3;
        aoff = (size_t)(b << 10) * lda + (h << 6);
        boff = (size_t)(b << 10) * ldb + (h << 6);
        coff = (size_t)z << 20;
    } else if (mode == 2) {
        int z = blockIdx.z;
        aoff = (size_t)z << 20;
        boff = (size_t)z << 17;
        coff = (size_t)z << 17;
    }

    float acc[4][4][4];
#pragma unroll
    for (int i = 0; i < 4; i++)
#pragma unroll
        for (int j = 0; j < 4; j++)
#pragma unroll
            for (int q = 0; q < 4; q++) acc[i][j][q] = 0.f;

    const int niter = K >> 5;

    auto issue_tile = [&](int it, int stage) {
        int k0 = it << 5;
        uint32_t sb = smbase + stage * STG;
#pragma unroll
        for (int i = 0; i < 2; i++) {
            int l = tid + (i << 8);
            int row = l >> 2, c16 = l & 3;
            size_t aidx = aoff + (size_t)(m0 + row) * lda + k0 + (c16 << 3);
            size_t bidx = boff + (size_t)(n0 + row) * ldb + k0 + (c16 << 3);
            uint32_t so = (uint32_t)(row * 80 + (c16 << 4));
            CP_ASYNC16(sb + so,         Ah + aidx);
            CP_ASYNC16(sb + 10240 + so, Al + aidx);
            CP_ASYNC16(sb + 20480 + so, Bh + bidx);
            if (TERMS == 3) CP_ASYNC16(sb + 30720 + so, Bl + bidx);
        }
        CP_COMMIT();
    };

    issue_tile(0, 0);

    // ldmatrix per-lane addressing
    const int a_row = (wy << 6) + (lane & 7) + ((lane >> 3) & 1) * 8;  // + mt*16
    const int a_kb  = (lane >> 4) << 4;                                // + ks*32
    const int l15 = lane & 15;
    const int b_row = (wx << 5) + (l15 & 7);                           // + nt*8
    const int b_kb  = (l15 >> 3) << 4;                                 // + ks*32

    for (int it = 0; it < niter; it++) {
        int st = it & 1;
        if (it + 1 < niter) { issue_tile(it + 1, st ^ 1); CP_WAIT1(); }
        else { CP_WAIT0(); }
        __syncthreads();

        uint32_t base = smbase + st * STG;
        uint32_t pAh = base;
        uint32_t pAl = base + 10240;
        uint32_t pBh = base + 20480;
        uint32_t pBl = base + 30720;

#pragma unroll
        for (int ks = 0; ks < 2; ks++) {
            const int ksb = ks << 5;
            uint32_t bhf[4][2], blf[4][2];
#pragma unroll
            for (int nt = 0; nt < 4; nt++) {
                uint32_t bo = (uint32_t)((b_row + (nt << 3)) * 80 + ksb + b_kb);
                ldmx2(bhf[nt], pBh + bo);
                if (TERMS == 3) ldmx2(blf[nt], pBl + bo);
            }
#pragma unroll
            for (int mt = 0; mt < 4; mt++) {
                uint32_t ao = (uint32_t)((a_row + (mt << 4)) * 80 + ksb + a_kb);
                uint32_t ahf[4], alf[4];
                ldmx4(ahf, pAh + ao);
                ldmx4(alf, pAl + ao);
#pragma unroll
                for (int nt = 0; nt < 4; nt++) {
                    if (TYPE == 0) {
                        mma_bf16(acc[mt][nt], ahf[0], ahf[1], ahf[2], ahf[3], bhf[nt][0], bhf[nt][1]);
                        if (TERMS == 3)
                            mma_bf16(acc[mt][nt], ahf[0], ahf[1], ahf[2], ahf[3], blf[nt][0], blf[nt][1]);
                        mma_bf16(acc[mt][nt], alf[0], alf[1], alf[2], alf[3], bhf[nt][0], bhf[nt][1]);
                    } else {
                        mma_f16(acc[mt][nt], ahf[0], ahf[1], ahf[2], ahf[3], bhf[nt][0], bhf[nt][1]);
                        if (TERMS == 3)
                            mma_f16(acc[mt][nt], ahf[0], ahf[1], ahf[2], ahf[3], blf[nt][0], blf[nt][1]);
                        mma_f16(acc[mt][nt], alf[0], alf[1], alf[2], alf[3], bhf[nt][0], bhf[nt][1]);
                    }
                }
            }
        }
        __syncthreads();
    }

    // epilogue: alpha, bias, residual, relu; fp32 and/or 16-bit hi/lo outputs
#pragma unroll
    for (int mt = 0; mt < 4; mt++) {
#pragma unroll
        for (int nt = 0; nt < 4; nt++) {
#pragma unroll
            for (int hf = 0; hf < 2; hf++) {
                int row = m0 + (wy << 6) + (mt << 4) + (lane >> 2) + (hf << 3);
                int col = n0 + (wx << 5) + (nt << 3) + ((lane & 3) << 1);
                float v0 = acc[mt][nt][hf * 2]     * alpha;
                float v1 = acc[mt][nt][hf * 2 + 1] * alpha;
                if (bias) { v0 += bias[col]; v1 += bias[col + 1]; }
                if (res) {
                    float2 rv = *reinterpret_cast<const float2*>(res + (size_t)row * ldc + col);
                    v0 += rv.x; v1 += rv.y;
                }
                if (relu) { v0 = fmaxf(v0, 0.f); v1 = fmaxf(v1, 0.f); }
                size_t oidx = coff + (size_t)row * ldc + col;
                if (cout) *reinterpret_cast<float2*>(cout + oidx) = make_float2(v0, v1);
                if (outh) {
                    float h0 = hival<TYPE>(v0), h1 = hival<TYPE>(v1);
                    *reinterpret_cast<uint32_t*>(outh + oidx) = packT<TYPE>(v0, v1);
                    *reinterpret_cast<uint32_t*>(outl + oidx) = packT<TYPE>(v0 - h0, v1 - h1);
                }
            }
        }
    }
}

// ======================= softmax (emits fp32 + bf16 hi/lo) ==================
__global__ void __launch_bounds__(256) softmax_row(
    const float* __restrict__ Sc, const int* __restrict__ mask, float* __restrict__ Aout,
    __nv_bfloat16* __restrict__ Ahi, __nv_bfloat16* __restrict__ Alo)
{
    __shared__ float red[8];
    __shared__ float bcast;
    size_t row = blockIdx.x;
    int b = (int)((row >> 10) & 3);
    const float* in = Sc + row * 1024;
    const int* mrow = mask + b * 1024;
    int t = threadIdx.x;
    int wid = t >> 5, lane = t & 31;

    float v[4];
    float mx = -INFINITY;
#pragma unroll
    for (int i = 0; i < 4; i++) {
        int c = t + i * 256;
        float val = in[c];
        if (mrow[c] == 0) val = -INFINITY;
        v[i] = val;
        mx = fmaxf(mx, val);
    }
#pragma unroll
    for (int o = 16; o; o >>= 1) mx = fmaxf(mx, __shfl_xor_sync(0xffffffffu, mx, o));
    if (lane == 0) red[wid] = mx;
    __syncthreads();
    if (t < 32) {
        float m2 = (t < 8) ? red[t] : -INFINITY;
#pragma unroll
        for (int o = 4; o; o >>= 1) m2 = fmaxf(m2, __shfl_xor_sync(0xffffffffu, m2, o));
        if (t == 0) bcast = m2;
    }
    __syncthreads();
    mx = bcast;

    float sum = 0.f;
#pragma unroll
    for (int i = 0; i < 4; i++) { v[i] = expf(v[i] - mx); sum += v[i]; }
#pragma unroll
    for (int o = 16; o; o >>= 1) sum += __shfl_xor_sync(0xffffffffu, sum, o);
    __syncthreads();
    if (lane == 0) red[wid] = sum;
    __syncthreads();
    if (t < 32) {
        float s2 = (t < 8) ? red[t] : 0.f;
#pragma unroll
        for (int o = 4; o; o >>= 1) s2 += __shfl_xor_sync(0xffffffffu, s2, o);
        if (t == 0) bcast = g_lamscale / s2;
    }
    __syncthreads();
    float sc = bcast;
#pragma unroll
    for (int i = 0; i < 4; i++) {
        size_t idx = row * 1024 + t + i * 256;
        float vv = v[i] * sc;
        Aout[idx] = vv;
        __nv_bfloat16 hi = __float2bfloat16(vv);
        Ahi[idx] = hi;
        Alo[idx] = __float2bfloat16(vv - __bfloat162float(hi));
    }
}

// ======================= per-head LN(128) + concat, emits fp16 hi/lo ========
__global__ void __launch_bounds__(256) headln_kernel(
    const float* __restrict__ O, const float* __restrict__ w,
    const float* __restrict__ bvec, __half* __restrict__ och,
    __half* __restrict__ ocl)
{
    int gw = blockIdx.x * 8 + (threadIdx.x >> 5);
    int lane = threadIdx.x & 31;
    const float* xr = O + (size_t)gw * 128;
    float x0 = xr[lane], x1 = xr[lane + 32], x2 = xr[lane + 64], x3 = xr[lane + 96];
    float s = x0 + x1 + x2 + x3;
#pragma unroll
    for (int o = 16; o; o >>= 1) s += __shfl_xor_sync(0xffffffffu, s, o);
    float mean = s * (1.f / 128.f);
    float d0 = x0 - mean, d1 = x1 - mean, d2 = x2 - mean, d3 = x3 - mean;
    float q = d0 * d0 + d1 * d1 + d2 * d2 + d3 * d3;
#pragma unroll
    for (int o = 16; o; o >>= 1) q += __shfl_xor_sync(0xffffffffu, q, o);
    float rstd = rsqrtf(q * (1.f / 128.f) + 1e-5f);

    int z = gw >> 10, s_ = gw & 1023;
    int h = z >> 2, b = z & 3;
    size_t base = ((size_t)(b * S_SZ + s_)) * 2048 + h * 128;
    float vals[4] = {
        (d0 * rstd * w[lane]      + bvec[lane])      * HEADLN_SCALE,
        (d1 * rstd * w[lane + 32] + bvec[lane + 32]) * HEADLN_SCALE,
        (d2 * rstd * w[lane + 64] + bvec[lane + 64]) * HEADLN_SCALE,
        (d3 * rstd * w[lane + 96] + bvec[lane + 96]) * HEADLN_SCALE };
#pragma unroll
    for (int i = 0; i < 4; i++) {
        __half hi = __float2half(vals[i]);
        och[base + lane + i * 32] = hi;
        ocl[base + lane + i * 32] = __float2half(vals[i] - __half2float(hi));
    }
}

// ======================= LayerNorm 1024 (optional fp16 hi/lo out) ===========
__global__ void __launch_bounds__(256) ln1024(
    const float* __restrict__ X, const float* __restrict__ w,
    const float* __restrict__ bvec, float* __restrict__ out,
    __half* __restrict__ outh, __half* __restrict__ outl)
{
    __shared__ float red[8];
    __shared__ float bc;
    size_t row = blockIdx.x;
    const float* xr = X + row * 1024;
    int t = threadIdx.x;
    int wid = t >> 5, lane = t & 31;

    float v[4];
    float s = 0.f;
#pragma unroll
    for (int i = 0; i < 4; i++) { v[i] = xr[t + i * 256]; s += v[i]; }
#pragma unroll
    for (int o = 16; o; o >>= 1) s += __shfl_xor_sync(0xffffffffu, s, o);
    if (lane == 0) red[wid] = s;
    __syncthreads();
    if (t < 32) {
        float s2 = (t < 8) ? red[t] : 0.f;
#pragma unroll
        for (int o = 4; o; o >>= 1) s2 += __shfl_xor_sync(0xffffffffu, s2, o);
        if (t == 0) bc = s2 * (1.f / 1024.f);
    }
    __syncthreads();
    float mean = bc;

    float q = 0.f;
#pragma unroll
    for (int i = 0; i < 4; i++) { float d = v[i] - mean; q += d * d; }
#pragma unroll
    for (int o = 16; o; o >>= 1) q += __shfl_xor_sync(0xffffffffu, q, o);
    __syncthreads();
    if (lane == 0) red[wid] = q;
    __syncthreads();
    if (t < 32) {
        float q2 = (t < 8) ? red[t] : 0.f;
#pragma unroll
        for (int o = 4; o; o >>= 1) q2 += __shfl_xor_sync(0xffffffffu, q2, o);
        if (t == 0) bc = rsqrtf(q2 * (1.f / 1024.f) + 1e-5f);
    }
    __syncthreads();
    float rstd = bc;
#pragma unroll
    for (int i = 0; i < 4; i++) {
        int c = t + i * 256;
        float vv = (v[i] - mean) * rstd * w[c] + bvec[c];
        out[row * 1024 + c] = vv;
        if (outh) {
            __half hi = __float2half(vv);
            outh[row * 1024 + c] = hi;
            outl[row * 1024 + c] = __float2half(vv - __half2float(hi));
        }
    }
}

// ======================= host launcher ======================================
extern "C" void kernel_launch(void* const* d_in, const int* in_sizes, int n_in,
                              void* d_out, int out_size)
{
    const float* x    = (const float*)d_in[0];
    const int*   mask = (const int*)  d_in[1];
    const float* WQ1  = (const float*)d_in[2];
    const float* bQ1  = (const float*)d_in[3];
    const float* WK1  = (const float*)d_in[4];
    const float* bK1  = (const float*)d_in[5];
    const float* WV   = (const float*)d_in[6];
    const float* bV   = (const float*)d_in[7];
    const float* lnhw = (const float*)d_in[8];
    const float* lnhb = (const float*)d_in[9];
    const float* WO   = (const float*)d_in[10];
    const float* bO   = (const float*)d_in[11];
    const float* ln1w = (const float*)d_in[12];
    const float* ln1b = (const float*)d_in[13];
    const float* ln2w = (const float*)d_in[14];
    const float* ln2b = (const float*)d_in[15];
    const float* W1   = (const float*)d_in[16];
    const float* b1   = (const float*)d_in[17];
    const float* W2   = (const float*)d_in[18];
    const float* b2   = (const float*)d_in[19];
    const float* lq1  = (const float*)d_in[20];
    const float* lk1  = (const float*)d_in[21];
    const float* lq2  = (const float*)d_in[22];
    const float* lk2  = (const float*)d_in[23];

    float* out = (float*)d_out;

    const int SM3 = 2 * 4 * 10240;   // 81920: bf16 3-term, double-buffered
    const int SM2 = 2 * 3 * 10240;   // 61440: fp16 2-term
    cudaFuncSetAttribute(gemm_mma<0, 3>, cudaFuncAttributeMaxDynamicSharedMemorySize, SM3);
    cudaFuncSetAttribute(gemm_mma<1, 2>, cudaFuncAttributeMaxDynamicSharedMemorySize, SM2);

    float *sp, *op, *h1pre, *h1, *r2pre, *biasqkv;
    __nv_bfloat16 *qkvh, *qkvl, *bqh, *bql, *xh, *xl, *ah, *al, *vth, *vtl;
    __half *woth, *w1th, *w2th, *och, *ocl, *h1h, *h1l, *ffhh, *ffhl;
    cudaGetSymbolAddress((void**)&qkvh,  g_QKVh);
    cudaGetSymbolAddress((void**)&qkvl,  g_QKVl);
    cudaGetSymbolAddress((void**)&bqh,   g_Bqh);
    cudaGetSymbolAddress((void**)&bql,   g_Bql);
    cudaGetSymbolAddress((void**)&woth,  g_WOth);
    cudaGetSymbolAddress((void**)&w1th,  g_W1th);
    cudaGetSymbolAddress((void**)&w2th,  g_W2th);
    cudaGetSymbolAddress((void**)&biasqkv, g_biasqkv);
    cudaGetSymbolAddress((void**)&xh,    g_xh);
    cudaGetSymbolAddress((void**)&xl,    g_xl);
    cudaGetSymbolAddress((void**)&sp,    g_S);
    cudaGetSymbolAddress((void**)&ah,    g_Ah);
    cudaGetSymbolAddress((void**)&al,    g_Al);
    cudaGetSymbolAddress((void**)&vth,   g_Vth);
    cudaGetSymbolAddress((void**)&vtl,   g_Vtl);
    cudaGetSymbolAddress((void**)&op,    g_O);
    cudaGetSymbolAddress((void**)&och,   g_Och);
    cudaGetSymbolAddress((void**)&ocl,   g_Ocl);
    cudaGetSymbolAddress((void**)&h1pre, g_h1pre);
    cudaGetSymbolAddress((void**)&h1,    g_h1);
    cudaGetSymbolAddress((void**)&h1h,   g_h1h);
    cudaGetSymbolAddress((void**)&h1l,   g_h1l);
    cudaGetSymbolAddress((void**)&ffhh,  g_ffhh);
    cudaGetSymbolAddress((void**)&ffhl,  g_ffhl);
    cudaGetSymbolAddress((void**)&r2pre, g_r2pre);

    float* A_ptr = (out_size >= FULL_ELEMS) ? (out + R2_ELEMS) : sp;

    lam_kernel<<<1, 64>>>(lq1, lk1, lq2, lk2);
    concat_bias<<<16, 256>>>(bQ1, bK1, bV, biasqkv);

    // weight transpose-converts: QKV weights bf16 hi/lo; WO/W1/W2 fp16 hi only
    convW<__nv_bfloat16, 1><<<dim3(32, 32),  dim3(32, 8)>>>(WQ1, bqh,               bql,               1024, 64);
    convW<__nv_bfloat16, 1><<<dim3(32, 32),  dim3(32, 8)>>>(WK1, bqh + 1024 * 1024, bql + 1024 * 1024, 1024, 64);
    convW<__nv_bfloat16, 1><<<dim3(32, 64),  dim3(32, 8)>>>(WV,  bqh + 2048 * 1024, bql + 2048 * 1024, 1024, 128);
    convW<__half, 0>       <<<dim3(64, 32),  dim3(32, 8)>>>(WO,  woth, nullptr, 2048, 1024);
    convW<__half, 0>       <<<dim3(32, 128), dim3(32, 8)>>>(W1,  w1th, nullptr, 1024, 4096);
    convW<__half, 0>       <<<dim3(128, 32), dim3(32, 8)>>>(W2,  w2th, nullptr, 4096, 1024);
    conv_hilo<<<4096, 256>>>(x, xh, xl, 1048576);

    // fused QKV projection (bf16 3-term): [4096, 4096], K=1024
    gemm_mma<0, 3><<<dim3(32, 32, 1), 256, SM3>>>(
        (const uint16_t*)xh, (const uint16_t*)xl, (const uint16_t*)bqh, (const uint16_t*)bql,
        biasqkv, nullptr, nullptr, (uint16_t*)qkvh, (uint16_t*)qkvl,
        1024, 1024, 1024, 4096, 1.0f, 0, 0);

    // scores (bf16 3-term), batched z=h*4+b, alpha = 1/sqrt(1024)
    gemm_mma<0, 3><<<dim3(8, 8, 64), 256, SM3>>>(
        (const uint16_t*)qkvh, (const uint16_t*)qkvl,
        (const uint16_t*)(qkvh + 1024), (const uint16_t*)(qkvl + 1024),
        nullptr, nullptr, sp, nullptr, nullptr,
        64, 4096, 4096, 1024, 0.03125f, 0, 1);

    softmax_row<<<65536, 256>>>(sp, mask, A_ptr, ah, al);
    convVt_bf16<<<dim3(32, 4, 64), dim3(32, 8)>>>(qkvh, qkvl, vth, vtl);

    // AV (bf16 3-term), batched
    gemm_mma<0, 3><<<dim3(1, 8, 64), 256, SM3>>>(
        (const uint16_t*)ah, (const uint16_t*)al, (const uint16_t*)vth, (const uint16_t*)vtl,
        nullptr, nullptr, op, nullptr, nullptr,
        1024, 1024, 1024, 128, 1.0f, 0, 2);

    headln_kernel<<<8192, 256>>>(op, lnhw, lnhb, och, ocl);

    // output projection (fp16 2-term) + residual(x), LN1 (emits h1 fp32 + fp16 hi/lo)
    gemm_mma<1, 2><<<dim3(8, 32, 1), 256, SM2>>>(
        (const uint16_t*)och, (const uint16_t*)ocl, (const uint16_t*)woth, nullptr,
        bO, x, h1pre, nullptr, nullptr,
        2048, 2048, 2048, 1024, 1.0f, 0, 0);
    ln1024<<<4096, 256>>>(h1pre, ln1w, ln1b, h1, h1h, h1l);

    // FFN (fp16 2-term): relu(h1 @ W1 + b1) @ W2 + b2 + h1, LN2 -> out
    gemm_mma<1, 2><<<dim3(32, 32, 1), 256, SM2>>>(
        (const uint16_t*)h1h, (const uint16_t*)h1l, (const uint16_t*)w1th, nullptr,
        b1, nullptr, nullptr, (uint16_t*)ffhh, (uint16_t*)ffhl,
        1024, 1024, 1024, 4096, 1.0f, 1, 0);
    gemm_mma<1, 2><<<dim3(8, 32, 1), 256, SM2>>>(
        (const uint16_t*)ffhh, (const uint16_t*)ffhl, (const uint16_t*)w2th, nullptr,
        b2, h1, r2pre, nullptr, nullptr,
        4096, 4096, 4096, 1024, 1.0f, 0, 0);
    ln1024<<<4096, 256>>>(r2pre, ln2w, ln2b, out, nullptr, nullptr);
}

// round 10
// speedup vs baseline: 4.2089x; 1.0186x over previous
#include <cuda_runtime.h>
#include <cuda_bf16.h>
#include <cuda_fp16.h>
#include <math.h>
#include <stddef.h>
#include <stdint.h>

#define B_SZ   4
#define S_SZ   1024
#define D_M    1024
#define H_N    16
#define D_INT  64
#define D_V    128
#define HID    4096
#define NTOK   4096
#define HB     64
#define LAMBDA_INIT 0.3555090675909693f
#define HEADLN_SCALE 0.6444909324090307f
#define R2_ELEMS 4194304
#define FULL_ELEMS 71303168

// ======================= helpers =======================
__device__ __forceinline__ uint32_t smem_u32(const void* p) {
    uint32_t a;
    asm("{ .reg .u64 t; cvta.to.shared.u64 t, %1; cvt.u32.u64 %0, t; }" : "=r"(a) : "l"(p));
    return a;
}
#define CP_ASYNC16(sdst, gsrc) \
    asm volatile("cp.async.cg.shared.global [%0], [%1], 16;" :: "r"(sdst), "l"(gsrc) : "memory")
#define CP_COMMIT() asm volatile("cp.async.commit_group;" ::: "memory")
template<int N> __device__ __forceinline__ void cp_waitg() {
    asm volatile("cp.async.wait_group %0;" :: "n"(N) : "memory");
}

__device__ __forceinline__ void mma_bf16(float* d, uint32_t a0, uint32_t a1, uint32_t a2,
                                         uint32_t a3, uint32_t b0, uint32_t b1) {
    asm volatile(
        "mma.sync.aligned.m16n8k16.row.col.f32.bf16.bf16.f32 "
        "{%0,%1,%2,%3}, {%4,%5,%6,%7}, {%8,%9}, {%0,%1,%2,%3};"
        : "+f"(d[0]), "+f"(d[1]), "+f"(d[2]), "+f"(d[3])
        : "r"(a0), "r"(a1), "r"(a2), "r"(a3), "r"(b0), "r"(b1));
}
__device__ __forceinline__ void mma_f16(float* d, uint32_t a0, uint32_t a1, uint32_t a2,
                                        uint32_t a3, uint32_t b0, uint32_t b1) {
    asm volatile(
        "mma.sync.aligned.m16n8k16.row.col.f32.f16.f16.f32 "
        "{%0,%1,%2,%3}, {%4,%5,%6,%7}, {%8,%9}, {%0,%1,%2,%3};"
        : "+f"(d[0]), "+f"(d[1]), "+f"(d[2]), "+f"(d[3])
        : "r"(a0), "r"(a1), "r"(a2), "r"(a3), "r"(b0), "r"(b1));
}
__device__ __forceinline__ void ldmx4(uint32_t* r, uint32_t addr) {
    asm volatile("ldmatrix.sync.aligned.m8n8.x4.shared.b16 {%0,%1,%2,%3}, [%4];"
        : "=r"(r[0]), "=r"(r[1]), "=r"(r[2]), "=r"(r[3]) : "r"(addr));
}
__device__ __forceinline__ void ldmx2(uint32_t* r, uint32_t addr) {
    asm volatile("ldmatrix.sync.aligned.m8n8.x2.shared.b16 {%0,%1}, [%2];"
        : "=r"(r[0]), "=r"(r[1]) : "r"(addr));
}

template<int TYPE> __device__ __forceinline__ float hival(float v) {
    if (TYPE == 0) return __bfloat162float(__float2bfloat16(v));
    else           return __half2float(__float2half(v));
}
template<int TYPE> __device__ __forceinline__ uint32_t packT(float a, float b) {
    if (TYPE == 0) {
        __nv_bfloat162 p; p.x = __float2bfloat16(a); p.y = __float2bfloat16(b);
        return *reinterpret_cast<uint32_t*>(&p);
    } else {
        __half2 p; p.x = __float2half(a); p.y = __float2half(b);
        return *reinterpret_cast<uint32_t*>(&p);
    }
}

// ======================= static scratch =======================
__device__ __align__(16) __nv_bfloat16  g_QKh  [(size_t)NTOK * 2048];   // Q|K bf16 hi
__device__ __align__(16) __nv_bfloat16  g_QKl  [(size_t)NTOK * 2048];
__device__ __align__(16) __nv_bfloat16  g_Bqh  [(size_t)2048 * 1024];   // WQ|WK K-major
__device__ __align__(16) __nv_bfloat16  g_Bql  [(size_t)2048 * 1024];
__device__ __align__(16) __half         g_WVh  [(size_t)2048 * 1024];   // WV fp16 hi
__device__ __align__(16) __half         g_WOth [(size_t)1024 * 2048];
__device__ __align__(16) __half         g_W1th [(size_t)4096 * 1024];
__device__ __align__(16) __half         g_W2th [(size_t)1024 * 4096];
__device__ __align__(16) float          g_biasqk[2048];
__device__ __align__(16) __nv_bfloat16  g_xh   [(size_t)NTOK * 1024];
__device__ __align__(16) __nv_bfloat16  g_xl   [(size_t)NTOK * 1024];
__device__ __align__(16) __half         g_xhf  [(size_t)NTOK * 1024];
__device__ __align__(16) __half         g_xlf  [(size_t)NTOK * 1024];
__device__ __align__(16) float          g_S    [(size_t)HB * S_SZ * S_SZ];
__device__ __align__(16) __half         g_Ah   [(size_t)HB * S_SZ * S_SZ];
__device__ __align__(16) __half         g_Al   [(size_t)HB * S_SZ * S_SZ];
__device__ __align__(16) __half         g_Vh   [(size_t)NTOK * 2048];   // V fp16 hi [tok][h*128+v]
__device__ __align__(16) __half         g_Vth  [(size_t)HB * 128 * 1024]; // V^T fp16 hi
__device__ __align__(16) float          g_O    [(size_t)HB * S_SZ * D_V];
__device__ __align__(16) __half         g_Och  [(size_t)NTOK * 2048];
__device__ __align__(16) __half         g_Ocl  [(size_t)NTOK * 2048];
__device__ __align__(16) float          g_h1pre[(size_t)NTOK * D_M];
__device__ __align__(16) float          g_h1   [(size_t)NTOK * D_M];
__device__ __align__(16) __half         g_h1h  [(size_t)NTOK * D_M];
__device__ __align__(16) __half         g_h1l  [(size_t)NTOK * D_M];
__device__ __align__(16) __half         g_ffhh [(size_t)NTOK * HID];
__device__ __align__(16) __half         g_ffhl [(size_t)NTOK * HID];
__device__ __align__(16) float          g_r2pre[(size_t)NTOK * D_M];
__device__ float g_lamscale;

// ======================= lambda =======================
__global__ void lam_kernel(const float* __restrict__ lq1, const float* __restrict__ lk1,
                           const float* __restrict__ lq2, const float* __restrict__ lk2)
{
    __shared__ float s1[64], s2[64];
    int t = threadIdx.x;
    s1[t] = lq1[t] * lk1[t];
    s2[t] = lq2[t] * lk2[t];
    __syncthreads();
    if (t == 0) {
        float d1 = 0.f, d2 = 0.f;
        for (int i = 0; i < 64; i++) { d1 += s1[i]; d2 += s2[i]; }
        g_lamscale = 1.0f - (expf(d1) - expf(d2) + LAMBDA_INIT);
    }
}

// ======================= conversions =======================
// x -> bf16 hi/lo (for QK GEMM) AND fp16 hi/lo (for V GEMM)
__global__ void __launch_bounds__(256) conv_hilo_both(
    const float* __restrict__ in,
    __nv_bfloat16* __restrict__ obh, __nv_bfloat16* __restrict__ obl,
    __half* __restrict__ ofh, __half* __restrict__ ofl, int n4)
{
    int i = blockIdx.x * 256 + threadIdx.x;
    if (i >= n4) return;
    float4 v = reinterpret_cast<const float4*>(in)[i];
    float vv[4] = {v.x, v.y, v.z, v.w};
    uint32_t bh[2], bl[2], fh[2], fl[2];
#pragma unroll
    for (int p = 0; p < 2; p++) {
        float a = vv[p * 2], b = vv[p * 2 + 1];
        float ha = hival<0>(a), hb = hival<0>(b);
        bh[p] = packT<0>(a, b);
        bl[p] = packT<0>(a - ha, b - hb);
        float fa = hival<1>(a), fb = hival<1>(b);
        fh[p] = packT<1>(a, b);
        fl[p] = packT<1>(a - fa, b - fb);
    }
    reinterpret_cast<uint32_t*>(obh)[i * 2] = bh[0];  reinterpret_cast<uint32_t*>(obh)[i * 2 + 1] = bh[1];
    reinterpret_cast<uint32_t*>(obl)[i * 2] = bl[0];  reinterpret_cast<uint32_t*>(obl)[i * 2 + 1] = bl[1];
    reinterpret_cast<uint32_t*>(ofh)[i * 2] = fh[0];  reinterpret_cast<uint32_t*>(ofh)[i * 2 + 1] = fh[1];
    reinterpret_cast<uint32_t*>(ofl)[i * 2] = fl[0];  reinterpret_cast<uint32_t*>(ofl)[i * 2 + 1] = fl[1];
}

// weight transpose-convert: out[n][k] (K-major) from in[(n/dout)*K*dout + k*dout + n%dout]
template<typename T, int LO>
__global__ void convW(const float* __restrict__ in, T* __restrict__ oh,
                      T* __restrict__ ol, int K, int dout)
{
    __shared__ float t[32][33];
    int k0 = blockIdx.x * 32, n0 = blockIdx.y * 32;
    int h = n0 / dout, d0 = n0 - h * dout;
    const float* src = in + (size_t)h * K * dout + d0;
    for (int r = threadIdx.y; r < 32; r += 8)
        t[r][threadIdx.x] = src[(size_t)(k0 + r) * dout + threadIdx.x];
    __syncthreads();
    for (int r = threadIdx.y; r < 32; r += 8) {
        float v = t[threadIdx.x][r];
        T hi = (T)v;
        size_t idx = (size_t)(n0 + r) * K + k0 + threadIdx.x;
        oh[idx] = hi;
        if (LO) ol[idx] = (T)(v - (float)hi);
    }
}

// V transpose (fp16 hi): Vt[z][v][t] from Vh[(b*1024+t)*2048 + h*128 + v]
__global__ void convVt_f16(const __half* __restrict__ sh, __half* __restrict__ oh)
{
    __shared__ __half th[32][33];
    int z = blockIdx.z, h = z >> 2, b = z & 3;
    int t0 = blockIdx.x * 32, v0 = blockIdx.y * 32;
    for (int r = threadIdx.y; r < 32; r += 8)
        th[r][threadIdx.x] = sh[(size_t)(b * 1024 + t0 + r) * 2048 + h * 128 + v0 + threadIdx.x];
    __syncthreads();
    size_t base = (size_t)z * 131072;
    for (int r = threadIdx.y; r < 32; r += 8)
        oh[base + (size_t)(v0 + r) * 1024 + t0 + threadIdx.x] = th[threadIdx.x][r];
}

__global__ void concat_bias2(const float* __restrict__ bq, const float* __restrict__ bk,
                             float* __restrict__ o)
{
    int t = blockIdx.x * 256 + threadIdx.x;
    if (t < 1024) o[t] = bq[t];
    else if (t < 2048) o[t] = bk[t - 1024];
}

// ======================= tensor-core GEMM ====================================
// C[128x128 tile] = sum_k A[m][k]*B[n][k], K-major 16-bit hi/lo.
// TYPE: 0=bf16, 1=fp16. TERMS: 3 = Ah*Bh+Ah*Bl+Al*Bh ; 2 = Ah*Bh+Al*Bh (no Bl).
// NS: cp.async pipeline depth. modes: 0 plain; 1 scores batched; 2 AV batched.
template<int TYPE, int TERMS, int NS>
__global__ void __launch_bounds__(256, 2) gemm_mma(
    const uint16_t* __restrict__ Ah, const uint16_t* __restrict__ Al,
    const uint16_t* __restrict__ Bh, const uint16_t* __restrict__ Bl,
    const float* __restrict__ bias, const float* __restrict__ res,
    float* __restrict__ cout, uint16_t* __restrict__ outh, uint16_t* __restrict__ outl,
    int K, int lda, int ldb, int ldc, float alpha, int relu, int mode)
{
    constexpr int NTILE = (TERMS == 3) ? 4 : 3;
    constexpr int STG = NTILE * 10240;
    extern __shared__ char dsm[];
    const int tid = threadIdx.x;
    const int lane = tid & 31, wid = tid >> 5;
    const int wy = wid >> 2, wx = wid & 3;       // warp tile: 64(M) x 32(N)
    const int m0 = blockIdx.y * 128, n0 = blockIdx.x * 128;
    const uint32_t smbase = smem_u32(dsm);

    size_t aoff = 0, boff = 0, coff = 0;
    if (mode == 1) {
        int z = blockIdx.z, h = z >> 2, b = z & 3;
        aoff = (size_t)(b << 10) * lda + (h << 6);
        boff = (size_t)(b << 10) * ldb + (h << 6);
        coff = (size_t)z << 20;
    } else if (mode == 2) {
        int z = blockIdx.z;
        aoff = (size_t)z << 20;
        boff = (size_t)z << 17;
        coff = (size_t)z << 17;
    }

    float acc[4][4][4];
#pragma unroll
    for (int i = 0; i < 4; i++)
#pragma unroll
        for (int j = 0; j < 4; j++)
#pragma unroll
            for (int q = 0; q < 4; q++) acc[i][j][q] = 0.f;

    const int niter = K >> 5;

    auto issue_tile = [&](int it, int slot) {
        int k0 = it << 5;
        uint32_t sb = smbase + slot * STG;
#pragma unroll
        for (int i = 0; i < 2; i++) {
            int l = tid + (i << 8);
            int row = l >> 2, c16 = l & 3;
            size_t aidx = aoff + (size_t)(m0 + row) * lda + k0 + (c16 << 3);
            size_t bidx = boff + (size_t)(n0 + row) * ldb + k0 + (c16 << 3);
            uint32_t so = (uint32_t)(row * 80 + (c16 << 4));
            CP_ASYNC16(sb + so,         Ah + aidx);
            CP_ASYNC16(sb + 10240 + so, Al + aidx);
            CP_ASYNC16(sb + 20480 + so, Bh + bidx);
            if (TERMS == 3) CP_ASYNC16(sb + 30720 + so, Bl + bidx);
        }
        CP_COMMIT();
    };

#pragma unroll
    for (int s = 0; s < NS - 1; s++)
        if (s < niter) issue_tile(s, s);

    // ldmatrix per-lane addressing
    const int a_row = (wy << 6) + (lane & 7) + ((lane >> 3) & 1) * 8;  // + mt*16
    const int a_kb  = (lane >> 4) << 4;                                // + ks*32
    const int l15 = lane & 15;
    const int b_row = (wx << 5) + (l15 & 7);                           // + nt*8
    const int b_kb  = (l15 >> 3) << 4;                                 // + ks*32

    int cs = 0, is_ = NS - 1;
#pragma unroll 1
    for (int it = 0; it < niter; it++) {
        if (it + NS - 1 < niter) {
            issue_tile(it + NS - 1, is_);
            cp_waitg<NS - 1>();
        } else {
            cp_waitg<0>();
        }
        __syncthreads();

        uint32_t base = smbase + cs * STG;
        uint32_t pAh = base;
        uint32_t pAl = base + 10240;
        uint32_t pBh = base + 20480;
        uint32_t pBl = base + 30720;

#pragma unroll
        for (int ks = 0; ks < 2; ks++) {
            const int ksb = ks << 5;
            uint32_t bhf[4][2], blf[4][2];
#pragma unroll
            for (int nt = 0; nt < 4; nt++) {
                uint32_t bo = (uint32_t)((b_row + (nt << 3)) * 80 + ksb + b_kb);
                ldmx2(bhf[nt], pBh + bo);
                if (TERMS == 3) ldmx2(blf[nt], pBl + bo);
            }
#pragma unroll
            for (int mt = 0; mt < 4; mt++) {
                uint32_t ao = (uint32_t)((a_row + (mt << 4)) * 80 + ksb + a_kb);
                uint32_t ahf[4], alf[4];
                ldmx4(ahf, pAh + ao);
                ldmx4(alf, pAl + ao);
#pragma unroll
                for (int nt = 0; nt < 4; nt++) {
                    if (TYPE == 0) {
                        mma_bf16(acc[mt][nt], ahf[0], ahf[1], ahf[2], ahf[3], bhf[nt][0], bhf[nt][1]);
                        if (TERMS == 3)
                            mma_bf16(acc[mt][nt], ahf[0], ahf[1], ahf[2], ahf[3], blf[nt][0], blf[nt][1]);
                        mma_bf16(acc[mt][nt], alf[0], alf[1], alf[2], alf[3], bhf[nt][0], bhf[nt][1]);
                    } else {
                        mma_f16(acc[mt][nt], ahf[0], ahf[1], ahf[2], ahf[3], bhf[nt][0], bhf[nt][1]);
                        if (TERMS == 3)
                            mma_f16(acc[mt][nt], ahf[0], ahf[1], ahf[2], ahf[3], blf[nt][0], blf[nt][1]);
                        mma_f16(acc[mt][nt], alf[0], alf[1], alf[2], alf[3], bhf[nt][0], bhf[nt][1]);
                    }
                }
            }
        }
        __syncthreads();
        cs = (cs + 1 == NS) ? 0 : cs + 1;
        is_ = (is_ + 1 == NS) ? 0 : is_ + 1;
    }

    // epilogue: alpha, bias, residual, relu; fp32 and/or 16-bit hi/lo outputs
#pragma unroll
    for (int mt = 0; mt < 4; mt++) {
#pragma unroll
        for (int nt = 0; nt < 4; nt++) {
#pragma unroll
            for (int hf = 0; hf < 2; hf++) {
                int row = m0 + (wy << 6) + (mt << 4) + (lane >> 2) + (hf << 3);
                int col = n0 + (wx << 5) + (nt << 3) + ((lane & 3) << 1);
                float v0 = acc[mt][nt][hf * 2]     * alpha;
                float v1 = acc[mt][nt][hf * 2 + 1] * alpha;
                if (bias) { v0 += bias[col]; v1 += bias[col + 1]; }
                if (res) {
                    float2 rv = *reinterpret_cast<const float2*>(res + (size_t)row * ldc + col);
                    v0 += rv.x; v1 += rv.y;
                }
                if (relu) { v0 = fmaxf(v0, 0.f); v1 = fmaxf(v1, 0.f); }
                size_t oidx = coff + (size_t)row * ldc + col;
                if (cout) *reinterpret_cast<float2*>(cout + oidx) = make_float2(v0, v1);
                if (outh) {
                    *reinterpret_cast<uint32_t*>(outh + oidx) = packT<TYPE>(v0, v1);
                    if (outl) {
                        float h0 = hival<TYPE>(v0), h1 = hival<TYPE>(v1);
                        *reinterpret_cast<uint32_t*>(outl + oidx) = packT<TYPE>(v0 - h0, v1 - h1);
                    }
                }
            }
        }
    }
}

// ======================= softmax (emits fp32 + fp16 hi/lo) ==================
__global__ void __launch_bounds__(256) softmax_row(
    const float* __restrict__ Sc, const int* __restrict__ mask, float* __restrict__ Aout,
    __half* __restrict__ Ahi, __half* __restrict__ Alo)
{
    __shared__ float red[8];
    __shared__ float bcast;
    size_t row = blockIdx.x;
    int b = (int)((row >> 10) & 3);
    const float* in = Sc + row * 1024;
    const int* mrow = mask + b * 1024;
    int t = threadIdx.x;
    int wid = t >> 5, lane = t & 31;

    float v[4];
    float mx = -INFINITY;
#pragma unroll
    for (int i = 0; i < 4; i++) {
        int c = t + i * 256;
        float val = in[c];
        if (mrow[c] == 0) val = -INFINITY;
        v[i] = val;
        mx = fmaxf(mx, val);
    }
#pragma unroll
    for (int o = 16; o; o >>= 1) mx = fmaxf(mx, __shfl_xor_sync(0xffffffffu, mx, o));
    if (lane == 0) red[wid] = mx;
    __syncthreads();
    if (t < 32) {
        float m2 = (t < 8) ? red[t] : -INFINITY;
#pragma unroll
        for (int o = 4; o; o >>= 1) m2 = fmaxf(m2, __shfl_xor_sync(0xffffffffu, m2, o));
        if (t == 0) bcast = m2;
    }
    __syncthreads();
    mx = bcast;

    float sum = 0.f;
#pragma unroll
    for (int i = 0; i < 4; i++) { v[i] = expf(v[i] - mx); sum += v[i]; }
#pragma unroll
    for (int o = 16; o; o >>= 1) sum += __shfl_xor_sync(0xffffffffu, sum, o);
    __syncthreads();
    if (lane == 0) red[wid] = sum;
    __syncthreads();
    if (t < 32) {
        float s2 = (t < 8) ? red[t] : 0.f;
#pragma unroll
        for (int o = 4; o; o >>= 1) s2 += __shfl_xor_sync(0xffffffffu, s2, o);
        if (t == 0) bcast = g_lamscale / s2;
    }
    __syncthreads();
    float sc = bcast;
#pragma unroll
    for (int i = 0; i < 4; i++) {
        size_t idx = row * 1024 + t + i * 256;
        float vv = v[i] * sc;
        Aout[idx] = vv;
        __half hi = __float2half(vv);
        Ahi[idx] = hi;
        Alo[idx] = __float2half(vv - __half2float(hi));
    }
}

// ======================= per-head LN(128) + concat, emits fp16 hi/lo ========
__global__ void __launch_bounds__(256) headln_kernel(
    const float* __restrict__ O, const float* __restrict__ w,
    const float* __restrict__ bvec, __half* __restrict__ och,
    __half* __restrict__ ocl)
{
    int gw = blockIdx.x * 8 + (threadIdx.x >> 5);
    int lane = threadIdx.x & 31;
    const float* xr = O + (size_t)gw * 128;
    float x0 = xr[lane], x1 = xr[lane + 32], x2 = xr[lane + 64], x3 = xr[lane + 96];
    float s = x0 + x1 + x2 + x3;
#pragma unroll
    for (int o = 16; o; o >>= 1) s += __shfl_xor_sync(0xffffffffu, s, o);
    float mean = s * (1.f / 128.f);
    float d0 = x0 - mean, d1 = x1 - mean, d2 = x2 - mean, d3 = x3 - mean;
    float q = d0 * d0 + d1 * d1 + d2 * d2 + d3 * d3;
#pragma unroll
    for (int o = 16; o; o >>= 1) q += __shfl_xor_sync(0xffffffffu, q, o);
    float rstd = rsqrtf(q * (1.f / 128.f) + 1e-5f);

    int z = gw >> 10, s_ = gw & 1023;
    int h = z >> 2, b = z & 3;
    size_t base = ((size_t)(b * S_SZ + s_)) * 2048 + h * 128;
    float vals[4] = {
        (d0 * rstd * w[lane]      + bvec[lane])      * HEADLN_SCALE,
        (d1 * rstd * w[lane + 32] + bvec[lane + 32]) * HEADLN_SCALE,
        (d2 * rstd * w[lane + 64] + bvec[lane + 64]) * HEADLN_SCALE,
        (d3 * rstd * w[lane + 96] + bvec[lane + 96]) * HEADLN_SCALE };
#pragma unroll
    for (int i = 0; i < 4; i++) {
        __half hi = __float2half(vals[i]);
        och[base + lane + i * 32] = hi;
        ocl[base + lane + i * 32] = __float2half(vals[i] - __half2float(hi));
    }
}

// ======================= LayerNorm 1024 (optional fp16 hi/lo out) ===========
__global__ void __launch_bounds__(256) ln1024(
    const float* __restrict__ X, const float* __restrict__ w,
    const float* __restrict__ bvec, float* __restrict__ out,
    __half* __restrict__ outh, __half* __restrict__ outl)
{
    __shared__ float red[8];
    __shared__ float bc;
    size_t row = blockIdx.x;
    const float* xr = X + row * 1024;
    int t = threadIdx.x;
    int wid = t >> 5, lane = t & 31;

    float v[4];
    float s = 0.f;
#pragma unroll
    for (int i = 0; i < 4; i++) { v[i] = xr[t + i * 256]; s += v[i]; }
#pragma unroll
    for (int o = 16; o; o >>= 1) s += __shfl_xor_sync(0xffffffffu, s, o);
    if (lane == 0) red[wid] = s;
    __syncthreads();
    if (t < 32) {
        float s2 = (t < 8) ? red[t] : 0.f;
#pragma unroll
        for (int o = 4; o; o >>= 1) s2 += __shfl_xor_sync(0xffffffffu, s2, o);
        if (t == 0) bc = s2 * (1.f / 1024.f);
    }
    __syncthreads();
    float mean = bc;

    float q = 0.f;
#pragma unroll
    for (int i = 0; i < 4; i++) { float d = v[i] - mean; q += d * d; }
#pragma unroll
    for (int o = 16; o; o >>= 1) q += __shfl_xor_sync(0xffffffffu, q, o);
    __syncthreads();
    if (lane == 0) red[wid] = q;
    __syncthreads();
    if (t < 32) {
        float q2 = (t < 8) ? red[t] : 0.f;
#pragma unroll
        for (int o = 4; o; o >>= 1) q2 += __shfl_xor_sync(0xffffffffu, q2, o);
        if (t == 0) bc = rsqrtf(q2 * (1.f / 1024.f) + 1e-5f);
    }
    __syncthreads();
    float rstd = bc;
#pragma unroll
    for (int i = 0; i < 4; i++) {
        int c = t + i * 256;
        float vv = (v[i] - mean) * rstd * w[c] + bvec[c];
        out[row * 1024 + c] = vv;
        if (outh) {
            __half hi = __float2half(vv);
            outh[row * 1024 + c] = hi;
            outl[row * 1024 + c] = __float2half(vv - __half2float(hi));
        }
    }
}

// ======================= host launcher ======================================
extern "C" void kernel_launch(void* const* d_in, const int* in_sizes, int n_in,
                              void* d_out, int out_size)
{
    const float* x    = (const float*)d_in[0];
    const int*   mask = (const int*)  d_in[1];
    const float* WQ1  = (const float*)d_in[2];
    const float* bQ1  = (const float*)d_in[3];
    const float* WK1  = (const float*)d_in[4];
    const float* bK1  = (const float*)d_in[5];
    const float* WV   = (const float*)d_in[6];
    const float* bV   = (const float*)d_in[7];
    const float* lnhw = (const float*)d_in[8];
    const float* lnhb = (const float*)d_in[9];
    const float* WO   = (const float*)d_in[10];
    const float* bO   = (const float*)d_in[11];
    const float* ln1w = (const float*)d_in[12];
    const float* ln1b = (const float*)d_in[13];
    const float* ln2w = (const float*)d_in[14];
    const float* ln2b = (const float*)d_in[15];
    const float* W1   = (const float*)d_in[16];
    const float* b1   = (const float*)d_in[17];
    const float* W2   = (const float*)d_in[18];
    const float* b2   = (const float*)d_in[19];
    const float* lq1  = (const float*)d_in[20];
    const float* lk1  = (const float*)d_in[21];
    const float* lq2  = (const float*)d_in[22];
    const float* lk2  = (const float*)d_in[23];

    float* out = (float*)d_out;

    const int SM3 = 2 * 4 * 10240;   // 81920: 3-term, 2-stage
    const int SM2 = 3 * 3 * 10240;   // 92160: 2-term, 3-stage
    cudaFuncSetAttribute(gemm_mma<0, 3, 2>, cudaFuncAttributeMaxDynamicSharedMemorySize, SM3);
    cudaFuncSetAttribute(gemm_mma<1, 2, 3>, cudaFuncAttributeMaxDynamicSharedMemorySize, SM2);

    float *sp, *op, *h1pre, *h1, *r2pre, *biasqk;
    __nv_bfloat16 *qkh, *qkl, *bqh, *bql, *xh, *xl;
    __half *wvh, *woth, *w1th, *w2th, *xhf, *xlf, *ah, *al, *vh, *vth;
    __half *och, *ocl, *h1h, *h1l, *ffhh, *ffhl;
    cudaGetSymbolAddress((void**)&qkh,   g_QKh);
    cudaGetSymbolAddress((void**)&qkl,   g_QKl);
    cudaGetSymbolAddress((void**)&bqh,   g_Bqh);
    cudaGetSymbolAddress((void**)&bql,   g_Bql);
    cudaGetSymbolAddress((void**)&wvh,   g_WVh);
    cudaGetSymbolAddress((void**)&woth,  g_WOth);
    cudaGetSymbolAddress((void**)&w1th,  g_W1th);
    cudaGetSymbolAddress((void**)&w2th,  g_W2th);
    cudaGetSymbolAddress((void**)&biasqk, g_biasqk);
    cudaGetSymbolAddress((void**)&xh,    g_xh);
    cudaGetSymbolAddress((void**)&xl,    g_xl);
    cudaGetSymbolAddress((void**)&xhf,   g_xhf);
    cudaGetSymbolAddress((void**)&xlf,   g_xlf);
    cudaGetSymbolAddress((void**)&sp,    g_S);
    cudaGetSymbolAddress((void**)&ah,    g_Ah);
    cudaGetSymbolAddress((void**)&al,    g_Al);
    cudaGetSymbolAddress((void**)&vh,    g_Vh);
    cudaGetSymbolAddress((void**)&vth,   g_Vth);
    cudaGetSymbolAddress((void**)&op,    g_O);
    cudaGetSymbolAddress((void**)&och,   g_Och);
    cudaGetSymbolAddress((void**)&ocl,   g_Ocl);
    cudaGetSymbolAddress((void**)&h1pre, g_h1pre);
    cudaGetSymbolAddress((void**)&h1,    g_h1);
    cudaGetSymbolAddress((void**)&h1h,   g_h1h);
    cudaGetSymbolAddress((void**)&h1l,   g_h1l);
    cudaGetSymbolAddress((void**)&ffhh,  g_ffhh);
    cudaGetSymbolAddress((void**)&ffhl,  g_ffhl);
    cudaGetSymbolAddress((void**)&r2pre, g_r2pre);

    float* A_ptr = (out_size >= FULL_ELEMS) ? (out + R2_ELEMS) : sp;

    lam_kernel<<<1, 64>>>(lq1, lk1, lq2, lk2);
    concat_bias2<<<8, 256>>>(bQ1, bK1, biasqk);

    // weight converts: WQ|WK bf16 hi/lo (K-major); WV/WO/W1/W2 fp16 hi only
    convW<__nv_bfloat16, 1><<<dim3(32, 32),  dim3(32, 8)>>>(WQ1, bqh,               bql,               1024, 64);
    convW<__nv_bfloat16, 1><<<dim3(32, 32),  dim3(32, 8)>>>(WK1, bqh + 1024 * 1024, bql + 1024 * 1024, 1024, 64);
    convW<__half, 0>       <<<dim3(32, 64),  dim3(32, 8)>>>(WV,  wvh,  nullptr, 1024, 128);
    convW<__half, 0>       <<<dim3(64, 32),  dim3(32, 8)>>>(WO,  woth, nullptr, 2048, 1024);
    convW<__half, 0>       <<<dim3(32, 128), dim3(32, 8)>>>(W1,  w1th, nullptr, 1024, 4096);
    convW<__half, 0>       <<<dim3(128, 32), dim3(32, 8)>>>(W2,  w2th, nullptr, 4096, 1024);
    conv_hilo_both<<<4096, 256>>>(x, xh, xl, xhf, xlf, 1048576);

    // QK projection (bf16 3-term): [4096, 2048], K=1024
    gemm_mma<0, 3, 2><<<dim3(16, 32, 1), 256, SM3>>>(
        (const uint16_t*)xh, (const uint16_t*)xl, (const uint16_t*)bqh, (const uint16_t*)bql,
        biasqk, nullptr, nullptr, (uint16_t*)qkh, (uint16_t*)qkl,
        1024, 1024, 1024, 2048, 1.0f, 0, 0);

    // V projection (fp16 2-term): [4096, 2048], K=1024, fp16-hi output only
    gemm_mma<1, 2, 3><<<dim3(16, 32, 1), 256, SM2>>>(
        (const uint16_t*)xhf, (const uint16_t*)xlf, (const uint16_t*)wvh, nullptr,
        bV, nullptr, nullptr, (uint16_t*)vh, nullptr,
        1024, 1024, 1024, 2048, 1.0f, 0, 0);

    // scores (bf16 3-term), batched z=h*4+b, alpha = 1/sqrt(1024)
    gemm_mma<0, 3, 2><<<dim3(8, 8, 64), 256, SM3>>>(
        (const uint16_t*)qkh, (const uint16_t*)qkl,
        (const uint16_t*)(qkh + 1024), (const uint16_t*)(qkl + 1024),
        nullptr, nullptr, sp, nullptr, nullptr,
        64, 2048, 2048, 1024, 0.03125f, 0, 1);

    softmax_row<<<65536, 256>>>(sp, mask, A_ptr, ah, al);
    convVt_f16<<<dim3(32, 4, 64), dim3(32, 8)>>>(vh, vth);

    // AV (fp16 2-term), batched
    gemm_mma<1, 2, 3><<<dim3(1, 8, 64), 256, SM2>>>(
        (const uint16_t*)ah, (const uint16_t*)al, (const uint16_t*)vth, nullptr,
        nullptr, nullptr, op, nullptr, nullptr,
        1024, 1024, 1024, 128, 1.0f, 0, 2);

    headln_kernel<<<8192, 256>>>(op, lnhw, lnhb, och, ocl);

    // output projection (fp16 2-term) + residual(x), LN1
    gemm_mma<1, 2, 3><<<dim3(8, 32, 1), 256, SM2>>>(
        (const uint16_t*)och, (const uint16_t*)ocl, (const uint16_t*)woth, nullptr,
        bO, x, h1pre, nullptr, nullptr,
        2048, 2048, 2048, 1024, 1.0f, 0, 0);
    ln1024<<<4096, 256>>>(h1pre, ln1w, ln1b, h1, h1h, h1l);

    // FFN (fp16 2-term): relu(h1 @ W1 + b1) @ W2 + b2 + h1, LN2 -> out
    gemm_mma<1, 2, 3><<<dim3(32, 32, 1), 256, SM2>>>(
        (const uint16_t*)h1h, (const uint16_t*)h1l, (const uint16_t*)w1th, nullptr,
        b1, nullptr, nullptr, (uint16_t*)ffhh, (uint16_t*)ffhl,
        1024, 1024, 1024, 4096, 1.0f, 1, 0);
    gemm_mma<1, 2, 3><<<dim3(8, 32, 1), 256, SM2>>>(
        (const uint16_t*)ffhh, (const uint16_t*)ffhl, (const uint16_t*)w2th, nullptr,
        b2, h1, r2pre, nullptr, nullptr,
        4096, 4096, 4096, 1024, 1.0f, 0, 0);
    ln1024<<<4096, 256>>>(r2pre, ln2w, ln2b, out, nullptr, nullptr);
}

// round 11
// speedup vs baseline: 4.6703x; 1.1096x over previous
#include <cuda_runtime.h>
#include <cuda_fp16.h>
#include <math.h>
#include <stddef.h>
#include <stdint.h>

#define B_SZ   4
#define S_SZ   1024
#define D_M    1024
#define H_N    16
#define D_INT  64
#define D_V    128
#define HID    4096
#define NTOK   4096
#define HB     64
#define LAMBDA_INIT 0.3555090675909693f
#define HEADLN_SCALE 0.6444909324090307f
#define R2_ELEMS 4194304
#define FULL_ELEMS 71303168

// ======================= helpers =======================
__device__ __forceinline__ uint32_t smem_u32(const void* p) {
    uint32_t a;
    asm("{ .reg .u64 t; cvta.to.shared.u64 t, %1; cvt.u32.u64 %0, t; }" : "=r"(a) : "l"(p));
    return a;
}
#define CP_ASYNC16(sdst, gsrc) \
    asm volatile("cp.async.cg.shared.global [%0], [%1], 16;" :: "r"(sdst), "l"(gsrc) : "memory")
#define CP_COMMIT() asm volatile("cp.async.commit_group;" ::: "memory")
template<int N> __device__ __forceinline__ void cp_waitg() {
    asm volatile("cp.async.wait_group %0;" :: "n"(N) : "memory");
}

__device__ __forceinline__ void mma_f16(float* d, uint32_t a0, uint32_t a1, uint32_t a2,
                                        uint32_t a3, uint32_t b0, uint32_t b1) {
    asm volatile(
        "mma.sync.aligned.m16n8k16.row.col.f32.f16.f16.f32 "
        "{%0,%1,%2,%3}, {%4,%5,%6,%7}, {%8,%9}, {%0,%1,%2,%3};"
        : "+f"(d[0]), "+f"(d[1]), "+f"(d[2]), "+f"(d[3])
        : "r"(a0), "r"(a1), "r"(a2), "r"(a3), "r"(b0), "r"(b1));
}
__device__ __forceinline__ void ldmx4(uint32_t* r, uint32_t addr) {
    asm volatile("ldmatrix.sync.aligned.m8n8.x4.shared.b16 {%0,%1,%2,%3}, [%4];"
        : "=r"(r[0]), "=r"(r[1]), "=r"(r[2]), "=r"(r[3]) : "r"(addr));
}
__device__ __forceinline__ void ldmx2(uint32_t* r, uint32_t addr) {
    asm volatile("ldmatrix.sync.aligned.m8n8.x2.shared.b16 {%0,%1}, [%2];"
        : "=r"(r[0]), "=r"(r[1]) : "r"(addr));
}
__device__ __forceinline__ uint32_t packh2(float a, float b) {
    __half2 p; p.x = __float2half(a); p.y = __float2half(b);
    return *reinterpret_cast<uint32_t*>(&p);
}

// ======================= static scratch =======================
__device__ __align__(16) __half  g_QKh  [(size_t)NTOK * 2048];   // Q|K fp16 hi
__device__ __align__(16) __half  g_QKl  [(size_t)NTOK * 2048];   // Q|K fp16 lo
__device__ __align__(16) __half  g_Bqh  [(size_t)2048 * 1024];   // WQ|WK K-major fp16 hi
__device__ __align__(16) __half  g_WVh  [(size_t)2048 * 1024];
__device__ __align__(16) __half  g_WOth [(size_t)1024 * 2048];
__device__ __align__(16) __half  g_W1th [(size_t)4096 * 1024];
__device__ __align__(16) __half  g_W2th [(size_t)1024 * 4096];
__device__ __align__(16) float   g_biasqk[2048];
__device__ __align__(16) __half  g_xhf  [(size_t)NTOK * 1024];
__device__ __align__(16) __half  g_xlf  [(size_t)NTOK * 1024];
__device__ __align__(16) __half  g_Sh   [(size_t)HB * S_SZ * S_SZ];  // scores fp16
__device__ __align__(16) __half  g_Ah   [(size_t)HB * S_SZ * S_SZ];  // A fp16 hi
__device__ __align__(16) __half  g_Vh   [(size_t)NTOK * 2048];
__device__ __align__(16) __half  g_Vth  [(size_t)HB * 128 * 1024];
__device__ __align__(16) float   g_O    [(size_t)HB * S_SZ * D_V];
__device__ __align__(16) __half  g_Och  [(size_t)NTOK * 2048];
__device__ __align__(16) __half  g_Ocl  [(size_t)NTOK * 2048];
__device__ __align__(16) float   g_h1pre[(size_t)NTOK * D_M];
__device__ __align__(16) float   g_h1   [(size_t)NTOK * D_M];
__device__ __align__(16) __half  g_h1h  [(size_t)NTOK * D_M];
__device__ __align__(16) __half  g_h1l  [(size_t)NTOK * D_M];
__device__ __align__(16) __half  g_ffhh [(size_t)NTOK * HID];
__device__ __align__(16) __half  g_ffhl [(size_t)NTOK * HID];
__device__ __align__(16) float   g_r2pre[(size_t)NTOK * D_M];
__device__ float g_lamscale;

// ======================= lambda =======================
__global__ void lam_kernel(const float* __restrict__ lq1, const float* __restrict__ lk1,
                           const float* __restrict__ lq2, const float* __restrict__ lk2)
{
    __shared__ float s1[64], s2[64];
    int t = threadIdx.x;
    s1[t] = lq1[t] * lk1[t];
    s2[t] = lq2[t] * lk2[t];
    __syncthreads();
    if (t == 0) {
        float d1 = 0.f, d2 = 0.f;
        for (int i = 0; i < 64; i++) { d1 += s1[i]; d2 += s2[i]; }
        g_lamscale = 1.0f - (expf(d1) - expf(d2) + LAMBDA_INIT);
    }
}

// ======================= conversions =======================
// x -> fp16 hi/lo
__global__ void __launch_bounds__(256) conv_hilo_f16(
    const float* __restrict__ in, __half* __restrict__ oh, __half* __restrict__ ol, int n4)
{
    int i = blockIdx.x * 256 + threadIdx.x;
    if (i >= n4) return;
    float4 v = reinterpret_cast<const float4*>(in)[i];
    float vv[4] = {v.x, v.y, v.z, v.w};
    uint32_t fh[2], fl[2];
#pragma unroll
    for (int p = 0; p < 2; p++) {
        float a = vv[p * 2], b = vv[p * 2 + 1];
        float ha = __half2float(__float2half(a)), hb = __half2float(__float2half(b));
        fh[p] = packh2(a, b);
        fl[p] = packh2(a - ha, b - hb);
    }
    reinterpret_cast<uint32_t*>(oh)[i * 2] = fh[0];  reinterpret_cast<uint32_t*>(oh)[i * 2 + 1] = fh[1];
    reinterpret_cast<uint32_t*>(ol)[i * 2] = fl[0];  reinterpret_cast<uint32_t*>(ol)[i * 2 + 1] = fl[1];
}

// weight transpose-convert (fp16 hi only): out[n][k] from in[(n/dout)*K*dout + k*dout + n%dout]
__global__ void convW(const float* __restrict__ in, __half* __restrict__ oh, int K, int dout)
{
    __shared__ float t[32][33];
    int k0 = blockIdx.x * 32, n0 = blockIdx.y * 32;
    int h = n0 / dout, d0 = n0 - h * dout;
    const float* src = in + (size_t)h * K * dout + d0;
    for (int r = threadIdx.y; r < 32; r += 8)
        t[r][threadIdx.x] = src[(size_t)(k0 + r) * dout + threadIdx.x];
    __syncthreads();
    for (int r = threadIdx.y; r < 32; r += 8)
        oh[(size_t)(n0 + r) * K + k0 + threadIdx.x] = __float2half(t[threadIdx.x][r]);
}

// V transpose (fp16 hi): Vt[z][v][t] from Vh[(b*1024+t)*2048 + h*128 + v]
__global__ void convVt_f16(const __half* __restrict__ sh, __half* __restrict__ oh)
{
    __shared__ __half th[32][33];
    int z = blockIdx.z, h = z >> 2, b = z & 3;
    int t0 = blockIdx.x * 32, v0 = blockIdx.y * 32;
    for (int r = threadIdx.y; r < 32; r += 8)
        th[r][threadIdx.x] = sh[(size_t)(b * 1024 + t0 + r) * 2048 + h * 128 + v0 + threadIdx.x];
    __syncthreads();
    size_t base = (size_t)z * 131072;
    for (int r = threadIdx.y; r < 32; r += 8)
        oh[base + (size_t)(v0 + r) * 1024 + t0 + threadIdx.x] = th[threadIdx.x][r];
}

__global__ void concat_bias2(const float* __restrict__ bq, const float* __restrict__ bk,
                             float* __restrict__ o)
{
    int t = blockIdx.x * 256 + threadIdx.x;
    if (t < 1024) o[t] = bq[t];
    else if (t < 2048) o[t] = bk[t - 1024];
}

// ======================= tensor-core GEMM (fp16 mma.sync) ====================
// C[128x128 tile] = sum_k A[m][k]*B[n][k], K-major fp16.
// TERMS: 2 = Ah*Bh + Al*Bh ; 1 = Ah*Bh only.
// NS: cp.async pipeline depth. modes: 0 plain; 1 scores batched; 2 AV batched.
template<int TERMS, int NS>
__global__ void __launch_bounds__(256, 2) gemm_mma(
    const __half* __restrict__ Ah, const __half* __restrict__ Al,
    const __half* __restrict__ Bh,
    const float* __restrict__ bias, const float* __restrict__ res,
    float* __restrict__ cout, __half* __restrict__ outh, __half* __restrict__ outl,
    int K, int lda, int ldb, int ldc, float alpha, int relu, int mode)
{
    constexpr int NTILE = TERMS + 1;
    constexpr int STG = NTILE * 10240;
    constexpr uint32_t oAl = 10240;
    constexpr uint32_t oBh = (TERMS >= 2) ? 20480u : 10240u;
    extern __shared__ char dsm[];
    const int tid = threadIdx.x;
    const int lane = tid & 31, wid = tid >> 5;
    const int wy = wid >> 2, wx = wid & 3;       // warp tile: 64(M) x 32(N)
    const int m0 = blockIdx.y * 128, n0 = blockIdx.x * 128;
    const uint32_t smbase = smem_u32(dsm);

    size_t aoff = 0, boff = 0, coff = 0;
    if (mode == 1) {
        int z = blockIdx.z, h = z >> 2, b = z & 3;
        aoff = (size_t)(b << 10) * lda + (h << 6);
        boff = (size_t)(b << 10) * ldb + (h << 6);
        coff = (size_t)z << 20;
    } else if (mode == 2) {
        int z = blockIdx.z;
        aoff = (size_t)z << 20;
        boff = (size_t)z << 17;
        coff = (size_t)z << 17;
    }

    float acc[4][4][4];
#pragma unroll
    for (int i = 0; i < 4; i++)
#pragma unroll
        for (int j = 0; j < 4; j++)
#pragma unroll
            for (int q = 0; q < 4; q++) acc[i][j][q] = 0.f;

    const int niter = K >> 5;

    auto issue_tile = [&](int it, int slot) {
        int k0 = it << 5;
        uint32_t sb = smbase + slot * STG;
#pragma unroll
        for (int i = 0; i < 2; i++) {
            int l = tid + (i << 8);
            int row = l >> 2, c16 = l & 3;
            size_t aidx = aoff + (size_t)(m0 + row) * lda + k0 + (c16 << 3);
            size_t bidx = boff + (size_t)(n0 + row) * ldb + k0 + (c16 << 3);
            uint32_t so = (uint32_t)(row * 80 + (c16 << 4));
            CP_ASYNC16(sb + so,       Ah + aidx);
            if (TERMS >= 2) CP_ASYNC16(sb + oAl + so, Al + aidx);
            CP_ASYNC16(sb + oBh + so, Bh + bidx);
        }
        CP_COMMIT();
    };

#pragma unroll
    for (int s = 0; s < NS - 1; s++)
        if (s < niter) issue_tile(s, s);

    // ldmatrix per-lane addressing
    const int a_row = (wy << 6) + (lane & 7) + ((lane >> 3) & 1) * 8;  // + mt*16
    const int a_kb  = (lane >> 4) << 4;                                // + ks*32
    const int l15 = lane & 15;
    const int b_row = (wx << 5) + (l15 & 7);                           // + nt*8
    const int b_kb  = (l15 >> 3) << 4;                                 // + ks*32

    int cs = 0, is_ = NS - 1;
#pragma unroll 1
    for (int it = 0; it < niter; it++) {
        if (it + NS - 1 < niter) {
            issue_tile(it + NS - 1, is_);
            cp_waitg<NS - 1>();
        } else {
            cp_waitg<0>();
        }
        __syncthreads();

        uint32_t base = smbase + cs * STG;
        uint32_t pAh = base;
        uint32_t pAl = base + oAl;
        uint32_t pBh = base + oBh;

#pragma unroll
        for (int ks = 0; ks < 2; ks++) {
            const int ksb = ks << 5;
            uint32_t bhf[4][2];
#pragma unroll
            for (int nt = 0; nt < 4; nt++) {
                uint32_t bo = (uint32_t)((b_row + (nt << 3)) * 80 + ksb + b_kb);
                ldmx2(bhf[nt], pBh + bo);
            }
#pragma unroll
            for (int mt = 0; mt < 4; mt++) {
                uint32_t ao = (uint32_t)((a_row + (mt << 4)) * 80 + ksb + a_kb);
                uint32_t ahf[4], alf[4];
                ldmx4(ahf, pAh + ao);
                if (TERMS >= 2) ldmx4(alf, pAl + ao);
#pragma unroll
                for (int nt = 0; nt < 4; nt++) {
                    mma_f16(acc[mt][nt], ahf[0], ahf[1], ahf[2], ahf[3], bhf[nt][0], bhf[nt][1]);
                    if (TERMS >= 2)
                        mma_f16(acc[mt][nt], alf[0], alf[1], alf[2], alf[3], bhf[nt][0], bhf[nt][1]);
                }
            }
        }
        __syncthreads();
        cs = (cs + 1 == NS) ? 0 : cs + 1;
        is_ = (is_ + 1 == NS) ? 0 : is_ + 1;
    }

    // epilogue: alpha, bias, residual, relu; fp32 and/or fp16 hi(/lo) outputs
#pragma unroll
    for (int mt = 0; mt < 4; mt++) {
#pragma unroll
        for (int nt = 0; nt < 4; nt++) {
#pragma unroll
            for (int hf = 0; hf < 2; hf++) {
                int row = m0 + (wy << 6) + (mt << 4) + (lane >> 2) + (hf << 3);
                int col = n0 + (wx << 5) + (nt << 3) + ((lane & 3) << 1);
                float v0 = acc[mt][nt][hf * 2]     * alpha;
                float v1 = acc[mt][nt][hf * 2 + 1] * alpha;
                if (bias) { v0 += bias[col]; v1 += bias[col + 1]; }
                if (res) {
                    float2 rv = *reinterpret_cast<const float2*>(res + (size_t)row * ldc + col);
                    v0 += rv.x; v1 += rv.y;
                }
                if (relu) { v0 = fmaxf(v0, 0.f); v1 = fmaxf(v1, 0.f); }
                size_t oidx = coff + (size_t)row * ldc + col;
                if (cout) *reinterpret_cast<float2*>(cout + oidx) = make_float2(v0, v1);
                if (outh) {
                    *reinterpret_cast<uint32_t*>(outh + oidx) = packh2(v0, v1);
                    if (outl) {
                        float h0 = __half2float(__float2half(v0));
                        float h1 = __half2float(__float2half(v1));
                        *reinterpret_cast<uint32_t*>(outl + oidx) = packh2(v0 - h0, v1 - h1);
                    }
                }
            }
        }
    }
}

// ======================= softmax (fp16 scores in; fp32 A + fp16 hi out) =====
__global__ void __launch_bounds__(256) softmax_row(
    const __half* __restrict__ Sc, const int* __restrict__ mask, float* __restrict__ Aout,
    __half* __restrict__ Ahi)
{
    __shared__ float red[8];
    __shared__ float bcast;
    size_t row = blockIdx.x;
    int b = (int)((row >> 10) & 3);
    const __half* in = Sc + row * 1024;
    const int* mrow = mask + b * 1024;
    int t = threadIdx.x;
    int wid = t >> 5, lane = t & 31;

    float v[4];
    float mx = -INFINITY;
#pragma unroll
    for (int i = 0; i < 4; i++) {
        int c = t + i * 256;
        float val = __half2float(in[c]);
        if (mrow[c] == 0) val = -INFINITY;
        v[i] = val;
        mx = fmaxf(mx, val);
    }
#pragma unroll
    for (int o = 16; o; o >>= 1) mx = fmaxf(mx, __shfl_xor_sync(0xffffffffu, mx, o));
    if (lane == 0) red[wid] = mx;
    __syncthreads();
    if (t < 32) {
        float m2 = (t < 8) ? red[t] : -INFINITY;
#pragma unroll
        for (int o = 4; o; o >>= 1) m2 = fmaxf(m2, __shfl_xor_sync(0xffffffffu, m2, o));
        if (t == 0) bcast = m2;
    }
    __syncthreads();
    mx = bcast;

    float sum = 0.f;
#pragma unroll
    for (int i = 0; i < 4; i++) { v[i] = expf(v[i] - mx); sum += v[i]; }
#pragma unroll
    for (int o = 16; o; o >>= 1) sum += __shfl_xor_sync(0xffffffffu, sum, o);
    __syncthreads();
    if (lane == 0) red[wid] = sum;
    __syncthreads();
    if (t < 32) {
        float s2 = (t < 8) ? red[t] : 0.f;
#pragma unroll
        for (int o = 4; o; o >>= 1) s2 += __shfl_xor_sync(0xffffffffu, s2, o);
        if (t == 0) bcast = g_lamscale / s2;
    }
    __syncthreads();
    float sc = bcast;
#pragma unroll
    for (int i = 0; i < 4; i++) {
        size_t idx = row * 1024 + t + i * 256;
        float vv = v[i] * sc;
        Aout[idx] = vv;
        Ahi[idx] = __float2half(vv);
    }
}

// ======================= per-head LN(128) + concat, emits fp16 hi/lo ========
__global__ void __launch_bounds__(256) headln_kernel(
    const float* __restrict__ O, const float* __restrict__ w,
    const float* __restrict__ bvec, __half* __restrict__ och,
    __half* __restrict__ ocl)
{
    int gw = blockIdx.x * 8 + (threadIdx.x >> 5);
    int lane = threadIdx.x & 31;
    const float* xr = O + (size_t)gw * 128;
    float x0 = xr[lane], x1 = xr[lane + 32], x2 = xr[lane + 64], x3 = xr[lane + 96];
    float s = x0 + x1 + x2 + x3;
#pragma unroll
    for (int o = 16; o; o >>= 1) s += __shfl_xor_sync(0xffffffffu, s, o);
    float mean = s * (1.f / 128.f);
    float d0 = x0 - mean, d1 = x1 - mean, d2 = x2 - mean, d3 = x3 - mean;
    float q = d0 * d0 + d1 * d1 + d2 * d2 + d3 * d3;
#pragma unroll
    for (int o = 16; o; o >>= 1) q += __shfl_xor_sync(0xffffffffu, q, o);
    float rstd = rsqrtf(q * (1.f / 128.f) + 1e-5f);

    int z = gw >> 10, s_ = gw & 1023;
    int h = z >> 2, b = z & 3;
    size_t base = ((size_t)(b * S_SZ + s_)) * 2048 + h * 128;
    float vals[4] = {
        (d0 * rstd * w[lane]      + bvec[lane])      * HEADLN_SCALE,
        (d1 * rstd * w[lane + 32] + bvec[lane + 32]) * HEADLN_SCALE,
        (d2 * rstd * w[lane + 64] + bvec[lane + 64]) * HEADLN_SCALE,
        (d3 * rstd * w[lane + 96] + bvec[lane + 96]) * HEADLN_SCALE };
#pragma unroll
    for (int i = 0; i < 4; i++) {
        __half hi = __float2half(vals[i]);
        och[base + lane + i * 32] = hi;
        ocl[base + lane + i * 32] = __float2half(vals[i] - __half2float(hi));
    }
}

// ======================= LayerNorm 1024 (optional fp16 hi/lo out) ===========
__global__ void __launch_bounds__(256) ln1024(
    const float* __restrict__ X, const float* __restrict__ w,
    const float* __restrict__ bvec, float* __restrict__ out,
    __half* __restrict__ outh, __half* __restrict__ outl)
{
    __shared__ float red[8];
    __shared__ float bc;
    size_t row = blockIdx.x;
    const float* xr = X + row * 1024;
    int t = threadIdx.x;
    int wid = t >> 5, lane = t & 31;

    float v[4];
    float s = 0.f;
#pragma unroll
    for (int i = 0; i < 4; i++) { v[i] = xr[t + i * 256]; s += v[i]; }
#pragma unroll
    for (int o = 16; o; o >>= 1) s += __shfl_xor_sync(0xffffffffu, s, o);
    if (lane == 0) red[wid] = s;
    __syncthreads();
    if (t < 32) {
        float s2 = (t < 8) ? red[t] : 0.f;
#pragma unroll
        for (int o = 4; o; o >>= 1) s2 += __shfl_xor_sync(0xffffffffu, s2, o);
        if (t == 0) bc = s2 * (1.f / 1024.f);
    }
    __syncthreads();
    float mean = bc;

    float q = 0.f;
#pragma unroll
    for (int i = 0; i < 4; i++) { float d = v[i] - mean; q += d * d; }
#pragma unroll
    for (int o = 16; o; o >>= 1) q += __shfl_xor_sync(0xffffffffu, q, o);
    __syncthreads();
    if (lane == 0) red[wid] = q;
    __syncthreads();
    if (t < 32) {
        float q2 = (t < 8) ? red[t] : 0.f;
#pragma unroll
        for (int o = 4; o; o >>= 1) q2 += __shfl_xor_sync(0xffffffffu, q2, o);
        if (t == 0) bc = rsqrtf(q2 * (1.f / 1024.f) + 1e-5f);
    }
    __syncthreads();
    float rstd = bc;
#pragma unroll
    for (int i = 0; i < 4; i++) {
        int c = t + i * 256;
        float vv = (v[i] - mean) * rstd * w[c] + bvec[c];
        out[row * 1024 + c] = vv;
        if (outh) {
            __half hi = __float2half(vv);
            outh[row * 1024 + c] = hi;
            outl[row * 1024 + c] = __float2half(vv - __half2float(hi));
        }
    }
}

// ======================= host launcher ======================================
extern "C" void kernel_launch(void* const* d_in, const int* in_sizes, int n_in,
                              void* d_out, int out_size)
{
    const float* x    = (const float*)d_in[0];
    const int*   mask = (const int*)  d_in[1];
    const float* WQ1  = (const float*)d_in[2];
    const float* bQ1  = (const float*)d_in[3];
    const float* WK1  = (const float*)d_in[4];
    const float* bK1  = (const float*)d_in[5];
    const float* WV   = (const float*)d_in[6];
    const float* bV   = (const float*)d_in[7];
    const float* lnhw = (const float*)d_in[8];
    const float* lnhb = (const float*)d_in[9];
    const float* WO   = (const float*)d_in[10];
    const float* bO   = (const float*)d_in[11];
    const float* ln1w = (const float*)d_in[12];
    const float* ln1b = (const float*)d_in[13];
    const float* ln2w = (const float*)d_in[14];
    const float* ln2b = (const float*)d_in[15];
    const float* W1   = (const float*)d_in[16];
    const float* b1   = (const float*)d_in[17];
    const float* W2   = (const float*)d_in[18];
    const float* b2   = (const float*)d_in[19];
    const float* lq1  = (const float*)d_in[20];
    const float* lk1  = (const float*)d_in[21];
    const float* lq2  = (const float*)d_in[22];
    const float* lk2  = (const float*)d_in[23];

    float* out = (float*)d_out;

    const int SM2 = 3 * 3 * 10240;   // 92160: 2-term, 3-stage
    const int SM1 = 4 * 2 * 10240;   // 81920: 1-term, 4-stage
    cudaFuncSetAttribute(gemm_mma<2, 3>, cudaFuncAttributeMaxDynamicSharedMemorySize, SM2);
    cudaFuncSetAttribute(gemm_mma<1, 4>, cudaFuncAttributeMaxDynamicSharedMemorySize, SM1);

    float *op, *h1pre, *h1, *r2pre, *biasqk;
    __half *qkh, *qkl, *bqh, *wvh, *woth, *w1th, *w2th;
    __half *xhf, *xlf, *sh, *ah, *vh, *vth, *och, *ocl, *h1h, *h1l, *ffhh, *ffhl;
    cudaGetSymbolAddress((void**)&qkh,   g_QKh);
    cudaGetSymbolAddress((void**)&qkl,   g_QKl);
    cudaGetSymbolAddress((void**)&bqh,   g_Bqh);
    cudaGetSymbolAddress((void**)&wvh,   g_WVh);
    cudaGetSymbolAddress((void**)&woth,  g_WOth);
    cudaGetSymbolAddress((void**)&w1th,  g_W1th);
    cudaGetSymbolAddress((void**)&w2th,  g_W2th);
    cudaGetSymbolAddress((void**)&biasqk, g_biasqk);
    cudaGetSymbolAddress((void**)&xhf,   g_xhf);
    cudaGetSymbolAddress((void**)&xlf,   g_xlf);
    cudaGetSymbolAddress((void**)&sh,    g_Sh);
    cudaGetSymbolAddress((void**)&ah,    g_Ah);
    cudaGetSymbolAddress((void**)&vh,    g_Vh);
    cudaGetSymbolAddress((void**)&vth,   g_Vth);
    cudaGetSymbolAddress((void**)&op,    g_O);
    cudaGetSymbolAddress((void**)&och,   g_Och);
    cudaGetSymbolAddress((void**)&ocl,   g_Ocl);
    cudaGetSymbolAddress((void**)&h1pre, g_h1pre);
    cudaGetSymbolAddress((void**)&h1,    g_h1);
    cudaGetSymbolAddress((void**)&h1h,   g_h1h);
    cudaGetSymbolAddress((void**)&h1l,   g_h1l);
    cudaGetSymbolAddress((void**)&ffhh,  g_ffhh);
    cudaGetSymbolAddress((void**)&ffhl,  g_ffhl);
    cudaGetSymbolAddress((void**)&r2pre, g_r2pre);

    float* A_ptr = (out_size >= FULL_ELEMS) ? (out + R2_ELEMS) : op;  // fp32 A dest

    lam_kernel<<<1, 64>>>(lq1, lk1, lq2, lk2);
    concat_bias2<<<8, 256>>>(bQ1, bK1, biasqk);

    // weight converts (fp16 hi, K-major)
    convW<<<dim3(32, 32),  dim3(32, 8)>>>(WQ1, bqh,               1024, 64);
    convW<<<dim3(32, 32),  dim3(32, 8)>>>(WK1, bqh + 1024 * 1024, 1024, 64);
    convW<<<dim3(32, 64),  dim3(32, 8)>>>(WV,  wvh,  1024, 128);
    convW<<<dim3(64, 32),  dim3(32, 8)>>>(WO,  woth, 2048, 1024);
    convW<<<dim3(32, 128), dim3(32, 8)>>>(W1,  w1th, 1024, 4096);
    convW<<<dim3(128, 32), dim3(32, 8)>>>(W2,  w2th, 4096, 1024);
    conv_hilo_f16<<<4096, 256>>>(x, xhf, xlf, 1048576);

    // QK projection (fp16 2-term): [4096, 2048], K=1024; emits hi+lo
    gemm_mma<2, 3><<<dim3(16, 32, 1), 256, SM2>>>(
        xhf, xlf, bqh, biasqk, nullptr, nullptr, qkh, qkl,
        1024, 1024, 1024, 2048, 1.0f, 0, 0);

    // V projection (fp16 2-term): [4096, 2048], K=1024, hi only
    gemm_mma<2, 3><<<dim3(16, 32, 1), 256, SM2>>>(
        xhf, xlf, wvh, bV, nullptr, nullptr, vh, nullptr,
        1024, 1024, 1024, 2048, 1.0f, 0, 0);

    // scores (fp16 2-term, Q hi/lo x K hi), batched; alpha = 1/sqrt(1024); fp16 out
    gemm_mma<2, 3><<<dim3(8, 8, 64), 256, SM2>>>(
        qkh, qkl, qkh + 1024, nullptr, nullptr, nullptr, sh, nullptr,
        64, 2048, 2048, 1024, 0.03125f, 0, 1);

    softmax_row<<<65536, 256>>>(sh, mask, A_ptr, ah);
    convVt_f16<<<dim3(32, 4, 64), dim3(32, 8)>>>(vh, vth);

    // AV (fp16 1-term), batched
    gemm_mma<1, 4><<<dim3(1, 8, 64), 256, SM1>>>(
        ah, nullptr, vth, nullptr, nullptr, op, nullptr, nullptr,
        1024, 1024, 1024, 128, 1.0f, 0, 2);

    headln_kernel<<<8192, 256>>>(op, lnhw, lnhb, och, ocl);

    // output projection (fp16 2-term) + residual(x), LN1
    gemm_mma<2, 3><<<dim3(8, 32, 1), 256, SM2>>>(
        och, ocl, woth, bO, x, h1pre, nullptr, nullptr,
        2048, 2048, 2048, 1024, 1.0f, 0, 0);
    ln1024<<<4096, 256>>>(h1pre, ln1w, ln1b, h1, h1h, h1l);

    // FFN (fp16 2-term): relu(h1 @ W1 + b1) @ W2 + b2 + h1, LN2 -> out
    gemm_mma<2, 3><<<dim3(32, 32, 1), 256, SM2>>>(
        h1h, h1l, w1th, b1, nullptr, nullptr, ffhh, ffhl,
        1024, 1024, 1024, 4096, 1.0f, 1, 0);
    gemm_mma<2, 3><<<dim3(8, 32, 1), 256, SM2>>>(
        ffhh, ffhl, w2th, b2, h1, r2pre, nullptr, nullptr,
        4096, 4096, 4096, 1024, 1.0f, 0, 0);
    ln1024<<<4096, 256>>>(r2pre, ln2w, ln2b, out, nullptr, nullptr);
}